// round 2
// baseline (speedup 1.0000x reference)
#include <cuda_runtime.h>

#define NT 1024
#define NHEAD 16
#define DH 64
#define NN (1024u*1024u)

// scratch (device globals: allocation-free)
__device__ float g_bias[16u*1024u*1024u]; // [h][i][j]
__device__ float g_qt[1024*1024];         // [dim_inner][token], pre-scaled by 0.125
__device__ float g_kt[1024*1024];         // [dim_inner][token]
__device__ float g_v [1024*1024];         // [token][dim_inner]
__device__ float g_g [1024*1024];         // sigmoid gates, [token][dim_inner]
__device__ float g_o [1024*1024];         // gated attention out, [token][dim_inner]

// ---------------------------------------------------------------------------
// Bias kernel: LayerNorm over 128 pair features + project to 16 heads.
// One warp per (i,j). Block = 256 thr handles i=blockIdx.y, 128 j's.
// ---------------------------------------------------------------------------
__global__ __launch_bounds__(256, 2) void bias_kernel(
    const float* __restrict__ pw, const float* __restrict__ gamma,
    const float* __restrict__ beta, const float* __restrict__ Wb)
{
    __shared__ float tile[16][129];
    int tid  = threadIdx.x;
    int lane = tid & 31, warp = tid >> 5;
    int i  = blockIdx.y;
    int j0 = blockIdx.x * 128;
    int p0 = lane * 4;

    // per-lane weight slice in registers: wg[q][h] = gamma[p0+q]*W[p0+q][h]
    float wg[4][16];
    float binit[16];
    {
        float4 gg = *(const float4*)(gamma + p0);
        float4 bb = *(const float4*)(beta  + p0);
        float g4[4] = {gg.x, gg.y, gg.z, gg.w};
        float b4[4] = {bb.x, bb.y, bb.z, bb.w};
#pragma unroll
        for (int h = 0; h < 16; h++) binit[h] = 0.f;
#pragma unroll
        for (int q = 0; q < 4; q++) {
#pragma unroll
            for (int h = 0; h < 16; h++) {
                float w = Wb[(p0 + q) * 16 + h];
                wg[q][h]  = g4[q] * w;
                binit[h] += b4[q] * w;
            }
        }
    }

    const float4* base = (const float4*)pw + ((size_t)i * 1024 + j0) * 32;
    float4 x = base[(size_t)warp * 32 + lane];   // prefetch first
#pragma unroll 1
    for (int t = 0; t < 16; t++) {
        int jj = warp + 8 * t;
        float4 xn;
        if (t < 15) xn = base[(size_t)(jj + 8) * 32 + lane];

        float s  = x.x + x.y + x.z + x.w;
        float ss = x.x*x.x + x.y*x.y + x.z*x.z + x.w*x.w;
#pragma unroll
        for (int off = 16; off >= 1; off >>= 1) {
            s  += __shfl_xor_sync(0xffffffffu, s,  off);
            ss += __shfl_xor_sync(0xffffffffu, ss, off);
        }
        float mu  = s * 0.0078125f;
        float var = ss * 0.0078125f - mu * mu;
        float rs  = rsqrtf(var + 1e-5f);
        float t0 = (x.x - mu) * rs, t1 = (x.y - mu) * rs;
        float t2 = (x.z - mu) * rs, t3 = (x.w - mu) * rs;

        float acc[16];
#pragma unroll
        for (int h = 0; h < 16; h++)
            acc[h] = binit[h] + t0*wg[0][h] + t1*wg[1][h] + t2*wg[2][h] + t3*wg[3][h];

        // 16-value butterfly reduce across warp (16 shfl, not 80):
#pragma unroll
        for (int q = 0; q < 8; q++) {
            bool hi = (lane & 16);
            float keep = hi ? acc[q + 8] : acc[q];
            float send = hi ? acc[q]     : acc[q + 8];
            acc[q] = keep + __shfl_xor_sync(0xffffffffu, send, 16);
        }
#pragma unroll
        for (int q = 0; q < 4; q++) {
            bool hi = (lane & 8);
            float keep = hi ? acc[q + 4] : acc[q];
            float send = hi ? acc[q]     : acc[q + 4];
            acc[q] = keep + __shfl_xor_sync(0xffffffffu, send, 8);
        }
#pragma unroll
        for (int q = 0; q < 2; q++) {
            bool hi = (lane & 4);
            float keep = hi ? acc[q + 2] : acc[q];
            float send = hi ? acc[q]     : acc[q + 2];
            acc[q] = keep + __shfl_xor_sync(0xffffffffu, send, 4);
        }
        {
            bool hi = (lane & 2);
            float keep = hi ? acc[1] : acc[0];
            float send = hi ? acc[0] : acc[1];
            acc[0] = keep + __shfl_xor_sync(0xffffffffu, send, 2);
        }
        acc[0] += __shfl_xor_sync(0xffffffffu, acc[0], 1);
        int h = (lane >> 1) & 15;
        if ((lane & 1) == 0) tile[h][jj] = acc[0];
        x = xn;
    }
    __syncthreads();
    size_t obase = (size_t)i * 1024 + j0;
    for (int e = tid; e < 2048; e += 256) {
        int h = e >> 7, jj = e & 127;
        g_bias[(size_t)h * NN + obase + jj] = tile[h][jj];
    }
}

// ---------------------------------------------------------------------------
// 1024x1024x1024 fp32 GEMM, C = A @ B, 64x64 block tile, BK=16, 4x4 per thread.
// mode: 0=natural  1=*0.125 + transposed  2=transposed  3=sigmoid(x+aux[n])
// asel: 0=Aext 5=g_o;  csel: 0=Cext 1=g_qt 2=g_kt 3=g_v 4=g_g
// ---------------------------------------------------------------------------
__global__ __launch_bounds__(256, 2) void gemm1024(
    const float* __restrict__ Aext, int asel,
    const float* __restrict__ B,
    float* __restrict__ Cext, int csel,
    const float* __restrict__ aux, int mode)
{
    const float* A = (asel == 5) ? (const float*)g_o : Aext;
    float* C = Cext;
    if      (csel == 1) C = g_qt;
    else if (csel == 2) C = g_kt;
    else if (csel == 3) C = g_v;
    else if (csel == 4) C = g_g;

    __shared__ float As[16][68];
    __shared__ float Bs[16][68];
    int tid  = threadIdx.x;
    int row0 = blockIdx.y * 64, col0 = blockIdx.x * 64;
    int tr4 = (tid >> 4) * 4;     // row micro-tile
    int tc4 = (tid & 15) * 4;     // col micro-tile
    int la_r = tid >> 2;
    int la_c = (tid & 3) * 4;
    int lb_k = tid >> 4;
    int lb_c = (tid & 15) * 4;
    const float* Aptr = A + (size_t)(row0 + la_r) * 1024 + la_c;
    const float* Bptr = B + (size_t)lb_k * 1024 + col0 + lb_c;

    float acc[4][4] = {};
    float4 av = *(const float4*)(Aptr);
    float4 bv = *(const float4*)(Bptr);
#pragma unroll 1
    for (int k0 = 0; k0 < 1024; k0 += 16) {
        As[la_c + 0][la_r] = av.x;
        As[la_c + 1][la_r] = av.y;
        As[la_c + 2][la_r] = av.z;
        As[la_c + 3][la_r] = av.w;
        *(float4*)&Bs[lb_k][lb_c] = bv;
        __syncthreads();
        if (k0 + 16 < 1024) {   // prefetch next tiles during compute
            av = *(const float4*)(Aptr + k0 + 16);
            bv = *(const float4*)(Bptr + (size_t)(k0 + 16) * 1024);
        }
#pragma unroll
        for (int kk = 0; kk < 16; kk++) {
            float4 a = *(const float4*)&As[kk][tr4];
            float4 b = *(const float4*)&Bs[kk][tc4];
            float ar[4] = {a.x, a.y, a.z, a.w};
            float br[4] = {b.x, b.y, b.z, b.w};
#pragma unroll
            for (int ii = 0; ii < 4; ii++)
#pragma unroll
                for (int jj = 0; jj < 4; jj++)
                    acc[ii][jj] += ar[ii] * br[jj];
        }
        __syncthreads();
    }

    if (mode == 0) {
#pragma unroll
        for (int ii = 0; ii < 4; ii++) {
            float4 v = make_float4(acc[ii][0], acc[ii][1], acc[ii][2], acc[ii][3]);
            *(float4*)(C + (size_t)(row0 + tr4 + ii) * 1024 + col0 + tc4) = v;
        }
    } else if (mode == 1) {
#pragma unroll
        for (int ii = 0; ii < 4; ii++)
#pragma unroll
            for (int jj = 0; jj < 4; jj++)
                C[(size_t)(col0 + tc4 + jj) * 1024 + row0 + tr4 + ii] = acc[ii][jj] * 0.125f;
    } else if (mode == 2) {
#pragma unroll
        for (int ii = 0; ii < 4; ii++)
#pragma unroll
            for (int jj = 0; jj < 4; jj++)
                C[(size_t)(col0 + tc4 + jj) * 1024 + row0 + tr4 + ii] = acc[ii][jj];
    } else {
#pragma unroll
        for (int ii = 0; ii < 4; ii++) {
            float vv[4];
#pragma unroll
            for (int jj = 0; jj < 4; jj++) {
                float z = acc[ii][jj] + aux[col0 + tc4 + jj];
                vv[jj] = 1.0f / (1.0f + __expf(-z));
            }
            float4 v = make_float4(vv[0], vv[1], vv[2], vv[3]);
            *(float4*)(C + (size_t)(row0 + tr4 + ii) * 1024 + col0 + tc4) = v;
        }
    }
}

// ---------------------------------------------------------------------------
// Flash attention with additive pair bias + fused gating.
// Block: 256 thr, 64 queries x head. Grid (16 qblocks, 16 heads).
// smem: Qt(d-major) + KV (Kt then V, dual-use) + P = exactly 48 KB.
// ---------------------------------------------------------------------------
__global__ __launch_bounds__(256) void attn_kernel()
{
    __shared__ float Qt[64][64];   // [d][q]
    __shared__ float KV[64][64];   // phase1: [d][k]   phase2: [k][d]
    __shared__ float Ps[64][64];   // [q][k]
    int tid = threadIdx.x;
    int h   = blockIdx.y;
    int q0  = blockIdx.x * 64;
    int tr4 = (tid >> 4) * 4;
    int tc4 = (tid & 15) * 4;

#pragma unroll
    for (int it = 0; it < 4; it++) {
        int e = tid + it * 256;
        int dd = e >> 4, rc = (e & 15) * 4;
        *(float4*)&Qt[dd][rc] =
            *(const float4*)(g_qt + (size_t)(h * 64 + dd) * 1024 + q0 + rc);
    }
    float m_i[4], l_i[4], o[4][4];
#pragma unroll
    for (int ii = 0; ii < 4; ii++) {
        m_i[ii] = -1e30f; l_i[ii] = 0.f;
#pragma unroll
        for (int jj = 0; jj < 4; jj++) o[ii][jj] = 0.f;
    }
    __syncthreads();

#pragma unroll 1
    for (int kb = 0; kb < 16; kb++) {
        int k0 = kb * 64;
        // K^T tile
#pragma unroll
        for (int it = 0; it < 4; it++) {
            int e = tid + it * 256;
            int dd = e >> 4, cc = (e & 15) * 4;
            *(float4*)&KV[dd][cc] =
                *(const float4*)(g_kt + (size_t)(h * 64 + dd) * 1024 + k0 + cc);
        }
        __syncthreads();

        // S = Q K^T (q pre-scaled) + bias
        float s[4][4];
#pragma unroll
        for (int ii = 0; ii < 4; ii++) {
            float4 bb = *(const float4*)(g_bias + (size_t)h * NN
                              + (size_t)(q0 + tr4 + ii) * 1024 + k0 + tc4);
            s[ii][0] = bb.x; s[ii][1] = bb.y; s[ii][2] = bb.z; s[ii][3] = bb.w;
        }
#pragma unroll 8
        for (int d = 0; d < 64; d++) {
            float4 qa = *(const float4*)&Qt[d][tr4];
            float4 ka = *(const float4*)&KV[d][tc4];
            float ar[4] = {qa.x, qa.y, qa.z, qa.w};
            float br[4] = {ka.x, ka.y, ka.z, ka.w};
#pragma unroll
            for (int ii = 0; ii < 4; ii++)
#pragma unroll
                for (int jj = 0; jj < 4; jj++)
                    s[ii][jj] += ar[ii] * br[jj];
        }

        // online softmax (reduce across the 16-lane tc group)
#pragma unroll
        for (int ii = 0; ii < 4; ii++) {
            float rm = fmaxf(fmaxf(s[ii][0], s[ii][1]), fmaxf(s[ii][2], s[ii][3]));
#pragma unroll
            for (int off = 8; off >= 1; off >>= 1)
                rm = fmaxf(rm, __shfl_xor_sync(0xffffffffu, rm, off));
            float mn   = fmaxf(m_i[ii], rm);
            float corr = __expf(m_i[ii] - mn);
            m_i[ii] = mn;
            float rsum = 0.f;
#pragma unroll
            for (int jj = 0; jj < 4; jj++) {
                s[ii][jj] = __expf(s[ii][jj] - mn);
                rsum += s[ii][jj];
            }
#pragma unroll
            for (int off = 8; off >= 1; off >>= 1)
                rsum += __shfl_xor_sync(0xffffffffu, rsum, off);
            l_i[ii] = l_i[ii] * corr + rsum;
#pragma unroll
            for (int jj = 0; jj < 4; jj++) o[ii][jj] *= corr;
        }
        __syncthreads();   // done reading Kt; Ps from prev iter consumed long ago

        // write P, load V into KV
#pragma unroll
        for (int ii = 0; ii < 4; ii++)
            *(float4*)&Ps[tr4 + ii][tc4] =
                make_float4(s[ii][0], s[ii][1], s[ii][2], s[ii][3]);
#pragma unroll
        for (int it = 0; it < 4; it++) {
            int e = tid + it * 256;
            int cc = e >> 4, dd = (e & 15) * 4;
            *(float4*)&KV[cc][dd] =
                *(const float4*)(g_v + (size_t)(k0 + cc) * 1024 + h * 64 + dd);
        }
        __syncthreads();

        // O += P @ V
#pragma unroll 8
        for (int c = 0; c < 64; c++) {
            float4 vv = *(const float4*)&KV[c][tc4];
            float vr[4] = {vv.x, vv.y, vv.z, vv.w};
            float pr[4];
#pragma unroll
            for (int ii = 0; ii < 4; ii++) pr[ii] = Ps[tr4 + ii][c];
#pragma unroll
            for (int ii = 0; ii < 4; ii++)
#pragma unroll
                for (int jj = 0; jj < 4; jj++)
                    o[ii][jj] += pr[ii] * vr[jj];
        }
        __syncthreads();
    }

    // normalize, gate, store
#pragma unroll
    for (int ii = 0; ii < 4; ii++) {
        float inv = 1.0f / l_i[ii];
        size_t off = (size_t)(q0 + tr4 + ii) * 1024 + h * 64 + tc4;
        float4 gg = *(const float4*)(g_g + off);
        float4 ov;
        ov.x = o[ii][0] * inv * gg.x;
        ov.y = o[ii][1] * inv * gg.y;
        ov.z = o[ii][2] * inv * gg.z;
        ov.w = o[ii][3] * inv * gg.w;
        *(float4*)(g_o + off) = ov;
    }
}

// ---------------------------------------------------------------------------
extern "C" void kernel_launch(void* const* d_in, const int* in_sizes, int n_in,
                              void* d_out, int out_size)
{
    const float* single = (const float*)d_in[0];
    const float* pw     = (const float*)d_in[1];
    const float* gamma  = (const float*)d_in[2];
    const float* beta   = (const float*)d_in[3];
    const float* Wb     = (const float*)d_in[4];
    const float* Wq     = (const float*)d_in[5];
    const float* Wk     = (const float*)d_in[6];
    const float* Wv     = (const float*)d_in[7];
    const float* Wg     = (const float*)d_in[8];
    const float* bg     = (const float*)d_in[9];
    const float* Wo     = (const float*)d_in[10];
    float* out = (float*)d_out;

    dim3 bgrid(8, 1024);
    bias_kernel<<<bgrid, 256>>>(pw, gamma, beta, Wb);

    dim3 ggrid(16, 16);
    gemm1024<<<ggrid, 256>>>(single, 0, Wq, nullptr, 1, nullptr, 1); // q: *0.125, T
    gemm1024<<<ggrid, 256>>>(single, 0, Wk, nullptr, 2, nullptr, 2); // k: T
    gemm1024<<<ggrid, 256>>>(single, 0, Wv, nullptr, 3, nullptr, 0); // v
    gemm1024<<<ggrid, 256>>>(single, 0, Wg, nullptr, 4, bg,      3); // gates

    dim3 agrid(16, 16);
    attn_kernel<<<agrid, 256>>>();

    gemm1024<<<ggrid, 256>>>(nullptr, 5, Wo, out, 0, nullptr, 0);    // final proj
}

// round 3
// speedup vs baseline: 1.1369x; 1.1369x over previous
#include <cuda_runtime.h>
#include <cuda_bf16.h>

#define NN (1024u*1024u)

// scratch (device globals: allocation-free)
__device__ float g_bias[16u*1024u*1024u]; // [h][i][j]
__device__ float g_qt[NN];                // [dim_inner][token], pre-scaled 0.125
__device__ float g_kt[NN];                // [dim_inner][token]
__device__ float g_v [NN];                // [token][dim_inner]
__device__ float g_g [NN];                // gates
__device__ __nv_bfloat16 g_shi[NN], g_slo[NN];        // single_repr hi/lo
__device__ __nv_bfloat16 g_wth[5][NN], g_wtl[5][NN];  // W^T [n][k] hi/lo
__device__ __nv_bfloat16 g_ohi[NN], g_olo[NN];        // gated attn out hi/lo

// ---------------------------------------------------------------------------
// Bias kernel (unchanged): LN over 128 pair features + project to 16 heads.
// ---------------------------------------------------------------------------
__global__ __launch_bounds__(256, 2) void bias_kernel(
    const float* __restrict__ pw, const float* __restrict__ gamma,
    const float* __restrict__ beta, const float* __restrict__ Wb)
{
    __shared__ float tile[16][129];
    int tid  = threadIdx.x;
    int lane = tid & 31, warp = tid >> 5;
    int i  = blockIdx.y;
    int j0 = blockIdx.x * 128;
    int p0 = lane * 4;

    float wg[4][16];
    float binit[16];
    {
        float4 gg = *(const float4*)(gamma + p0);
        float4 bb = *(const float4*)(beta  + p0);
        float g4[4] = {gg.x, gg.y, gg.z, gg.w};
        float b4[4] = {bb.x, bb.y, bb.z, bb.w};
#pragma unroll
        for (int h = 0; h < 16; h++) binit[h] = 0.f;
#pragma unroll
        for (int q = 0; q < 4; q++) {
#pragma unroll
            for (int h = 0; h < 16; h++) {
                float w = Wb[(p0 + q) * 16 + h];
                wg[q][h]  = g4[q] * w;
                binit[h] += b4[q] * w;
            }
        }
    }

    const float4* base = (const float4*)pw + ((size_t)i * 1024 + j0) * 32;
    float4 x = base[(size_t)warp * 32 + lane];
#pragma unroll 1
    for (int t = 0; t < 16; t++) {
        int jj = warp + 8 * t;
        float4 xn;
        if (t < 15) xn = base[(size_t)(jj + 8) * 32 + lane];

        float s  = x.x + x.y + x.z + x.w;
        float ss = x.x*x.x + x.y*x.y + x.z*x.z + x.w*x.w;
#pragma unroll
        for (int off = 16; off >= 1; off >>= 1) {
            s  += __shfl_xor_sync(0xffffffffu, s,  off);
            ss += __shfl_xor_sync(0xffffffffu, ss, off);
        }
        float mu  = s * 0.0078125f;
        float var = ss * 0.0078125f - mu * mu;
        float rs  = rsqrtf(var + 1e-5f);
        float t0 = (x.x - mu) * rs, t1 = (x.y - mu) * rs;
        float t2 = (x.z - mu) * rs, t3 = (x.w - mu) * rs;

        float acc[16];
#pragma unroll
        for (int h = 0; h < 16; h++)
            acc[h] = binit[h] + t0*wg[0][h] + t1*wg[1][h] + t2*wg[2][h] + t3*wg[3][h];

#pragma unroll
        for (int q = 0; q < 8; q++) {
            bool hi = (lane & 16);
            float keep = hi ? acc[q + 8] : acc[q];
            float send = hi ? acc[q]     : acc[q + 8];
            acc[q] = keep + __shfl_xor_sync(0xffffffffu, send, 16);
        }
#pragma unroll
        for (int q = 0; q < 4; q++) {
            bool hi = (lane & 8);
            float keep = hi ? acc[q + 4] : acc[q];
            float send = hi ? acc[q]     : acc[q + 4];
            acc[q] = keep + __shfl_xor_sync(0xffffffffu, send, 8);
        }
#pragma unroll
        for (int q = 0; q < 2; q++) {
            bool hi = (lane & 4);
            float keep = hi ? acc[q + 2] : acc[q];
            float send = hi ? acc[q]     : acc[q + 2];
            acc[q] = keep + __shfl_xor_sync(0xffffffffu, send, 4);
        }
        {
            bool hi = (lane & 2);
            float keep = hi ? acc[1] : acc[0];
            float send = hi ? acc[0] : acc[1];
            acc[0] = keep + __shfl_xor_sync(0xffffffffu, send, 2);
        }
        acc[0] += __shfl_xor_sync(0xffffffffu, acc[0], 1);
        int h = (lane >> 1) & 15;
        if ((lane & 1) == 0) tile[h][jj] = acc[0];
        x = xn;
    }
    __syncthreads();
    size_t obase = (size_t)i * 1024 + j0;
    for (int e = tid; e < 2048; e += 256) {
        int h = e >> 7, jj = e & 127;
        g_bias[(size_t)h * NN + obase + jj] = tile[h][jj];
    }
}

// ---------------------------------------------------------------------------
// Convert single_repr -> bf16 hi/lo, row-major (error-compensated split).
// ---------------------------------------------------------------------------
__global__ __launch_bounds__(256) void conv_plain(const float* __restrict__ src)
{
    unsigned i = blockIdx.x * 256u + threadIdx.x;   // 0 .. 262143
    float4 v = ((const float4*)src)[i];
    __nv_bfloat162 h01, h23, l01, l23;
    h01.x = __float2bfloat16(v.x); l01.x = __float2bfloat16(v.x - __bfloat162float(h01.x));
    h01.y = __float2bfloat16(v.y); l01.y = __float2bfloat16(v.y - __bfloat162float(h01.y));
    h23.x = __float2bfloat16(v.z); l23.x = __float2bfloat16(v.z - __bfloat162float(h23.x));
    h23.y = __float2bfloat16(v.w); l23.y = __float2bfloat16(v.w - __bfloat162float(h23.y));
    *(__nv_bfloat162*)(g_shi + 4u*i)     = h01;
    *(__nv_bfloat162*)(g_shi + 4u*i + 2) = h23;
    *(__nv_bfloat162*)(g_slo + 4u*i)     = l01;
    *(__nv_bfloat162*)(g_slo + 4u*i + 2) = l23;
}

// ---------------------------------------------------------------------------
// Convert + transpose weight: W[k][n] (1024x1024) -> WT[n][k] bf16 hi/lo.
// ---------------------------------------------------------------------------
__global__ __launch_bounds__(256) void convT(const float* __restrict__ W, int widx)
{
    __shared__ float ts[32][33];
    int tx = threadIdx.x, ty = threadIdx.y;
    int nx = blockIdx.x * 32 + tx;
#pragma unroll
    for (int i = 0; i < 4; i++)
        ts[ty + i*8][tx] = W[(size_t)(blockIdx.y*32 + ty + i*8) * 1024 + nx];
    __syncthreads();
    __nv_bfloat16* Th = g_wth[widx];
    __nv_bfloat16* Tl = g_wtl[widx];
#pragma unroll
    for (int i = 0; i < 4; i++) {
        int r = ty + i*8;
        float v = ts[tx][r];
        size_t o = (size_t)(blockIdx.x*32 + r) * 1024 + blockIdx.y*32 + tx;
        __nv_bfloat16 h = __float2bfloat16(v);
        Th[o] = h;
        Tl[o] = __float2bfloat16(v - __bfloat162float(h));
    }
}

// ---------------------------------------------------------------------------
// Tensor-core GEMM: C[m][n] = A[m][k] @ B[k][n], via bf16 split (3 mma passes).
// A given as hi/lo row-major; B given as hi/lo TRANSPOSED [n][k].
// Block 128(M)x64(N), BK=32, 8 warps (4x2), warp tile 32x32 (mma m16n8k16).
// mode: 0=natural 1=*0.125+T 2=T 3=sigmoid(x+aux[n])
// ---------------------------------------------------------------------------
#define MMA_BF16(c, a, b) asm volatile( \
    "mma.sync.aligned.m16n8k16.row.col.f32.bf16.bf16.f32 " \
    "{%0,%1,%2,%3},{%4,%5,%6,%7},{%8,%9},{%0,%1,%2,%3};" \
    : "+f"((c)[0]), "+f"((c)[1]), "+f"((c)[2]), "+f"((c)[3]) \
    : "r"((a)[0]), "r"((a)[1]), "r"((a)[2]), "r"((a)[3]), \
      "r"((b)[0]), "r"((b)[1]))

__global__ __launch_bounds__(256) void gemm_mma(
    int asel, int widx, float* __restrict__ Cext, int csel,
    const float* __restrict__ aux, int mode)
{
    const __nv_bfloat16* Ah = asel ? g_ohi : g_shi;
    const __nv_bfloat16* Al = asel ? g_olo : g_slo;
    const __nv_bfloat16* Bh = g_wth[widx];
    const __nv_bfloat16* Bl = g_wtl[widx];
    float* C = Cext;
    if      (csel == 1) C = g_qt;
    else if (csel == 2) C = g_kt;
    else if (csel == 3) C = g_v;
    else if (csel == 4) C = g_g;

    __shared__ __nv_bfloat16 sAh[128][40], sAl[128][40];
    __shared__ __nv_bfloat16 sBh[64][40],  sBl[64][40];

    int tid  = threadIdx.x;
    int lane = tid & 31, warp = tid >> 5;
    int gid  = lane >> 2, tg = lane & 3;
    int warp_m = (warp >> 1) * 32, warp_n = (warp & 1) * 32;
    int row0 = blockIdx.y * 128, col0 = blockIdx.x * 64;

    int arow = tid >> 2;            // 0..63 (two passes: +0, +64)
    int aseg = (tid & 3) * 8;       // bf16 col offset within BK=32
    int bn   = tid >> 2;            // 0..63
    int bseg = (tid & 3) * 8;

    float acc[2][4][4];
#pragma unroll
    for (int mt = 0; mt < 2; mt++)
#pragma unroll
        for (int nt = 0; nt < 4; nt++)
#pragma unroll
            for (int q = 0; q < 4; q++) acc[mt][nt][q] = 0.f;

    uint4 pAh0, pAh1, pAl0, pAl1, pBh, pBl;
    {
        const int k0 = 0;
        pAh0 = *(const uint4*)(Ah + (size_t)(row0 + arow)      * 1024 + k0 + aseg);
        pAh1 = *(const uint4*)(Ah + (size_t)(row0 + arow + 64) * 1024 + k0 + aseg);
        pAl0 = *(const uint4*)(Al + (size_t)(row0 + arow)      * 1024 + k0 + aseg);
        pAl1 = *(const uint4*)(Al + (size_t)(row0 + arow + 64) * 1024 + k0 + aseg);
        pBh  = *(const uint4*)(Bh + (size_t)(col0 + bn)        * 1024 + k0 + bseg);
        pBl  = *(const uint4*)(Bl + (size_t)(col0 + bn)        * 1024 + k0 + bseg);
    }

#pragma unroll 1
    for (int kt = 0; kt < 32; kt++) {
        __syncthreads();
        *(uint4*)&sAh[arow][aseg]      = pAh0;
        *(uint4*)&sAh[arow + 64][aseg] = pAh1;
        *(uint4*)&sAl[arow][aseg]      = pAl0;
        *(uint4*)&sAl[arow + 64][aseg] = pAl1;
        *(uint4*)&sBh[bn][bseg]        = pBh;
        *(uint4*)&sBl[bn][bseg]        = pBl;
        __syncthreads();
        if (kt < 31) {
            int k0 = (kt + 1) * 32;
            pAh0 = *(const uint4*)(Ah + (size_t)(row0 + arow)      * 1024 + k0 + aseg);
            pAh1 = *(const uint4*)(Ah + (size_t)(row0 + arow + 64) * 1024 + k0 + aseg);
            pAl0 = *(const uint4*)(Al + (size_t)(row0 + arow)      * 1024 + k0 + aseg);
            pAl1 = *(const uint4*)(Al + (size_t)(row0 + arow + 64) * 1024 + k0 + aseg);
            pBh  = *(const uint4*)(Bh + (size_t)(col0 + bn)        * 1024 + k0 + bseg);
            pBl  = *(const uint4*)(Bl + (size_t)(col0 + bn)        * 1024 + k0 + bseg);
        }

#pragma unroll
        for (int k16 = 0; k16 < 32; k16 += 16) {
            int kk = k16 + tg * 2;
            unsigned a_h[2][4], a_l[2][4], b_h[4][2], b_l[4][2];
#pragma unroll
            for (int mt = 0; mt < 2; mt++) {
                int r = warp_m + mt * 16 + gid;
                a_h[mt][0] = *(const unsigned*)&sAh[r][kk];
                a_h[mt][1] = *(const unsigned*)&sAh[r + 8][kk];
                a_h[mt][2] = *(const unsigned*)&sAh[r][kk + 8];
                a_h[mt][3] = *(const unsigned*)&sAh[r + 8][kk + 8];
            }
#pragma unroll
            for (int nt = 0; nt < 4; nt++) {
                int n = warp_n + nt * 8 + gid;
                b_h[nt][0] = *(const unsigned*)&sBh[n][kk];
                b_h[nt][1] = *(const unsigned*)&sBh[n][kk + 8];
            }
#pragma unroll
            for (int mt = 0; mt < 2; mt++)
#pragma unroll
                for (int nt = 0; nt < 4; nt++)
                    MMA_BF16(acc[mt][nt], a_h[mt], b_h[nt]);

#pragma unroll
            for (int nt = 0; nt < 4; nt++) {
                int n = warp_n + nt * 8 + gid;
                b_l[nt][0] = *(const unsigned*)&sBl[n][kk];
                b_l[nt][1] = *(const unsigned*)&sBl[n][kk + 8];
            }
#pragma unroll
            for (int mt = 0; mt < 2; mt++)
#pragma unroll
                for (int nt = 0; nt < 4; nt++)
                    MMA_BF16(acc[mt][nt], a_h[mt], b_l[nt]);

#pragma unroll
            for (int mt = 0; mt < 2; mt++) {
                int r = warp_m + mt * 16 + gid;
                a_l[mt][0] = *(const unsigned*)&sAl[r][kk];
                a_l[mt][1] = *(const unsigned*)&sAl[r + 8][kk];
                a_l[mt][2] = *(const unsigned*)&sAl[r][kk + 8];
                a_l[mt][3] = *(const unsigned*)&sAl[r + 8][kk + 8];
            }
#pragma unroll
            for (int mt = 0; mt < 2; mt++)
#pragma unroll
                for (int nt = 0; nt < 4; nt++)
                    MMA_BF16(acc[mt][nt], a_l[mt], b_h[nt]);
        }
    }

    // epilogue
#pragma unroll
    for (int mt = 0; mt < 2; mt++) {
#pragma unroll
        for (int nt = 0; nt < 4; nt++) {
            int rg = row0 + warp_m + mt * 16 + gid;
            int cg = col0 + warp_n + nt * 8 + tg * 2;
            float* a4 = acc[mt][nt];
            if (mode == 0) {
                *(float2*)&C[(size_t)rg * 1024 + cg]       = make_float2(a4[0], a4[1]);
                *(float2*)&C[(size_t)(rg + 8) * 1024 + cg] = make_float2(a4[2], a4[3]);
            } else if (mode == 1) {
                C[(size_t)cg * 1024 + rg]           = a4[0] * 0.125f;
                C[(size_t)(cg + 1) * 1024 + rg]     = a4[1] * 0.125f;
                C[(size_t)cg * 1024 + rg + 8]       = a4[2] * 0.125f;
                C[(size_t)(cg + 1) * 1024 + rg + 8] = a4[3] * 0.125f;
            } else if (mode == 2) {
                C[(size_t)cg * 1024 + rg]           = a4[0];
                C[(size_t)(cg + 1) * 1024 + rg]     = a4[1];
                C[(size_t)cg * 1024 + rg + 8]       = a4[2];
                C[(size_t)(cg + 1) * 1024 + rg + 8] = a4[3];
            } else {
                float b0 = aux[cg], b1 = aux[cg + 1];
                float v0 = 1.f / (1.f + __expf(-(a4[0] + b0)));
                float v1 = 1.f / (1.f + __expf(-(a4[1] + b1)));
                float v2 = 1.f / (1.f + __expf(-(a4[2] + b0)));
                float v3 = 1.f / (1.f + __expf(-(a4[3] + b1)));
                *(float2*)&C[(size_t)rg * 1024 + cg]       = make_float2(v0, v1);
                *(float2*)&C[(size_t)(rg + 8) * 1024 + cg] = make_float2(v2, v3);
            }
        }
    }
}

// ---------------------------------------------------------------------------
// Flash attention (32-query blocks), fused gating + bf16 hi/lo output.
// Grid (32 qblocks, 16 heads), 256 thr, 32KB smem -> high occupancy.
// ---------------------------------------------------------------------------
__global__ __launch_bounds__(256) void attn_kernel()
{
    __shared__ float Qt[64][32];   // [d][q]
    __shared__ float KV[64][64];   // phase1: [d][k]  phase2: [k][d]
    __shared__ float Ps[32][64];   // [q][k]
    int tid = threadIdx.x;
    int h   = blockIdx.y;
    int q0  = blockIdx.x * 32;
    int tr2 = (tid >> 4) * 2;
    int tc4 = (tid & 15) * 4;

#pragma unroll
    for (int it = 0; it < 2; it++) {
        int e = tid + it * 256;
        int dd = e >> 3, qc = (e & 7) * 4;
        *(float4*)&Qt[dd][qc] =
            *(const float4*)(g_qt + (size_t)(h * 64 + dd) * 1024 + q0 + qc);
    }
    float m_i[2] = {-1e30f, -1e30f}, l_i[2] = {0.f, 0.f};
    float o[2][4] = {};
    __syncthreads();

#pragma unroll 1
    for (int kb = 0; kb < 16; kb++) {
        int k0 = kb * 64;
#pragma unroll
        for (int it = 0; it < 4; it++) {
            int e = tid + it * 256;
            int dd = e >> 4, cc = (e & 15) * 4;
            *(float4*)&KV[dd][cc] =
                *(const float4*)(g_kt + (size_t)(h * 64 + dd) * 1024 + k0 + cc);
        }
        __syncthreads();

        float s[2][4];
#pragma unroll
        for (int ii = 0; ii < 2; ii++) {
            float4 bb = *(const float4*)(g_bias + (size_t)h * NN
                              + (size_t)(q0 + tr2 + ii) * 1024 + k0 + tc4);
            s[ii][0] = bb.x; s[ii][1] = bb.y; s[ii][2] = bb.z; s[ii][3] = bb.w;
        }
#pragma unroll 8
        for (int d = 0; d < 64; d++) {
            float2 qa = *(const float2*)&Qt[d][tr2];
            float4 ka = *(const float4*)&KV[d][tc4];
            float ar[2] = {qa.x, qa.y};
            float br[4] = {ka.x, ka.y, ka.z, ka.w};
#pragma unroll
            for (int ii = 0; ii < 2; ii++)
#pragma unroll
                for (int jj = 0; jj < 4; jj++)
                    s[ii][jj] += ar[ii] * br[jj];
        }

#pragma unroll
        for (int ii = 0; ii < 2; ii++) {
            float rm = fmaxf(fmaxf(s[ii][0], s[ii][1]), fmaxf(s[ii][2], s[ii][3]));
#pragma unroll
            for (int off = 8; off >= 1; off >>= 1)
                rm = fmaxf(rm, __shfl_xor_sync(0xffffffffu, rm, off));
            float mn   = fmaxf(m_i[ii], rm);
            float corr = __expf(m_i[ii] - mn);
            m_i[ii] = mn;
            float rsum = 0.f;
#pragma unroll
            for (int jj = 0; jj < 4; jj++) {
                s[ii][jj] = __expf(s[ii][jj] - mn);
                rsum += s[ii][jj];
            }
#pragma unroll
            for (int off = 8; off >= 1; off >>= 1)
                rsum += __shfl_xor_sync(0xffffffffu, rsum, off);
            l_i[ii] = l_i[ii] * corr + rsum;
#pragma unroll
            for (int jj = 0; jj < 4; jj++) o[ii][jj] *= corr;
        }
        __syncthreads();

#pragma unroll
        for (int ii = 0; ii < 2; ii++)
            *(float4*)&Ps[tr2 + ii][tc4] =
                make_float4(s[ii][0], s[ii][1], s[ii][2], s[ii][3]);
#pragma unroll
        for (int it = 0; it < 4; it++) {
            int e = tid + it * 256;
            int cc = e >> 4, dd = (e & 15) * 4;
            *(float4*)&KV[cc][dd] =
                *(const float4*)(g_v + (size_t)(k0 + cc) * 1024 + h * 64 + dd);
        }
        __syncthreads();

#pragma unroll 8
        for (int c = 0; c < 64; c++) {
            float4 vv = *(const float4*)&KV[c][tc4];
            float vr[4] = {vv.x, vv.y, vv.z, vv.w};
            float pr[2];
#pragma unroll
            for (int ii = 0; ii < 2; ii++) pr[ii] = Ps[tr2 + ii][c];
#pragma unroll
            for (int ii = 0; ii < 2; ii++)
#pragma unroll
                for (int jj = 0; jj < 4; jj++)
                    o[ii][jj] += pr[ii] * vr[jj];
        }
        __syncthreads();
    }

    // normalize, gate, split to bf16 hi/lo for the output GEMM
#pragma unroll
    for (int ii = 0; ii < 2; ii++) {
        float inv = 1.0f / l_i[ii];
        size_t off = (size_t)(q0 + tr2 + ii) * 1024 + h * 64 + tc4;
        float4 gg = *(const float4*)(g_g + off);
        float v0 = o[ii][0] * inv * gg.x;
        float v1 = o[ii][1] * inv * gg.y;
        float v2 = o[ii][2] * inv * gg.z;
        float v3 = o[ii][3] * inv * gg.w;
        __nv_bfloat162 h01, h23, l01, l23;
        h01.x = __float2bfloat16(v0); l01.x = __float2bfloat16(v0 - __bfloat162float(h01.x));
        h01.y = __float2bfloat16(v1); l01.y = __float2bfloat16(v1 - __bfloat162float(h01.y));
        h23.x = __float2bfloat16(v2); l23.x = __float2bfloat16(v2 - __bfloat162float(h23.x));
        h23.y = __float2bfloat16(v3); l23.y = __float2bfloat16(v3 - __bfloat162float(h23.y));
        *(__nv_bfloat162*)(g_ohi + off)     = h01;
        *(__nv_bfloat162*)(g_ohi + off + 2) = h23;
        *(__nv_bfloat162*)(g_olo + off)     = l01;
        *(__nv_bfloat162*)(g_olo + off + 2) = l23;
    }
}

// ---------------------------------------------------------------------------
extern "C" void kernel_launch(void* const* d_in, const int* in_sizes, int n_in,
                              void* d_out, int out_size)
{
    const float* single = (const float*)d_in[0];
    const float* pw     = (const float*)d_in[1];
    const float* gamma  = (const float*)d_in[2];
    const float* beta   = (const float*)d_in[3];
    const float* Wb     = (const float*)d_in[4];
    const float* Wq     = (const float*)d_in[5];
    const float* Wk     = (const float*)d_in[6];
    const float* Wv     = (const float*)d_in[7];
    const float* Wg     = (const float*)d_in[8];
    const float* bg     = (const float*)d_in[9];
    const float* Wo     = (const float*)d_in[10];
    float* out = (float*)d_out;

    dim3 bgrid(8, 1024);
    bias_kernel<<<bgrid, 256>>>(pw, gamma, beta, Wb);

    conv_plain<<<1024, 256>>>(single);
    dim3 tgrid(32, 32), tblk(32, 8);
    convT<<<tgrid, tblk>>>(Wq, 0);
    convT<<<tgrid, tblk>>>(Wk, 1);
    convT<<<tgrid, tblk>>>(Wv, 2);
    convT<<<tgrid, tblk>>>(Wg, 3);
    convT<<<tgrid, tblk>>>(Wo, 4);

    dim3 ggrid(16, 8);  // (N/64, M/128)
    gemm_mma<<<ggrid, 256>>>(0, 0, nullptr, 1, nullptr, 1); // Q: *0.125, T
    gemm_mma<<<ggrid, 256>>>(0, 1, nullptr, 2, nullptr, 2); // K: T
    gemm_mma<<<ggrid, 256>>>(0, 2, nullptr, 3, nullptr, 0); // V
    gemm_mma<<<ggrid, 256>>>(0, 3, nullptr, 4, bg,      3); // gates

    dim3 agrid(32, 16);
    attn_kernel<<<agrid, 256>>>();

    gemm_mma<<<ggrid, 256>>>(1, 4, out, 0, nullptr, 0);     // final proj
}

// round 4
// speedup vs baseline: 2.0288x; 1.7846x over previous
#include <cuda_runtime.h>
#include <cuda_bf16.h>

#define NN (1024u*1024u)

// scratch (device globals: allocation-free)
__device__ float g_bias[16u*1024u*1024u]; // [h][i][j]
__device__ float g_g [NN];                // gates fp32 [token][dim_inner]
__device__ __nv_bfloat16 g_shi[NN], g_slo[NN];        // single_repr hi/lo
__device__ __nv_bfloat16 g_wth[5][NN], g_wtl[5][NN];  // W^T [n][k] hi/lo
__device__ __nv_bfloat16 g_ohi[NN], g_olo[NN];        // gated attn out hi/lo
__device__ __nv_bfloat16 g_qh[NN], g_ql[NN];          // Q [tok][d_inner] *0.125
__device__ __nv_bfloat16 g_kh[NN], g_kl[NN];          // K [tok][d_inner]
__device__ __nv_bfloat16 g_vh[NN], g_vl[NN];          // V [tok][d_inner]
__device__ __nv_bfloat16 g_vth[NN], g_vtl[NN];        // V^T [d_inner][tok]
__device__ __nv_bfloat16 g_wbth[16*128], g_wbtl[16*128]; // (gamma*Wb)^T [h][p]
__device__ float g_binit[16];                            // beta @ Wb

__device__ __forceinline__ unsigned pk2(float a, float b) {
    __nv_bfloat162 t = __floats2bfloat162_rn(a, b);
    return *reinterpret_cast<unsigned*>(&t);
}
__device__ __forceinline__ float lores(float a) {
    return a - __bfloat162float(__float2bfloat16(a));
}

#define MMA_BF16(c, a, b) asm volatile( \
    "mma.sync.aligned.m16n8k16.row.col.f32.bf16.bf16.f32 " \
    "{%0,%1,%2,%3},{%4,%5,%6,%7},{%8,%9},{%0,%1,%2,%3};" \
    : "+f"((c)[0]), "+f"((c)[1]), "+f"((c)[2]), "+f"((c)[3]) \
    : "r"((a)[0]), "r"((a)[1]), "r"((a)[2]), "r"((a)[3]), \
      "r"((b)[0]), "r"((b)[1]))

// ---------------------------------------------------------------------------
// One-time prep: (gamma*W_bias)^T as bf16 hi/lo, and beta@W_bias.
// ---------------------------------------------------------------------------
__global__ void bias_setup(const float* __restrict__ gamma,
                           const float* __restrict__ beta,
                           const float* __restrict__ Wb)
{
    int tid = threadIdx.x;
    for (int idx = tid; idx < 2048; idx += 128) {
        int p = idx >> 4, h = idx & 15;
        float w = gamma[p] * Wb[idx];
        __nv_bfloat16 hi = __float2bfloat16(w);
        g_wbth[h * 128 + p] = hi;
        g_wbtl[h * 128 + p] = __float2bfloat16(w - __bfloat162float(hi));
    }
    if (tid < 16) {
        float s = 0.f;
        for (int p = 0; p < 128; p++) s += beta[p] * Wb[p * 16 + tid];
        g_binit[tid] = s;
    }
}

// ---------------------------------------------------------------------------
// Bias kernel: LN (SIMT, fp32 stats) + 128->16 projection on tensor cores.
// Block 128 thr (4 warps), tile = 64 rows (j) x 128 features, i = blockIdx.y.
// ---------------------------------------------------------------------------
__global__ __launch_bounds__(128) void bias_kernel(const float* __restrict__ pw)
{
    __shared__ __nv_bfloat16 sXh[64][136], sXl[64][136];
    __shared__ __nv_bfloat16 sWh[16][136], sWl[16][136];
    __shared__ float stage[16][64];
    __shared__ float sbin[16];

    int tid  = threadIdx.x;
    int lane = tid & 31, warp = tid >> 5;
    int gid  = lane >> 2, tg = lane & 3;
    int i  = blockIdx.y;
    int j0 = blockIdx.x * 64;

    for (int idx = tid; idx < 2048; idx += 128) {
        int h = idx >> 7, p = idx & 127;
        sWh[h][p] = g_wbth[idx];
        sWl[h][p] = g_wbtl[idx];
    }
    if (tid < 16) sbin[tid] = g_binit[tid];

    // LN: warp w handles rows w*16 .. w*16+15
    {
        const float4* rowp = (const float4*)(pw
            + ((size_t)i * 1024 + j0 + warp * 16) * 128) + lane;
        float4 x = rowp[0];
#pragma unroll 1
        for (int rr = 0; rr < 16; rr++) {
            float4 xn;
            if (rr < 15) xn = rowp[(rr + 1) * 32];
            float s  = x.x + x.y + x.z + x.w;
            float ss = x.x*x.x + x.y*x.y + x.z*x.z + x.w*x.w;
#pragma unroll
            for (int off = 16; off >= 1; off >>= 1) {
                s  += __shfl_xor_sync(0xffffffffu, s,  off);
                ss += __shfl_xor_sync(0xffffffffu, ss, off);
            }
            float mu  = s * 0.0078125f;
            float var = ss * 0.0078125f - mu * mu;
            float rs  = rsqrtf(var + 1e-5f);
            float y0 = (x.x - mu) * rs, y1 = (x.y - mu) * rs;
            float y2 = (x.z - mu) * rs, y3 = (x.w - mu) * rs;
            int r = warp * 16 + rr;
            uint2 ph = make_uint2(pk2(y0, y1), pk2(y2, y3));
            uint2 pl = make_uint2(pk2(lores(y0), lores(y1)),
                                  pk2(lores(y2), lores(y3)));
            *(uint2*)&sXh[r][lane * 4] = ph;
            *(uint2*)&sXl[r][lane * 4] = pl;
            x = xn;
        }
    }
    __syncthreads();

    // MMA: warp = m16 tile of rows, N = 16 (two n8 tiles), K = 128.
    float acc[2][4] = {};
    int warp_m = warp * 16;
#pragma unroll
    for (int c = 0; c < 8; c++) {
        int kk = c * 16 + tg * 2;
        unsigned ah[4], al[4], bh[2][2], bl[2][2];
        int r = warp_m + gid;
        ah[0] = *(const unsigned*)&sXh[r][kk];
        ah[1] = *(const unsigned*)&sXh[r + 8][kk];
        ah[2] = *(const unsigned*)&sXh[r][kk + 8];
        ah[3] = *(const unsigned*)&sXh[r + 8][kk + 8];
        al[0] = *(const unsigned*)&sXl[r][kk];
        al[1] = *(const unsigned*)&sXl[r + 8][kk];
        al[2] = *(const unsigned*)&sXl[r][kk + 8];
        al[3] = *(const unsigned*)&sXl[r + 8][kk + 8];
#pragma unroll
        for (int t = 0; t < 2; t++) {
            int n = t * 8 + gid;
            bh[t][0] = *(const unsigned*)&sWh[n][kk];
            bh[t][1] = *(const unsigned*)&sWh[n][kk + 8];
            bl[t][0] = *(const unsigned*)&sWl[n][kk];
            bl[t][1] = *(const unsigned*)&sWl[n][kk + 8];
        }
#pragma unroll
        for (int t = 0; t < 2; t++) {
            MMA_BF16(acc[t], ah, bh[t]);
            MMA_BF16(acc[t], ah, bl[t]);
            MMA_BF16(acc[t], al, bh[t]);
        }
    }
#pragma unroll
    for (int t = 0; t < 2; t++) {
        int hc = t * 8 + tg * 2;
        int r  = warp_m + gid;
        stage[hc][r]         = acc[t][0];
        stage[hc + 1][r]     = acc[t][1];
        stage[hc][r + 8]     = acc[t][2];
        stage[hc + 1][r + 8] = acc[t][3];
    }
    __syncthreads();
    size_t obase = (size_t)i * 1024 + j0;
    for (int e = tid; e < 1024; e += 128) {
        int hh = e >> 6, j = e & 63;
        g_bias[(size_t)hh * NN + obase + j] = stage[hh][j] + sbin[hh];
    }
}

// ---------------------------------------------------------------------------
// Convert single_repr -> bf16 hi/lo, row-major.
// ---------------------------------------------------------------------------
__global__ __launch_bounds__(256) void conv_plain(const float* __restrict__ src)
{
    unsigned i = blockIdx.x * 256u + threadIdx.x;
    float4 v = ((const float4*)src)[i];
    *(unsigned*)(g_shi + 4u*i)     = pk2(v.x, v.y);
    *(unsigned*)(g_shi + 4u*i + 2) = pk2(v.z, v.w);
    *(unsigned*)(g_slo + 4u*i)     = pk2(lores(v.x), lores(v.y));
    *(unsigned*)(g_slo + 4u*i + 2) = pk2(lores(v.z), lores(v.w));
}

// ---------------------------------------------------------------------------
// Convert + transpose weight: W[k][n] -> WT[n][k] bf16 hi/lo.
// ---------------------------------------------------------------------------
__global__ __launch_bounds__(256) void convT(const float* __restrict__ W, int widx)
{
    __shared__ float ts[32][33];
    int tx = threadIdx.x, ty = threadIdx.y;
    int nx = blockIdx.x * 32 + tx;
#pragma unroll
    for (int i = 0; i < 4; i++)
        ts[ty + i*8][tx] = W[(size_t)(blockIdx.y*32 + ty + i*8) * 1024 + nx];
    __syncthreads();
    __nv_bfloat16* Th = g_wth[widx];
    __nv_bfloat16* Tl = g_wtl[widx];
#pragma unroll
    for (int i = 0; i < 4; i++) {
        int r = ty + i*8;
        float v = ts[tx][r];
        size_t o = (size_t)(blockIdx.x*32 + r) * 1024 + blockIdx.y*32 + tx;
        __nv_bfloat16 h = __float2bfloat16(v);
        Th[o] = h;
        Tl[o] = __float2bfloat16(v - __bfloat162float(h));
    }
}

// ---------------------------------------------------------------------------
// bf16 transpose: g_vh/g_vl [tok][d] -> g_vth/g_vtl [d][tok].
// ---------------------------------------------------------------------------
__global__ __launch_bounds__(256) void vtrans()
{
    __shared__ __nv_bfloat16 th[64][72], tl[64][72];
    int tx = threadIdx.x, ty = threadIdx.y;
    int r0 = blockIdx.y * 64, c0 = blockIdx.x * 64;
#pragma unroll
    for (int i = 0; i < 8; i++) {
        int rr = ty + i * 8;
        *(unsigned*)&th[rr][tx*2] = *(const unsigned*)&g_vh[(size_t)(r0+rr)*1024 + c0 + tx*2];
        *(unsigned*)&tl[rr][tx*2] = *(const unsigned*)&g_vl[(size_t)(r0+rr)*1024 + c0 + tx*2];
    }
    __syncthreads();
#pragma unroll
    for (int i = 0; i < 8; i++) {
        int rc = ty + i * 8;   // output row (d)
        __nv_bfloat162 vh, vl;
        vh.x = th[tx*2][rc];   vh.y = th[tx*2+1][rc];
        vl.x = tl[tx*2][rc];   vl.y = tl[tx*2+1][rc];
        *(unsigned*)&g_vth[(size_t)(c0+rc)*1024 + r0 + tx*2] = *(unsigned*)&vh;
        *(unsigned*)&g_vtl[(size_t)(c0+rc)*1024 + r0 + tx*2] = *(unsigned*)&vl;
    }
}

// ---------------------------------------------------------------------------
// Tensor-core GEMM: C = A @ B via bf16 split (3 passes).
// A hi/lo row-major; B hi/lo transposed [n][k].
// mode: 0=fp32 natural -> Cext   3=sigmoid(x+aux) fp32 -> g_g
//       4=bf16 split natural * scale -> (dsel: 0=Q 1=K 2=V)
// ---------------------------------------------------------------------------
__global__ __launch_bounds__(256) void gemm_mma(
    int asel, int widx, float* __restrict__ Cext,
    const float* __restrict__ aux, int mode, int dsel, float scale)
{
    const __nv_bfloat16* Ah = asel ? g_ohi : g_shi;
    const __nv_bfloat16* Al = asel ? g_olo : g_slo;
    const __nv_bfloat16* Bh = g_wth[widx];
    const __nv_bfloat16* Bl = g_wtl[widx];

    __shared__ __nv_bfloat16 sAh[128][40], sAl[128][40];
    __shared__ __nv_bfloat16 sBh[64][40],  sBl[64][40];

    int tid  = threadIdx.x;
    int lane = tid & 31, warp = tid >> 5;
    int gid  = lane >> 2, tg = lane & 3;
    int warp_m = (warp >> 1) * 32, warp_n = (warp & 1) * 32;
    int row0 = blockIdx.y * 128, col0 = blockIdx.x * 64;

    int arow = tid >> 2;
    int aseg = (tid & 3) * 8;
    int bn   = tid >> 2;
    int bseg = (tid & 3) * 8;

    float acc[2][4][4];
#pragma unroll
    for (int mt = 0; mt < 2; mt++)
#pragma unroll
        for (int nt = 0; nt < 4; nt++)
#pragma unroll
            for (int q = 0; q < 4; q++) acc[mt][nt][q] = 0.f;

    uint4 pAh0, pAh1, pAl0, pAl1, pBh, pBl;
    pAh0 = *(const uint4*)(Ah + (size_t)(row0 + arow)      * 1024 + aseg);
    pAh1 = *(const uint4*)(Ah + (size_t)(row0 + arow + 64) * 1024 + aseg);
    pAl0 = *(const uint4*)(Al + (size_t)(row0 + arow)      * 1024 + aseg);
    pAl1 = *(const uint4*)(Al + (size_t)(row0 + arow + 64) * 1024 + aseg);
    pBh  = *(const uint4*)(Bh + (size_t)(col0 + bn)        * 1024 + bseg);
    pBl  = *(const uint4*)(Bl + (size_t)(col0 + bn)        * 1024 + bseg);

#pragma unroll 1
    for (int kt = 0; kt < 32; kt++) {
        __syncthreads();
        *(uint4*)&sAh[arow][aseg]      = pAh0;
        *(uint4*)&sAh[arow + 64][aseg] = pAh1;
        *(uint4*)&sAl[arow][aseg]      = pAl0;
        *(uint4*)&sAl[arow + 64][aseg] = pAl1;
        *(uint4*)&sBh[bn][bseg]        = pBh;
        *(uint4*)&sBl[bn][bseg]        = pBl;
        __syncthreads();
        if (kt < 31) {
            int k0 = (kt + 1) * 32;
            pAh0 = *(const uint4*)(Ah + (size_t)(row0 + arow)      * 1024 + k0 + aseg);
            pAh1 = *(const uint4*)(Ah + (size_t)(row0 + arow + 64) * 1024 + k0 + aseg);
            pAl0 = *(const uint4*)(Al + (size_t)(row0 + arow)      * 1024 + k0 + aseg);
            pAl1 = *(const uint4*)(Al + (size_t)(row0 + arow + 64) * 1024 + k0 + aseg);
            pBh  = *(const uint4*)(Bh + (size_t)(col0 + bn)        * 1024 + k0 + bseg);
            pBl  = *(const uint4*)(Bl + (size_t)(col0 + bn)        * 1024 + k0 + bseg);
        }

#pragma unroll
        for (int k16 = 0; k16 < 32; k16 += 16) {
            int kk = k16 + tg * 2;
            unsigned a_h[2][4], a_l[2][4], b_h[4][2], b_l[4][2];
#pragma unroll
            for (int mt = 0; mt < 2; mt++) {
                int r = warp_m + mt * 16 + gid;
                a_h[mt][0] = *(const unsigned*)&sAh[r][kk];
                a_h[mt][1] = *(const unsigned*)&sAh[r + 8][kk];
                a_h[mt][2] = *(const unsigned*)&sAh[r][kk + 8];
                a_h[mt][3] = *(const unsigned*)&sAh[r + 8][kk + 8];
            }
#pragma unroll
            for (int nt = 0; nt < 4; nt++) {
                int n = warp_n + nt * 8 + gid;
                b_h[nt][0] = *(const unsigned*)&sBh[n][kk];
                b_h[nt][1] = *(const unsigned*)&sBh[n][kk + 8];
            }
#pragma unroll
            for (int mt = 0; mt < 2; mt++)
#pragma unroll
                for (int nt = 0; nt < 4; nt++)
                    MMA_BF16(acc[mt][nt], a_h[mt], b_h[nt]);
#pragma unroll
            for (int nt = 0; nt < 4; nt++) {
                int n = warp_n + nt * 8 + gid;
                b_l[nt][0] = *(const unsigned*)&sBl[n][kk];
                b_l[nt][1] = *(const unsigned*)&sBl[n][kk + 8];
            }
#pragma unroll
            for (int mt = 0; mt < 2; mt++)
#pragma unroll
                for (int nt = 0; nt < 4; nt++)
                    MMA_BF16(acc[mt][nt], a_h[mt], b_l[nt]);
#pragma unroll
            for (int mt = 0; mt < 2; mt++) {
                int r = warp_m + mt * 16 + gid;
                a_l[mt][0] = *(const unsigned*)&sAl[r][kk];
                a_l[mt][1] = *(const unsigned*)&sAl[r + 8][kk];
                a_l[mt][2] = *(const unsigned*)&sAl[r][kk + 8];
                a_l[mt][3] = *(const unsigned*)&sAl[r + 8][kk + 8];
            }
#pragma unroll
            for (int mt = 0; mt < 2; mt++)
#pragma unroll
                for (int nt = 0; nt < 4; nt++)
                    MMA_BF16(acc[mt][nt], a_l[mt], b_h[nt]);
        }
    }

    __nv_bfloat16* Dh = (dsel == 0) ? g_qh : (dsel == 1) ? g_kh : g_vh;
    __nv_bfloat16* Dl = (dsel == 0) ? g_ql : (dsel == 1) ? g_kl : g_vl;
#pragma unroll
    for (int mt = 0; mt < 2; mt++) {
#pragma unroll
        for (int nt = 0; nt < 4; nt++) {
            int rg = row0 + warp_m + mt * 16 + gid;
            int cg = col0 + warp_n + nt * 8 + tg * 2;
            float* a4 = acc[mt][nt];
            if (mode == 0) {
                *(float2*)&Cext[(size_t)rg * 1024 + cg]       = make_float2(a4[0], a4[1]);
                *(float2*)&Cext[(size_t)(rg + 8) * 1024 + cg] = make_float2(a4[2], a4[3]);
            } else if (mode == 3) {
                float b0 = aux[cg], b1 = aux[cg + 1];
                float v0 = 1.f / (1.f + __expf(-(a4[0] + b0)));
                float v1 = 1.f / (1.f + __expf(-(a4[1] + b1)));
                float v2 = 1.f / (1.f + __expf(-(a4[2] + b0)));
                float v3 = 1.f / (1.f + __expf(-(a4[3] + b1)));
                *(float2*)&g_g[(size_t)rg * 1024 + cg]       = make_float2(v0, v1);
                *(float2*)&g_g[(size_t)(rg + 8) * 1024 + cg] = make_float2(v2, v3);
            } else {
                float v0 = a4[0] * scale, v1 = a4[1] * scale;
                float v2 = a4[2] * scale, v3 = a4[3] * scale;
                *(unsigned*)&Dh[(size_t)rg * 1024 + cg]       = pk2(v0, v1);
                *(unsigned*)&Dh[(size_t)(rg + 8) * 1024 + cg] = pk2(v2, v3);
                *(unsigned*)&Dl[(size_t)rg * 1024 + cg]       = pk2(lores(v0), lores(v1));
                *(unsigned*)&Dl[(size_t)(rg + 8) * 1024 + cg] = pk2(lores(v2), lores(v3));
            }
        }
    }
}

// ---------------------------------------------------------------------------
// Flash attention on tensor cores. 256 thr = 8 warps, each warp m16 q-rows
// -> 128 queries/CTA. Grid (8, 16) = 128 CTAs (one wave).
// S acc initialized from pair bias; P reused in regs as PV's A-fragment.
// ---------------------------------------------------------------------------
__global__ __launch_bounds__(256) void attn_kernel()
{
    __shared__ __nv_bfloat16 sKh[64][72], sKl[64][72];
    __shared__ __nv_bfloat16 sVh[64][72], sVl[64][72];

    int tid  = threadIdx.x;
    int lane = tid & 31, warp = tid >> 5;
    int gid  = lane >> 2, tg = lane & 3;
    int h  = blockIdx.y;
    int q0 = blockIdx.x * 128;
    int warp_m = warp * 16;
    int qrow = q0 + warp_m + gid;

    // Q fragments (hi/lo) straight from gmem
    unsigned qh[4][4], ql[4][4];
    {
        const __nv_bfloat16* Qh = g_qh + (size_t)qrow * 1024 + h * 64;
        const __nv_bfloat16* Ql = g_ql + (size_t)qrow * 1024 + h * 64;
#pragma unroll
        for (int c = 0; c < 4; c++) {
            int kk = c * 16 + tg * 2;
            qh[c][0] = *(const unsigned*)(Qh + kk);
            qh[c][1] = *(const unsigned*)(Qh + 8 * 1024 + kk);
            qh[c][2] = *(const unsigned*)(Qh + kk + 8);
            qh[c][3] = *(const unsigned*)(Qh + 8 * 1024 + kk + 8);
            ql[c][0] = *(const unsigned*)(Ql + kk);
            ql[c][1] = *(const unsigned*)(Ql + 8 * 1024 + kk);
            ql[c][2] = *(const unsigned*)(Ql + kk + 8);
            ql[c][3] = *(const unsigned*)(Ql + 8 * 1024 + kk + 8);
        }
    }

    float m0 = -1e30f, m1 = -1e30f, l0 = 0.f, l1 = 0.f;
    float O[8][4] = {};

    int lr = tid >> 2;            // 0..63 tile row for loads
    int cs = (tid & 3) * 16;      // 16-elem col segment

#pragma unroll 1
    for (int kb = 0; kb < 16; kb++) {
        int k0 = kb * 64;
        {
            const __nv_bfloat16* kh = g_kh  + (size_t)(k0 + lr) * 1024 + h * 64 + cs;
            const __nv_bfloat16* kl = g_kl  + (size_t)(k0 + lr) * 1024 + h * 64 + cs;
            const __nv_bfloat16* vh = g_vth + (size_t)(h * 64 + lr) * 1024 + k0 + cs;
            const __nv_bfloat16* vl = g_vtl + (size_t)(h * 64 + lr) * 1024 + k0 + cs;
            *(uint4*)&sKh[lr][cs]     = *(const uint4*)kh;
            *(uint4*)&sKh[lr][cs + 8] = *((const uint4*)kh + 1);
            *(uint4*)&sKl[lr][cs]     = *(const uint4*)kl;
            *(uint4*)&sKl[lr][cs + 8] = *((const uint4*)kl + 1);
            *(uint4*)&sVh[lr][cs]     = *(const uint4*)vh;
            *(uint4*)&sVh[lr][cs + 8] = *((const uint4*)vh + 1);
            *(uint4*)&sVl[lr][cs]     = *(const uint4*)vl;
            *(uint4*)&sVl[lr][cs + 8] = *((const uint4*)vl + 1);
        }
        __syncthreads();

        // S acc initialized with pair bias
        float S[8][4];
        {
            const float* bptr = g_bias + (size_t)h * NN + (size_t)qrow * 1024 + k0;
#pragma unroll
            for (int t = 0; t < 8; t++) {
                float2 b0 = *(const float2*)(bptr + 8 * t + 2 * tg);
                float2 b1 = *(const float2*)(bptr + 8 * 1024 + 8 * t + 2 * tg);
                S[t][0] = b0.x; S[t][1] = b0.y; S[t][2] = b1.x; S[t][3] = b1.y;
            }
        }
        // S += Q K^T (3-pass split)
#pragma unroll
        for (int c = 0; c < 4; c++) {
            int kk = c * 16 + tg * 2;
            unsigned bh[8][2], bl[8][2];
#pragma unroll
            for (int t = 0; t < 8; t++) {
                int n = t * 8 + gid;
                bh[t][0] = *(const unsigned*)&sKh[n][kk];
                bh[t][1] = *(const unsigned*)&sKh[n][kk + 8];
                bl[t][0] = *(const unsigned*)&sKl[n][kk];
                bl[t][1] = *(const unsigned*)&sKl[n][kk + 8];
            }
#pragma unroll
            for (int t = 0; t < 8; t++) {
                MMA_BF16(S[t], qh[c], bh[t]);
                MMA_BF16(S[t], qh[c], bl[t]);
                MMA_BF16(S[t], ql[c], bh[t]);
            }
        }

        // online softmax; rows gid (S[t][0..1]) and gid+8 (S[t][2..3])
        float rm0 = -1e30f, rm1 = -1e30f;
#pragma unroll
        for (int t = 0; t < 8; t++) {
            rm0 = fmaxf(rm0, fmaxf(S[t][0], S[t][1]));
            rm1 = fmaxf(rm1, fmaxf(S[t][2], S[t][3]));
        }
        rm0 = fmaxf(rm0, __shfl_xor_sync(0xffffffffu, rm0, 1));
        rm0 = fmaxf(rm0, __shfl_xor_sync(0xffffffffu, rm0, 2));
        rm1 = fmaxf(rm1, __shfl_xor_sync(0xffffffffu, rm1, 1));
        rm1 = fmaxf(rm1, __shfl_xor_sync(0xffffffffu, rm1, 2));
        float mn0 = fmaxf(m0, rm0), mn1 = fmaxf(m1, rm1);
        float c0 = __expf(m0 - mn0), c1 = __expf(m1 - mn1);
        m0 = mn0; m1 = mn1;
        float ps0 = 0.f, ps1 = 0.f;
#pragma unroll
        for (int t = 0; t < 8; t++) {
            S[t][0] = __expf(S[t][0] - mn0);
            S[t][1] = __expf(S[t][1] - mn0);
            S[t][2] = __expf(S[t][2] - mn1);
            S[t][3] = __expf(S[t][3] - mn1);
            ps0 += S[t][0] + S[t][1];
            ps1 += S[t][2] + S[t][3];
        }
        ps0 += __shfl_xor_sync(0xffffffffu, ps0, 1);
        ps0 += __shfl_xor_sync(0xffffffffu, ps0, 2);
        ps1 += __shfl_xor_sync(0xffffffffu, ps1, 1);
        ps1 += __shfl_xor_sync(0xffffffffu, ps1, 2);
        l0 = l0 * c0 + ps0;
        l1 = l1 * c1 + ps1;
#pragma unroll
        for (int t = 0; t < 8; t++) {
            O[t][0] *= c0; O[t][1] *= c0; O[t][2] *= c1; O[t][3] *= c1;
        }

        // P as A-fragments (hi + residual lo), register reuse
        unsigned ph[4][4], pl[4][4];
#pragma unroll
        for (int c = 0; c < 4; c++) {
            int t0 = 2 * c, t1 = 2 * c + 1;
            ph[c][0] = pk2(S[t0][0], S[t0][1]);
            ph[c][1] = pk2(S[t0][2], S[t0][3]);
            ph[c][2] = pk2(S[t1][0], S[t1][1]);
            ph[c][3] = pk2(S[t1][2], S[t1][3]);
            pl[c][0] = pk2(lores(S[t0][0]), lores(S[t0][1]));
            pl[c][1] = pk2(lores(S[t0][2]), lores(S[t0][3]));
            pl[c][2] = pk2(lores(S[t1][0]), lores(S[t1][1]));
            pl[c][3] = pk2(lores(S[t1][2]), lores(S[t1][3]));
        }

        // O += P V (3-pass split); B from V^T tile
#pragma unroll
        for (int c = 0; c < 4; c++) {
            int kk = c * 16 + tg * 2;
            unsigned bvh[8][2], bvl[8][2];
#pragma unroll
            for (int t = 0; t < 8; t++) {
                int n = t * 8 + gid;
                bvh[t][0] = *(const unsigned*)&sVh[n][kk];
                bvh[t][1] = *(const unsigned*)&sVh[n][kk + 8];
                bvl[t][0] = *(const unsigned*)&sVl[n][kk];
                bvl[t][1] = *(const unsigned*)&sVl[n][kk + 8];
            }
#pragma unroll
            for (int t = 0; t < 8; t++) {
                MMA_BF16(O[t], ph[c], bvh[t]);
                MMA_BF16(O[t], ph[c], bvl[t]);
                MMA_BF16(O[t], pl[c], bvh[t]);
            }
        }
        __syncthreads();
    }

    // normalize, gate, bf16 split out
    float inv0 = 1.f / l0, inv1 = 1.f / l1;
#pragma unroll
    for (int t = 0; t < 8; t++) {
        int col = h * 64 + 8 * t + 2 * tg;
        size_t o0 = (size_t)qrow * 1024 + col;
        size_t o1 = o0 + 8 * 1024;
        float2 gg0 = *(const float2*)(g_g + o0);
        float2 gg1 = *(const float2*)(g_g + o1);
        float v0 = O[t][0] * inv0 * gg0.x;
        float v1 = O[t][1] * inv0 * gg0.y;
        float v2 = O[t][2] * inv1 * gg1.x;
        float v3 = O[t][3] * inv1 * gg1.y;
        *(unsigned*)(g_ohi + o0) = pk2(v0, v1);
        *(unsigned*)(g_ohi + o1) = pk2(v2, v3);
        *(unsigned*)(g_olo + o0) = pk2(lores(v0), lores(v1));
        *(unsigned*)(g_olo + o1) = pk2(lores(v2), lores(v3));
    }
}

// ---------------------------------------------------------------------------
extern "C" void kernel_launch(void* const* d_in, const int* in_sizes, int n_in,
                              void* d_out, int out_size)
{
    const float* single = (const float*)d_in[0];
    const float* pw     = (const float*)d_in[1];
    const float* gamma  = (const float*)d_in[2];
    const float* beta   = (const float*)d_in[3];
    const float* Wb     = (const float*)d_in[4];
    const float* Wq     = (const float*)d_in[5];
    const float* Wk     = (const float*)d_in[6];
    const float* Wv     = (const float*)d_in[7];
    const float* Wg     = (const float*)d_in[8];
    const float* bg     = (const float*)d_in[9];
    const float* Wo     = (const float*)d_in[10];
    float* out = (float*)d_out;

    bias_setup<<<1, 128>>>(gamma, beta, Wb);
    dim3 bgrid(16, 1024);
    bias_kernel<<<bgrid, 128>>>(pw);

    conv_plain<<<1024, 256>>>(single);
    dim3 tgrid(32, 32), tblk(32, 8);
    convT<<<tgrid, tblk>>>(Wq, 0);
    convT<<<tgrid, tblk>>>(Wk, 1);
    convT<<<tgrid, tblk>>>(Wv, 2);
    convT<<<tgrid, tblk>>>(Wg, 3);
    convT<<<tgrid, tblk>>>(Wo, 4);

    dim3 ggrid(16, 8);
    gemm_mma<<<ggrid, 256>>>(0, 0, nullptr, nullptr, 4, 0, 0.125f); // Q
    gemm_mma<<<ggrid, 256>>>(0, 1, nullptr, nullptr, 4, 1, 1.0f);   // K
    gemm_mma<<<ggrid, 256>>>(0, 2, nullptr, nullptr, 4, 2, 1.0f);   // V
    dim3 vgrid(16, 16), vblk(32, 8);
    vtrans<<<vgrid, vblk>>>();
    gemm_mma<<<ggrid, 256>>>(0, 3, nullptr, bg, 3, 0, 1.0f);        // gates

    dim3 agrid(8, 16);
    attn_kernel<<<agrid, 256>>>();

    gemm_mma<<<ggrid, 256>>>(1, 4, out, nullptr, 0, 0, 1.0f);       // out proj
}

// round 5
// speedup vs baseline: 2.0876x; 1.0290x over previous
#include <cuda_runtime.h>
#include <cuda_bf16.h>

#define NN (1024u*1024u)

// scratch (device globals: allocation-free)
__device__ float g_bias[16u*1024u*1024u]; // [h][i][j]
__device__ float g_g [NN];                // gates fp32 [token][dim_inner]
__device__ __nv_bfloat16 g_shi[NN], g_slo[NN];        // single_repr hi/lo
__device__ __nv_bfloat16 g_wth[5][NN], g_wtl[5][NN];  // W^T [n][k] hi/lo
__device__ __nv_bfloat16 g_ohi[NN], g_olo[NN];        // gated attn out hi/lo
__device__ __nv_bfloat16 g_qh[NN], g_ql[NN];          // Q [tok][d_inner] *0.125
__device__ __nv_bfloat16 g_kh[NN], g_kl[NN];          // K [tok][d_inner]
__device__ __nv_bfloat16 g_vh[NN], g_vl[NN];          // V [tok][d_inner]
__device__ __nv_bfloat16 g_wbth[16*128], g_wbtl[16*128]; // (gamma*Wb)^T [h][p]
__device__ float g_binit[16];                            // beta @ Wb

__device__ __forceinline__ unsigned pk2(float a, float b) {
    __nv_bfloat162 t = __floats2bfloat162_rn(a, b);
    return *reinterpret_cast<unsigned*>(&t);
}
__device__ __forceinline__ float lores(float a) {
    return a - __bfloat162float(__float2bfloat16(a));
}
__device__ __forceinline__ unsigned cvta_s(const void* p) {
    return (unsigned)__cvta_generic_to_shared(p);
}

#define MMA_BF16(c, a, b) asm volatile( \
    "mma.sync.aligned.m16n8k16.row.col.f32.bf16.bf16.f32 " \
    "{%0,%1,%2,%3},{%4,%5,%6,%7},{%8,%9},{%0,%1,%2,%3};" \
    : "+f"((c)[0]), "+f"((c)[1]), "+f"((c)[2]), "+f"((c)[3]) \
    : "r"((a)[0]), "r"((a)[1]), "r"((a)[2]), "r"((a)[3]), \
      "r"((b)[0]), "r"((b)[1]))
#define MMA_BF16v(c, a, b0, b1) asm volatile( \
    "mma.sync.aligned.m16n8k16.row.col.f32.bf16.bf16.f32 " \
    "{%0,%1,%2,%3},{%4,%5,%6,%7},{%8,%9},{%0,%1,%2,%3};" \
    : "+f"((c)[0]), "+f"((c)[1]), "+f"((c)[2]), "+f"((c)[3]) \
    : "r"((a)[0]), "r"((a)[1]), "r"((a)[2]), "r"((a)[3]), \
      "r"(b0), "r"(b1))
#define LDSM4(R, addr) asm volatile( \
    "ldmatrix.sync.aligned.m8n8.x4.shared.b16 {%0,%1,%2,%3}, [%4];" \
    : "=r"((R)[0]), "=r"((R)[1]), "=r"((R)[2]), "=r"((R)[3]) : "r"(addr))
#define LDSM4T(R, addr) asm volatile( \
    "ldmatrix.sync.aligned.m8n8.x4.trans.shared.b16 {%0,%1,%2,%3}, [%4];" \
    : "=r"((R)[0]), "=r"((R)[1]), "=r"((R)[2]), "=r"((R)[3]) : "r"(addr))

// ---------------------------------------------------------------------------
// One-time prep: (gamma*W_bias)^T as bf16 hi/lo, and beta@W_bias.
// ---------------------------------------------------------------------------
__global__ void bias_setup(const float* __restrict__ gamma,
                           const float* __restrict__ beta,
                           const float* __restrict__ Wb)
{
    int tid = threadIdx.x;
    for (int idx = tid; idx < 2048; idx += 128) {
        int p = idx >> 4, h = idx & 15;
        float w = gamma[p] * Wb[idx];
        __nv_bfloat16 hi = __float2bfloat16(w);
        g_wbth[h * 128 + p] = hi;
        g_wbtl[h * 128 + p] = __float2bfloat16(w - __bfloat162float(hi));
    }
    if (tid < 16) {
        float s = 0.f;
        for (int p = 0; p < 128; p++) s += beta[p] * Wb[p * 16 + tid];
        g_binit[tid] = s;
    }
}

// ---------------------------------------------------------------------------
// Bias kernel: LN (SIMT fp32 stats) + 128->16 projection on tensor cores.
// ---------------------------------------------------------------------------
__global__ __launch_bounds__(128) void bias_kernel(const float* __restrict__ pw)
{
    __shared__ __nv_bfloat16 sXh[64][136], sXl[64][136];
    __shared__ __nv_bfloat16 sWh[16][136], sWl[16][136];
    __shared__ float stage[16][64];
    __shared__ float sbin[16];

    int tid  = threadIdx.x;
    int lane = tid & 31, warp = tid >> 5;
    int gid  = lane >> 2, tg = lane & 3;
    int i  = blockIdx.y;
    int j0 = blockIdx.x * 64;

    for (int idx = tid; idx < 2048; idx += 128) {
        int h = idx >> 7, p = idx & 127;
        sWh[h][p] = g_wbth[idx];
        sWl[h][p] = g_wbtl[idx];
    }
    if (tid < 16) sbin[tid] = g_binit[tid];

    {
        const float4* rowp = (const float4*)(pw
            + ((size_t)i * 1024 + j0 + warp * 16) * 128) + lane;
        float4 x = rowp[0];
#pragma unroll 1
        for (int rr = 0; rr < 16; rr++) {
            float4 xn;
            if (rr < 15) xn = rowp[(rr + 1) * 32];
            float s  = x.x + x.y + x.z + x.w;
            float ss = x.x*x.x + x.y*x.y + x.z*x.z + x.w*x.w;
#pragma unroll
            for (int off = 16; off >= 1; off >>= 1) {
                s  += __shfl_xor_sync(0xffffffffu, s,  off);
                ss += __shfl_xor_sync(0xffffffffu, ss, off);
            }
            float mu  = s * 0.0078125f;
            float var = ss * 0.0078125f - mu * mu;
            float rs  = rsqrtf(var + 1e-5f);
            float y0 = (x.x - mu) * rs, y1 = (x.y - mu) * rs;
            float y2 = (x.z - mu) * rs, y3 = (x.w - mu) * rs;
            int r = warp * 16 + rr;
            *(uint2*)&sXh[r][lane * 4] = make_uint2(pk2(y0, y1), pk2(y2, y3));
            *(uint2*)&sXl[r][lane * 4] =
                make_uint2(pk2(lores(y0), lores(y1)), pk2(lores(y2), lores(y3)));
            x = xn;
        }
    }
    __syncthreads();

    float acc[2][4] = {};
    int warp_m = warp * 16;
    unsigned aXh = cvta_s(sXh), aXl = cvta_s(sXl);
    unsigned aWh = cvta_s(sWh), aWl = cvta_s(sWl);
    int fr = lane & 15, fc = lane >> 4;   // ldmatrix lane mapping
#pragma unroll
    for (int c = 0; c < 8; c++) {
        int kk = c * 16;
        unsigned ah[4], al[4], bh[4], bl[4];
        LDSM4(ah, aXh + ((warp_m + fr) * 136 + kk + fc * 8) * 2);
        LDSM4(al, aXl + ((warp_m + fr) * 136 + kk + fc * 8) * 2);
        LDSM4(bh, aWh + ((fr) * 136 + kk + fc * 8) * 2);
        LDSM4(bl, aWl + ((fr) * 136 + kk + fc * 8) * 2);
#pragma unroll
        for (int t = 0; t < 2; t++) {
            MMA_BF16v(acc[t], ah, bh[t], bh[t + 2]);
            MMA_BF16v(acc[t], ah, bl[t], bl[t + 2]);
            MMA_BF16v(acc[t], al, bh[t], bh[t + 2]);
        }
    }
#pragma unroll
    for (int t = 0; t < 2; t++) {
        int hc = t * 8 + tg * 2;
        int r  = warp_m + gid;
        stage[hc][r]         = acc[t][0];
        stage[hc + 1][r]     = acc[t][1];
        stage[hc][r + 8]     = acc[t][2];
        stage[hc + 1][r + 8] = acc[t][3];
    }
    __syncthreads();
    size_t obase = (size_t)i * 1024 + j0;
    for (int e = tid; e < 1024; e += 128) {
        int hh = e >> 6, j = e & 63;
        g_bias[(size_t)hh * NN + obase + j] = stage[hh][j] + sbin[hh];
    }
}

// ---------------------------------------------------------------------------
// Convert single_repr -> bf16 hi/lo, row-major.
// ---------------------------------------------------------------------------
__global__ __launch_bounds__(256) void conv_plain(const float* __restrict__ src)
{
    unsigned i = blockIdx.x * 256u + threadIdx.x;
    float4 v = ((const float4*)src)[i];
    *(unsigned*)(g_shi + 4u*i)     = pk2(v.x, v.y);
    *(unsigned*)(g_shi + 4u*i + 2) = pk2(v.z, v.w);
    *(unsigned*)(g_slo + 4u*i)     = pk2(lores(v.x), lores(v.y));
    *(unsigned*)(g_slo + 4u*i + 2) = pk2(lores(v.z), lores(v.w));
}

// ---------------------------------------------------------------------------
// Convert + transpose weights (all 5 in one launch, blockIdx.z = widx).
// ---------------------------------------------------------------------------
__global__ __launch_bounds__(256) void convT(
    const float* __restrict__ W0, const float* __restrict__ W1,
    const float* __restrict__ W2, const float* __restrict__ W3,
    const float* __restrict__ W4)
{
    const float* Ws[5] = {W0, W1, W2, W3, W4};
    const float* W = Ws[blockIdx.z];
    __shared__ float ts[32][33];
    int tx = threadIdx.x, ty = threadIdx.y;
    int nx = blockIdx.x * 32 + tx;
#pragma unroll
    for (int i = 0; i < 4; i++)
        ts[ty + i*8][tx] = W[(size_t)(blockIdx.y*32 + ty + i*8) * 1024 + nx];
    __syncthreads();
    __nv_bfloat16* Th = g_wth[blockIdx.z];
    __nv_bfloat16* Tl = g_wtl[blockIdx.z];
#pragma unroll
    for (int i = 0; i < 4; i++) {
        int r = ty + i*8;
        float v = ts[tx][r];
        size_t o = (size_t)(blockIdx.x*32 + r) * 1024 + blockIdx.y*32 + tx;
        __nv_bfloat16 h = __float2bfloat16(v);
        Th[o] = h;
        Tl[o] = __float2bfloat16(v - __bfloat162float(h));
    }
}

// ---------------------------------------------------------------------------
// Tensor-core GEMM via bf16 split (3 passes), ldmatrix fragment loads.
// fused=1: blockIdx.z picks {Q,K,V,gates}. fused=0: A=g_o, fp32 out -> Cext.
// ---------------------------------------------------------------------------
__global__ __launch_bounds__(256) void gemm_mma(
    int fused, float* __restrict__ Cext, const float* __restrict__ aux)
{
    int widx, mode;     // mode: 4=bf16 split out, 3=sigmoid->g_g, 0=fp32->Cext
    float scale = 1.f;
    if (fused) {
        widx = blockIdx.z;
        mode = (widx == 3) ? 3 : 4;
        if (widx == 0) scale = 0.125f;
    } else { widx = 4; mode = 0; }

    const __nv_bfloat16* Ah = fused ? g_shi : g_ohi;
    const __nv_bfloat16* Al = fused ? g_slo : g_olo;
    const __nv_bfloat16* Bh = g_wth[widx];
    const __nv_bfloat16* Bl = g_wtl[widx];

    __shared__ __nv_bfloat16 sAh[128][40], sAl[128][40];
    __shared__ __nv_bfloat16 sBh[64][40],  sBl[64][40];

    int tid  = threadIdx.x;
    int lane = tid & 31, warp = tid >> 5;
    int gid  = lane >> 2, tg = lane & 3;
    int warp_m = (warp >> 1) * 32, warp_n = (warp & 1) * 32;
    int row0 = blockIdx.y * 128, col0 = blockIdx.x * 64;

    int arow = tid >> 2;
    int aseg = (tid & 3) * 8;
    int fr = lane & 15, fc8 = (lane >> 4) * 8;  // ldmatrix lane mapping

    float acc[2][4][4];
#pragma unroll
    for (int mt = 0; mt < 2; mt++)
#pragma unroll
        for (int nt = 0; nt < 4; nt++)
#pragma unroll
            for (int q = 0; q < 4; q++) acc[mt][nt][q] = 0.f;

    unsigned bAh = cvta_s(sAh), bAl = cvta_s(sAl);
    unsigned bBh = cvta_s(sBh), bBl = cvta_s(sBl);

    uint4 pAh0, pAh1, pAl0, pAl1, pBh, pBl;
    pAh0 = *(const uint4*)(Ah + (size_t)(row0 + arow)      * 1024 + aseg);
    pAh1 = *(const uint4*)(Ah + (size_t)(row0 + arow + 64) * 1024 + aseg);
    pAl0 = *(const uint4*)(Al + (size_t)(row0 + arow)      * 1024 + aseg);
    pAl1 = *(const uint4*)(Al + (size_t)(row0 + arow + 64) * 1024 + aseg);
    pBh  = *(const uint4*)(Bh + (size_t)(col0 + arow)      * 1024 + aseg);
    pBl  = *(const uint4*)(Bl + (size_t)(col0 + arow)      * 1024 + aseg);

#pragma unroll 1
    for (int kt = 0; kt < 32; kt++) {
        __syncthreads();
        *(uint4*)&sAh[arow][aseg]      = pAh0;
        *(uint4*)&sAh[arow + 64][aseg] = pAh1;
        *(uint4*)&sAl[arow][aseg]      = pAl0;
        *(uint4*)&sAl[arow + 64][aseg] = pAl1;
        *(uint4*)&sBh[arow][aseg]      = pBh;
        *(uint4*)&sBl[arow][aseg]      = pBl;
        __syncthreads();
        if (kt < 31) {
            int k0 = (kt + 1) * 32;
            pAh0 = *(const uint4*)(Ah + (size_t)(row0 + arow)      * 1024 + k0 + aseg);
            pAh1 = *(const uint4*)(Ah + (size_t)(row0 + arow + 64) * 1024 + k0 + aseg);
            pAl0 = *(const uint4*)(Al + (size_t)(row0 + arow)      * 1024 + k0 + aseg);
            pAl1 = *(const uint4*)(Al + (size_t)(row0 + arow + 64) * 1024 + k0 + aseg);
            pBh  = *(const uint4*)(Bh + (size_t)(col0 + arow)      * 1024 + k0 + aseg);
            pBl  = *(const uint4*)(Bl + (size_t)(col0 + arow)      * 1024 + k0 + aseg);
        }

#pragma unroll
        for (int k16 = 0; k16 < 32; k16 += 16) {
            unsigned a_h[2][4], a_l[2][4], b_h[2][4], b_l[2][4];
#pragma unroll
            for (int mt = 0; mt < 2; mt++) {
                unsigned off = ((warp_m + mt * 16 + fr) * 40 + k16 + fc8) * 2;
                LDSM4(a_h[mt], bAh + off);
                LDSM4(a_l[mt], bAl + off);
            }
#pragma unroll
            for (int tp = 0; tp < 2; tp++) {
                unsigned off = ((warp_n + tp * 16 + fr) * 40 + k16 + fc8) * 2;
                LDSM4(b_h[tp], bBh + off);
                LDSM4(b_l[tp], bBl + off);
            }
#pragma unroll
            for (int mt = 0; mt < 2; mt++)
#pragma unroll
                for (int tp = 0; tp < 2; tp++)
#pragma unroll
                    for (int u = 0; u < 2; u++) {
                        float* c4 = acc[mt][tp * 2 + u];
                        MMA_BF16v(c4, a_h[mt], b_h[tp][u], b_h[tp][u + 2]);
                        MMA_BF16v(c4, a_h[mt], b_l[tp][u], b_l[tp][u + 2]);
                        MMA_BF16v(c4, a_l[mt], b_h[tp][u], b_h[tp][u + 2]);
                    }
        }
    }

    __nv_bfloat16* Dh = (widx == 0) ? g_qh : (widx == 1) ? g_kh : g_vh;
    __nv_bfloat16* Dl = (widx == 0) ? g_ql : (widx == 1) ? g_kl : g_vl;
#pragma unroll
    for (int mt = 0; mt < 2; mt++) {
#pragma unroll
        for (int nt = 0; nt < 4; nt++) {
            int rg = row0 + warp_m + mt * 16 + gid;
            int cg = col0 + warp_n + nt * 8 + tg * 2;
            float* a4 = acc[mt][nt];
            if (mode == 0) {
                *(float2*)&Cext[(size_t)rg * 1024 + cg]       = make_float2(a4[0], a4[1]);
                *(float2*)&Cext[(size_t)(rg + 8) * 1024 + cg] = make_float2(a4[2], a4[3]);
            } else if (mode == 3) {
                float b0 = aux[cg], b1 = aux[cg + 1];
                float v0 = 1.f / (1.f + __expf(-(a4[0] + b0)));
                float v1 = 1.f / (1.f + __expf(-(a4[1] + b1)));
                float v2 = 1.f / (1.f + __expf(-(a4[2] + b0)));
                float v3 = 1.f / (1.f + __expf(-(a4[3] + b1)));
                *(float2*)&g_g[(size_t)rg * 1024 + cg]       = make_float2(v0, v1);
                *(float2*)&g_g[(size_t)(rg + 8) * 1024 + cg] = make_float2(v2, v3);
            } else {
                float v0 = a4[0] * scale, v1 = a4[1] * scale;
                float v2 = a4[2] * scale, v3 = a4[3] * scale;
                *(unsigned*)&Dh[(size_t)rg * 1024 + cg]       = pk2(v0, v1);
                *(unsigned*)&Dh[(size_t)(rg + 8) * 1024 + cg] = pk2(v2, v3);
                *(unsigned*)&Dl[(size_t)rg * 1024 + cg]       = pk2(lores(v0), lores(v1));
                *(unsigned*)&Dl[(size_t)(rg + 8) * 1024 + cg] = pk2(lores(v2), lores(v3));
            }
        }
    }
}

// ---------------------------------------------------------------------------
// Flash attention on tensor cores, ldmatrix fragments, V via ldmatrix.trans.
// 256 thr = 8 warps x m16 -> 128 queries/CTA. Grid (8, 16).
// ---------------------------------------------------------------------------
__global__ __launch_bounds__(256) void attn_kernel()
{
    __shared__ __nv_bfloat16 sKh[64][72], sKl[64][72];
    __shared__ __nv_bfloat16 sVh[64][72], sVl[64][72];  // [tok][d]

    int tid  = threadIdx.x;
    int lane = tid & 31, warp = tid >> 5;
    int gid  = lane >> 2, tg = lane & 3;
    int h  = blockIdx.y;
    int q0 = blockIdx.x * 128;
    int warp_m = warp * 16;
    int qrow = q0 + warp_m + gid;

    // ldmatrix lane mappings
    int fr = lane & 15, fc8 = (lane >> 4) * 8;               // non-trans
    int vr = (lane >> 4) * 8 + (lane & 7);                   // trans: source row
    int vc8 = ((lane >> 3) & 1) * 8;                         // trans: source col

    unsigned qh[4][4], ql[4][4];
    {
        const __nv_bfloat16* Qh = g_qh + (size_t)qrow * 1024 + h * 64;
        const __nv_bfloat16* Ql = g_ql + (size_t)qrow * 1024 + h * 64;
#pragma unroll
        for (int c = 0; c < 4; c++) {
            int kk = c * 16 + tg * 2;
            qh[c][0] = *(const unsigned*)(Qh + kk);
            qh[c][1] = *(const unsigned*)(Qh + 8 * 1024 + kk);
            qh[c][2] = *(const unsigned*)(Qh + kk + 8);
            qh[c][3] = *(const unsigned*)(Qh + 8 * 1024 + kk + 8);
            ql[c][0] = *(const unsigned*)(Ql + kk);
            ql[c][1] = *(const unsigned*)(Ql + 8 * 1024 + kk);
            ql[c][2] = *(const unsigned*)(Ql + kk + 8);
            ql[c][3] = *(const unsigned*)(Ql + 8 * 1024 + kk + 8);
        }
    }

    float m0 = -1e30f, m1 = -1e30f, l0 = 0.f, l1 = 0.f;
    float O[8][4] = {};

    int lr = tid >> 2;
    int cs = (tid & 3) * 16;
    unsigned bKh = cvta_s(sKh), bKl = cvta_s(sKl);
    unsigned bVh = cvta_s(sVh), bVl = cvta_s(sVl);

#pragma unroll 1
    for (int kb = 0; kb < 16; kb++) {
        int k0 = kb * 64;
        {
            const __nv_bfloat16* kh = g_kh + (size_t)(k0 + lr) * 1024 + h * 64 + cs;
            const __nv_bfloat16* kl = g_kl + (size_t)(k0 + lr) * 1024 + h * 64 + cs;
            const __nv_bfloat16* vh = g_vh + (size_t)(k0 + lr) * 1024 + h * 64 + cs;
            const __nv_bfloat16* vl = g_vl + (size_t)(k0 + lr) * 1024 + h * 64 + cs;
            *(uint4*)&sKh[lr][cs]     = *(const uint4*)kh;
            *(uint4*)&sKh[lr][cs + 8] = *((const uint4*)kh + 1);
            *(uint4*)&sKl[lr][cs]     = *(const uint4*)kl;
            *(uint4*)&sKl[lr][cs + 8] = *((const uint4*)kl + 1);
            *(uint4*)&sVh[lr][cs]     = *(const uint4*)vh;
            *(uint4*)&sVh[lr][cs + 8] = *((const uint4*)vh + 1);
            *(uint4*)&sVl[lr][cs]     = *(const uint4*)vl;
            *(uint4*)&sVl[lr][cs + 8] = *((const uint4*)vl + 1);
        }
        __syncthreads();

        // S init from pair bias
        float S[8][4];
        {
            const float* bptr = g_bias + (size_t)h * NN + (size_t)qrow * 1024 + k0;
#pragma unroll
            for (int t = 0; t < 8; t++) {
                float2 b0 = *(const float2*)(bptr + 8 * t + 2 * tg);
                float2 b1 = *(const float2*)(bptr + 8 * 1024 + 8 * t + 2 * tg);
                S[t][0] = b0.x; S[t][1] = b0.y; S[t][2] = b1.x; S[t][3] = b1.y;
            }
        }
        // S += Q K^T: K rows are tokens (n), cols d (k) -> plain ldmatrix
#pragma unroll
        for (int c = 0; c < 4; c++) {
            int kk = c * 16;
#pragma unroll
            for (int tp = 0; tp < 4; tp++) {
                unsigned bh[4], bl[4];
                unsigned off = ((tp * 16 + fr) * 72 + kk + fc8) * 2;
                LDSM4(bh, bKh + off);
                LDSM4(bl, bKl + off);
#pragma unroll
                for (int u = 0; u < 2; u++) {
                    float* c4 = S[tp * 2 + u];
                    MMA_BF16v(c4, qh[c], bh[u], bh[u + 2]);
                    MMA_BF16v(c4, qh[c], bl[u], bl[u + 2]);
                    MMA_BF16v(c4, ql[c], bh[u], bh[u + 2]);
                }
            }
        }

        // online softmax
        float rm0 = -1e30f, rm1 = -1e30f;
#pragma unroll
        for (int t = 0; t < 8; t++) {
            rm0 = fmaxf(rm0, fmaxf(S[t][0], S[t][1]));
            rm1 = fmaxf(rm1, fmaxf(S[t][2], S[t][3]));
        }
        rm0 = fmaxf(rm0, __shfl_xor_sync(0xffffffffu, rm0, 1));
        rm0 = fmaxf(rm0, __shfl_xor_sync(0xffffffffu, rm0, 2));
        rm1 = fmaxf(rm1, __shfl_xor_sync(0xffffffffu, rm1, 1));
        rm1 = fmaxf(rm1, __shfl_xor_sync(0xffffffffu, rm1, 2));
        float mn0 = fmaxf(m0, rm0), mn1 = fmaxf(m1, rm1);
        float c0 = __expf(m0 - mn0), c1 = __expf(m1 - mn1);
        m0 = mn0; m1 = mn1;
        float ps0 = 0.f, ps1 = 0.f;
#pragma unroll
        for (int t = 0; t < 8; t++) {
            S[t][0] = __expf(S[t][0] - mn0);
            S[t][1] = __expf(S[t][1] - mn0);
            S[t][2] = __expf(S[t][2] - mn1);
            S[t][3] = __expf(S[t][3] - mn1);
            ps0 += S[t][0] + S[t][1];
            ps1 += S[t][2] + S[t][3];
        }
        ps0 += __shfl_xor_sync(0xffffffffu, ps0, 1);
        ps0 += __shfl_xor_sync(0xffffffffu, ps0, 2);
        ps1 += __shfl_xor_sync(0xffffffffu, ps1, 1);
        ps1 += __shfl_xor_sync(0xffffffffu, ps1, 2);
        l0 = l0 * c0 + ps0;
        l1 = l1 * c1 + ps1;
#pragma unroll
        for (int t = 0; t < 8; t++) {
            O[t][0] *= c0; O[t][1] *= c0; O[t][2] *= c1; O[t][3] *= c1;
        }

        // P as A-fragments (hi + residual lo)
        unsigned ph[4][4], pl[4][4];
#pragma unroll
        for (int c = 0; c < 4; c++) {
            int t0 = 2 * c, t1 = 2 * c + 1;
            ph[c][0] = pk2(S[t0][0], S[t0][1]);
            ph[c][1] = pk2(S[t0][2], S[t0][3]);
            ph[c][2] = pk2(S[t1][0], S[t1][1]);
            ph[c][3] = pk2(S[t1][2], S[t1][3]);
            pl[c][0] = pk2(lores(S[t0][0]), lores(S[t0][1]));
            pl[c][1] = pk2(lores(S[t0][2]), lores(S[t0][3]));
            pl[c][2] = pk2(lores(S[t1][0]), lores(S[t1][1]));
            pl[c][3] = pk2(lores(S[t1][2]), lores(S[t1][3]));
        }

        // O += P V: V rows tokens (k), cols d (n) -> ldmatrix.trans
#pragma unroll
        for (int c = 0; c < 4; c++) {
#pragma unroll
            for (int tp = 0; tp < 4; tp++) {
                unsigned bh[4], bl[4];
                unsigned off = ((c * 16 + vr) * 72 + tp * 16 + vc8) * 2;
                LDSM4T(bh, bVh + off);
                LDSM4T(bl, bVl + off);
#pragma unroll
                for (int u = 0; u < 2; u++) {
                    float* c4 = O[tp * 2 + u];
                    MMA_BF16v(c4, ph[c], bh[u], bh[u + 2]);
                    MMA_BF16v(c4, ph[c], bl[u], bl[u + 2]);
                    MMA_BF16v(c4, pl[c], bh[u], bh[u + 2]);
                }
            }
        }
        __syncthreads();
    }

    float inv0 = 1.f / l0, inv1 = 1.f / l1;
#pragma unroll
    for (int t = 0; t < 8; t++) {
        int col = h * 64 + 8 * t + 2 * tg;
        size_t o0 = (size_t)qrow * 1024 + col;
        size_t o1 = o0 + 8 * 1024;
        float2 gg0 = *(const float2*)(g_g + o0);
        float2 gg1 = *(const float2*)(g_g + o1);
        float v0 = O[t][0] * inv0 * gg0.x;
        float v1 = O[t][1] * inv0 * gg0.y;
        float v2 = O[t][2] * inv1 * gg1.x;
        float v3 = O[t][3] * inv1 * gg1.y;
        *(unsigned*)(g_ohi + o0) = pk2(v0, v1);
        *(unsigned*)(g_ohi + o1) = pk2(v2, v3);
        *(unsigned*)(g_olo + o0) = pk2(lores(v0), lores(v1));
        *(unsigned*)(g_olo + o1) = pk2(lores(v2), lores(v3));
    }
}

// ---------------------------------------------------------------------------
extern "C" void kernel_launch(void* const* d_in, const int* in_sizes, int n_in,
                              void* d_out, int out_size)
{
    const float* single = (const float*)d_in[0];
    const float* pw     = (const float*)d_in[1];
    const float* gamma  = (const float*)d_in[2];
    const float* beta   = (const float*)d_in[3];
    const float* Wb     = (const float*)d_in[4];
    const float* Wq     = (const float*)d_in[5];
    const float* Wk     = (const float*)d_in[6];
    const float* Wv     = (const float*)d_in[7];
    const float* Wg     = (const float*)d_in[8];
    const float* bg     = (const float*)d_in[9];
    const float* Wo     = (const float*)d_in[10];
    float* out = (float*)d_out;

    bias_setup<<<1, 128>>>(gamma, beta, Wb);
    dim3 bgrid(16, 1024);
    bias_kernel<<<bgrid, 128>>>(pw);

    conv_plain<<<1024, 256>>>(single);
    dim3 tgrid(32, 32, 5), tblk(32, 8);
    convT<<<tgrid, tblk>>>(Wq, Wk, Wv, Wg, Wo);

    dim3 ggrid(16, 8, 4);
    gemm_mma<<<ggrid, 256>>>(1, nullptr, bg);      // Q,K,V,gates fused

    dim3 agrid(8, 16);
    attn_kernel<<<agrid, 256>>>();

    dim3 ogrid(16, 8, 1);
    gemm_mma<<<ogrid, 256>>>(0, out, nullptr);     // output projection
}

// round 7
// speedup vs baseline: 2.5749x; 1.2334x over previous
#include <cuda_runtime.h>
#include <cuda_bf16.h>
#include <cstdint>

#define NN (1024u*1024u)

// scratch (device globals: allocation-free)
__device__ float g_bias[16u*1024u*1024u]; // [h][i][j]
__device__ float g_g [NN];                // gates fp32 [token][dim_inner]
__device__ __nv_bfloat16 g_shi[NN], g_slo[NN];        // single_repr hi/lo
__device__ __nv_bfloat16 g_wth[5][NN], g_wtl[5][NN];  // W^T [n][k] hi/lo
__device__ __nv_bfloat16 g_ohi[NN], g_olo[NN];        // gated attn out hi/lo
__device__ __nv_bfloat16 g_qh[NN], g_ql[NN];          // Q [tok][d_inner] *0.125
__device__ __nv_bfloat16 g_kh[NN], g_kl[NN];          // K [tok][d_inner]
__device__ __nv_bfloat16 g_vh[NN], g_vl[NN];          // V [tok][d_inner]
__device__ __nv_bfloat16 g_wbth[16*128], g_wbtl[16*128]; // (gamma*Wb)^T [h][p]
__device__ float g_binit[16];                            // beta @ Wb

__device__ __forceinline__ unsigned pk2(float a, float b) {
    __nv_bfloat162 t = __floats2bfloat162_rn(a, b);
    return *reinterpret_cast<unsigned*>(&t);
}
__device__ __forceinline__ float lores(float a) {
    return a - __bfloat162float(__float2bfloat16(a));
}
__device__ __forceinline__ unsigned cvta_s(const void* p) {
    return (unsigned)__cvta_generic_to_shared(p);
}

#define MMA_BF16v(c, a, b0, b1) asm volatile( \
    "mma.sync.aligned.m16n8k16.row.col.f32.bf16.bf16.f32 " \
    "{%0,%1,%2,%3},{%4,%5,%6,%7},{%8,%9},{%0,%1,%2,%3};" \
    : "+f"((c)[0]), "+f"((c)[1]), "+f"((c)[2]), "+f"((c)[3]) \
    : "r"((a)[0]), "r"((a)[1]), "r"((a)[2]), "r"((a)[3]), \
      "r"(b0), "r"(b1))
#define LDSM4(R, addr) asm volatile( \
    "ldmatrix.sync.aligned.m8n8.x4.shared.b16 {%0,%1,%2,%3}, [%4];" \
    : "=r"((R)[0]), "=r"((R)[1]), "=r"((R)[2]), "=r"((R)[3]) : "r"(addr))
#define LDSM4T(R, addr) asm volatile( \
    "ldmatrix.sync.aligned.m8n8.x4.trans.shared.b16 {%0,%1,%2,%3}, [%4];" \
    : "=r"((R)[0]), "=r"((R)[1]), "=r"((R)[2]), "=r"((R)[3]) : "r"(addr))
#define CP_ASYNC16(dst, src) asm volatile( \
    "cp.async.cg.shared.global [%0], [%1], 16;" :: "r"(dst), "l"(src) : "memory")
#define CP_COMMIT() asm volatile("cp.async.commit_group;" ::: "memory")
#define CP_WAIT1()  asm volatile("cp.async.wait_group 1;" ::: "memory")
#define CP_WAIT0()  asm volatile("cp.async.wait_group 0;" ::: "memory")

// ---------------------------------------------------------------------------
// One-time prep: (gamma*W_bias)^T as bf16 hi/lo, and beta@W_bias.
// ---------------------------------------------------------------------------
__global__ void bias_setup(const float* __restrict__ gamma,
                           const float* __restrict__ beta,
                           const float* __restrict__ Wb)
{
    int tid = threadIdx.x;
    for (int idx = tid; idx < 2048; idx += 128) {
        int p = idx >> 4, h = idx & 15;
        float w = gamma[p] * Wb[idx];
        __nv_bfloat16 hi = __float2bfloat16(w);
        g_wbth[h * 128 + p] = hi;
        g_wbtl[h * 128 + p] = __float2bfloat16(w - __bfloat162float(hi));
    }
    if (tid < 16) {
        float s = 0.f;
        for (int p = 0; p < 128; p++) s += beta[p] * Wb[p * 16 + tid];
        g_binit[tid] = s;
    }
}

// ---------------------------------------------------------------------------
// Bias kernel: LN (SIMT fp32 stats) + 128->16 projection on tensor cores.
// ---------------------------------------------------------------------------
__global__ __launch_bounds__(256) void bias_kernel(const float* __restrict__ pw)
{
    __shared__ __nv_bfloat16 sXh[64][136], sXl[64][136];
    __shared__ __nv_bfloat16 sWh[16][136], sWl[16][136];
    __shared__ float stage[16][64];
    __shared__ float sbin[16];

    int tid  = threadIdx.x;
    int lane = tid & 31, warp = tid >> 5;
    int i  = blockIdx.y;
    int j0 = blockIdx.x * 64;

    for (int idx = tid; idx < 2048; idx += 256) {
        int h = idx >> 7, p = idx & 127;
        sWh[h][p] = g_wbth[idx];
        sWl[h][p] = g_wbtl[idx];
    }
    if (tid < 16) sbin[tid] = g_binit[tid];

    {
        const float4* rowp = (const float4*)(pw
            + ((size_t)i * 1024 + j0 + warp * 8) * 128) + lane;
        float4 x = rowp[0];
#pragma unroll 1
        for (int rr = 0; rr < 8; rr++) {
            float4 xn;
            if (rr < 7) xn = rowp[(rr + 1) * 32];
            float s  = x.x + x.y + x.z + x.w;
            float ss = x.x*x.x + x.y*x.y + x.z*x.z + x.w*x.w;
#pragma unroll
            for (int off = 16; off >= 1; off >>= 1) {
                s  += __shfl_xor_sync(0xffffffffu, s,  off);
                ss += __shfl_xor_sync(0xffffffffu, ss, off);
            }
            float mu  = s * 0.0078125f;
            float var = ss * 0.0078125f - mu * mu;
            float rs  = rsqrtf(var + 1e-5f);
            float y0 = (x.x - mu) * rs, y1 = (x.y - mu) * rs;
            float y2 = (x.z - mu) * rs, y3 = (x.w - mu) * rs;
            int r = warp * 8 + rr;
            *(uint2*)&sXh[r][lane * 4] = make_uint2(pk2(y0, y1), pk2(y2, y3));
            *(uint2*)&sXl[r][lane * 4] =
                make_uint2(pk2(lores(y0), lores(y1)), pk2(lores(y2), lores(y3)));
            x = xn;
        }
    }
    __syncthreads();

    if (warp < 4) {
        int gid  = lane >> 2, tg = lane & 3;
        float acc[2][4] = {};
        int warp_m = warp * 16;
        unsigned aXh = cvta_s(sXh), aXl = cvta_s(sXl);
        unsigned aWh = cvta_s(sWh), aWl = cvta_s(sWl);
        int fr = lane & 15, fc = lane >> 4;
#pragma unroll
        for (int c = 0; c < 8; c++) {
            int kk = c * 16;
            unsigned ah[4], al[4], bh[4], bl[4];
            LDSM4(ah, aXh + ((warp_m + fr) * 136 + kk + fc * 8) * 2);
            LDSM4(al, aXl + ((warp_m + fr) * 136 + kk + fc * 8) * 2);
            LDSM4(bh, aWh + ((fr) * 136 + kk + fc * 8) * 2);
            LDSM4(bl, aWl + ((fr) * 136 + kk + fc * 8) * 2);
#pragma unroll
            for (int t = 0; t < 2; t++) {
                MMA_BF16v(acc[t], ah, bh[t], bh[t + 2]);
                MMA_BF16v(acc[t], ah, bl[t], bl[t + 2]);
                MMA_BF16v(acc[t], al, bh[t], bh[t + 2]);
            }
        }
#pragma unroll
        for (int t = 0; t < 2; t++) {
            int hc = t * 8 + tg * 2;
            int r  = warp_m + gid;
            stage[hc][r]         = acc[t][0];
            stage[hc + 1][r]     = acc[t][1];
            stage[hc][r + 8]     = acc[t][2];
            stage[hc + 1][r + 8] = acc[t][3];
        }
    }
    __syncthreads();
    size_t obase = (size_t)i * 1024 + j0;
    for (int e = tid; e < 1024; e += 256) {
        int hh = e >> 6, j = e & 63;
        g_bias[(size_t)hh * NN + obase + j] = stage[hh][j] + sbin[hh];
    }
}

// ---------------------------------------------------------------------------
// Convert single_repr -> bf16 hi/lo, row-major.
// ---------------------------------------------------------------------------
__global__ __launch_bounds__(256) void conv_plain(const float* __restrict__ src)
{
    unsigned i = blockIdx.x * 256u + threadIdx.x;
    float4 v = ((const float4*)src)[i];
    *(unsigned*)(g_shi + 4u*i)     = pk2(v.x, v.y);
    *(unsigned*)(g_shi + 4u*i + 2) = pk2(v.z, v.w);
    *(unsigned*)(g_slo + 4u*i)     = pk2(lores(v.x), lores(v.y));
    *(unsigned*)(g_slo + 4u*i + 2) = pk2(lores(v.z), lores(v.w));
}

// ---------------------------------------------------------------------------
// Convert + transpose weights (all 5 in one launch, blockIdx.z = widx).
// ---------------------------------------------------------------------------
__global__ __launch_bounds__(256) void convT(
    const float* __restrict__ W0, const float* __restrict__ W1,
    const float* __restrict__ W2, const float* __restrict__ W3,
    const float* __restrict__ W4)
{
    const float* Ws[5] = {W0, W1, W2, W3, W4};
    const float* W = Ws[blockIdx.z];
    __shared__ float ts[32][33];
    int tx = threadIdx.x, ty = threadIdx.y;
    int nx = blockIdx.x * 32 + tx;
#pragma unroll
    for (int i = 0; i < 4; i++)
        ts[ty + i*8][tx] = W[(size_t)(blockIdx.y*32 + ty + i*8) * 1024 + nx];
    __syncthreads();
    __nv_bfloat16* Th = g_wth[blockIdx.z];
    __nv_bfloat16* Tl = g_wtl[blockIdx.z];
#pragma unroll
    for (int i = 0; i < 4; i++) {
        int r = ty + i*8;
        float v = ts[tx][r];
        size_t o = (size_t)(blockIdx.x*32 + r) * 1024 + blockIdx.y*32 + tx;
        __nv_bfloat16 h = __float2bfloat16(v);
        Th[o] = h;
        Tl[o] = __float2bfloat16(v - __bfloat162float(h));
    }
}

// ---------------------------------------------------------------------------
// Tensor-core GEMM, 128x128 block tile, BK=32, cp.async depth-2 pipeline.
// A hi/lo row-major; B hi/lo transposed [n][k]. 3-pass bf16 split, fp32 acc.
// fused=1: blockIdx.z in {Q,K,V,gates}; fused=0: A=attn out, fp32 -> Cext.
// Dynamic smem: 2 buffers x (Ah|Al|Bh|Bl each 128x40 bf16) = 81920 B.
// ---------------------------------------------------------------------------
__global__ __launch_bounds__(256) void gemm_mma(
    int fused, float* __restrict__ Cext, const float* __restrict__ aux)
{
    extern __shared__ __nv_bfloat16 dsm[];
    int widx = fused ? blockIdx.z : 4;
    int mode = fused ? ((widx == 3) ? 3 : 4) : 0;
    float scale = (widx == 0) ? 0.125f : 1.0f;

    const __nv_bfloat16* gAh = fused ? g_shi : g_ohi;
    const __nv_bfloat16* gAl = fused ? g_slo : g_olo;
    const __nv_bfloat16* gBh = g_wth[widx];
    const __nv_bfloat16* gBl = g_wtl[widx];

    int tid  = threadIdx.x;
    int lane = tid & 31, warp = tid >> 5;
    int gid  = lane >> 2, tg = lane & 3;
    int fr = lane & 15, fc8 = (lane >> 4) * 8;
    int warp_m = (warp >> 1) * 32, warp_n = (warp & 1) * 64;
    int m0 = blockIdx.y * 128, n0 = blockIdx.x * 128;
    unsigned sb = cvta_s(dsm);

    // per-thread load slice: 8 x 16B cp.async per chunk
    int mat = (tid * 8) >> 9;            // wrong if crossing; compute per-t below

    auto issue = [&](int ch, int buf) {
        int k0 = ch * 32;
        unsigned bo = buf * 81920u;      // bytes (2 bufs x 40960)… see below
        bo = buf * 40960u;
#pragma unroll
        for (int t = 0; t < 8; t++) {
            int s = tid + t * 256;
            int mt = s >> 9, rem = s & 511;
            int row = rem >> 2, seg = rem & 3;
            unsigned dst = sb + bo + mt * 10240u + row * 80u + seg * 16u;
            const __nv_bfloat16* src;
            if      (mt == 0) src = gAh + (size_t)(m0 + row) * 1024 + k0 + seg * 8;
            else if (mt == 1) src = gAl + (size_t)(m0 + row) * 1024 + k0 + seg * 8;
            else if (mt == 2) src = gBh + (size_t)(n0 + row) * 1024 + k0 + seg * 8;
            else              src = gBl + (size_t)(n0 + row) * 1024 + k0 + seg * 8;
            CP_ASYNC16(dst, src);
        }
        CP_COMMIT();
    };
    (void)mat;

    float acc[2][8][4];
#pragma unroll
    for (int a = 0; a < 2; a++)
#pragma unroll
        for (int b = 0; b < 8; b++)
#pragma unroll
            for (int q = 0; q < 4; q++) acc[a][b][q] = 0.f;

    issue(0, 0);
    issue(1, 1);

#pragma unroll 1
    for (int ch = 0; ch < 32; ch++) {
        if (ch < 31) { CP_WAIT1(); } else { CP_WAIT0(); }
        __syncthreads();
        unsigned base = sb + (ch & 1) * 40960u;
#pragma unroll
        for (int k16 = 0; k16 < 32; k16 += 16) {
            unsigned a_h[2][4], a_l[2][4], b_h[4][4], b_l[4][4];
#pragma unroll
            for (int mt = 0; mt < 2; mt++) {
                unsigned off = base + ((warp_m + mt * 16 + fr) * 40 + k16 + fc8) * 2;
                LDSM4(a_h[mt], off);
                LDSM4(a_l[mt], off + 10240u);
            }
#pragma unroll
            for (int nt = 0; nt < 4; nt++) {
                unsigned off = base + 20480u
                    + ((warp_n + nt * 16 + fr) * 40 + k16 + fc8) * 2;
                LDSM4(b_h[nt], off);
                LDSM4(b_l[nt], off + 10240u);
            }
#pragma unroll
            for (int mt = 0; mt < 2; mt++)
#pragma unroll
                for (int nt = 0; nt < 4; nt++)
#pragma unroll
                    for (int u = 0; u < 2; u++) {
                        float* c4 = acc[mt][nt * 2 + u];
                        MMA_BF16v(c4, a_h[mt], b_h[nt][u], b_h[nt][u + 2]);
                        MMA_BF16v(c4, a_h[mt], b_l[nt][u], b_l[nt][u + 2]);
                        MMA_BF16v(c4, a_l[mt], b_h[nt][u], b_h[nt][u + 2]);
                    }
        }
        __syncthreads();
        if (ch + 2 < 32) issue(ch + 2, ch & 1);
    }

    __nv_bfloat16* Dh = (widx == 0) ? g_qh : (widx == 1) ? g_kh : g_vh;
    __nv_bfloat16* Dl = (widx == 0) ? g_ql : (widx == 1) ? g_kl : g_vl;
#pragma unroll
    for (int mt = 0; mt < 2; mt++) {
#pragma unroll
        for (int j = 0; j < 8; j++) {
            int rg = m0 + warp_m + mt * 16 + gid;
            int cg = n0 + warp_n + j * 8 + tg * 2;
            float* a4 = acc[mt][j];
            if (mode == 0) {
                *(float2*)&Cext[(size_t)rg * 1024 + cg]       = make_float2(a4[0], a4[1]);
                *(float2*)&Cext[(size_t)(rg + 8) * 1024 + cg] = make_float2(a4[2], a4[3]);
            } else if (mode == 3) {
                float b0 = aux[cg], b1 = aux[cg + 1];
                float v0 = 1.f / (1.f + __expf(-(a4[0] + b0)));
                float v1 = 1.f / (1.f + __expf(-(a4[1] + b1)));
                float v2 = 1.f / (1.f + __expf(-(a4[2] + b0)));
                float v3 = 1.f / (1.f + __expf(-(a4[3] + b1)));
                *(float2*)&g_g[(size_t)rg * 1024 + cg]       = make_float2(v0, v1);
                *(float2*)&g_g[(size_t)(rg + 8) * 1024 + cg] = make_float2(v2, v3);
            } else {
                float v0 = a4[0] * scale, v1 = a4[1] * scale;
                float v2 = a4[2] * scale, v3 = a4[3] * scale;
                *(unsigned*)&Dh[(size_t)rg * 1024 + cg]       = pk2(v0, v1);
                *(unsigned*)&Dh[(size_t)(rg + 8) * 1024 + cg] = pk2(v2, v3);
                *(unsigned*)&Dl[(size_t)rg * 1024 + cg]       = pk2(lores(v0), lores(v1));
                *(unsigned*)&Dl[(size_t)(rg + 8) * 1024 + cg] =
                    pk2(lores(v2), lores(v3));
            }
        }
    }
}

// ---------------------------------------------------------------------------
// Flash attention, mma.sync + ldmatrix, cp.async depth-2 K/V pipeline.
// 256 thr = 8 warps x m16 -> 128 queries/CTA. Grid (8, 16).
// Dynamic smem: 2 buffers x (Kh|Kl|Vh|Vl each 64x72 bf16) = 73728 B.
// ---------------------------------------------------------------------------
__global__ __launch_bounds__(256) void attn_kernel()
{
    extern __shared__ __nv_bfloat16 dsm[];
    int tid  = threadIdx.x;
    int lane = tid & 31, warp = tid >> 5;
    int gid  = lane >> 2, tg = lane & 3;
    int h  = blockIdx.y;
    int q0 = blockIdx.x * 128;
    int warp_m = warp * 16;
    int qrow = q0 + warp_m + gid;
    unsigned sb = cvta_s(dsm);

    int fr = lane & 15, fc8 = (lane >> 4) * 8;
    int vr = (lane >> 4) * 8 + (lane & 7);
    int vc8 = ((lane >> 3) & 1) * 8;

    auto issue_kv = [&](int kb, int buf) {
        int k0 = kb * 64;
        unsigned bo = buf * 36864u;
#pragma unroll
        for (int t = 0; t < 8; t++) {
            int s = tid + t * 256;
            int mt = s >> 9, rem = s & 511;
            int row = rem >> 3, seg = rem & 7;
            unsigned dst = sb + bo + mt * 9216u + row * 144u + seg * 16u;
            const __nv_bfloat16* src;
            if      (mt == 0) src = g_kh + (size_t)(k0 + row) * 1024 + h * 64 + seg * 8;
            else if (mt == 1) src = g_kl + (size_t)(k0 + row) * 1024 + h * 64 + seg * 8;
            else if (mt == 2) src = g_vh + (size_t)(k0 + row) * 1024 + h * 64 + seg * 8;
            else              src = g_vl + (size_t)(k0 + row) * 1024 + h * 64 + seg * 8;
            CP_ASYNC16(dst, src);
        }
        CP_COMMIT();
    };

    unsigned qh[4][4], ql[4][4];
    {
        const __nv_bfloat16* Qh = g_qh + (size_t)qrow * 1024 + h * 64;
        const __nv_bfloat16* Ql = g_ql + (size_t)qrow * 1024 + h * 64;
#pragma unroll
        for (int c = 0; c < 4; c++) {
            int kk = c * 16 + tg * 2;
            qh[c][0] = *(const unsigned*)(Qh + kk);
            qh[c][1] = *(const unsigned*)(Qh + 8 * 1024 + kk);
            qh[c][2] = *(const unsigned*)(Qh + kk + 8);
            qh[c][3] = *(const unsigned*)(Qh + 8 * 1024 + kk + 8);
            ql[c][0] = *(const unsigned*)(Ql + kk);
            ql[c][1] = *(const unsigned*)(Ql + 8 * 1024 + kk);
            ql[c][2] = *(const unsigned*)(Ql + kk + 8);
            ql[c][3] = *(const unsigned*)(Ql + 8 * 1024 + kk + 8);
        }
    }

    float m0 = -1e30f, m1 = -1e30f, l0 = 0.f, l1 = 0.f;
    float O[8][4] = {};

    issue_kv(0, 0);
    issue_kv(1, 1);

#pragma unroll 1
    for (int kb = 0; kb < 16; kb++) {
        if (kb < 15) { CP_WAIT1(); } else { CP_WAIT0(); }
        __syncthreads();
        unsigned base = sb + (kb & 1) * 36864u;
        int k0 = kb * 64;

        float S[8][4];
        {
            const float* bptr = g_bias + (size_t)h * NN + (size_t)qrow * 1024 + k0;
#pragma unroll
            for (int t = 0; t < 8; t++) {
                float2 b0 = *(const float2*)(bptr + 8 * t + 2 * tg);
                float2 b1 = *(const float2*)(bptr + 8 * 1024 + 8 * t + 2 * tg);
                S[t][0] = b0.x; S[t][1] = b0.y; S[t][2] = b1.x; S[t][3] = b1.y;
            }
        }
#pragma unroll
        for (int c = 0; c < 4; c++) {
            int kk = c * 16;
#pragma unroll
            for (int tp = 0; tp < 4; tp++) {
                unsigned bh[4], bl[4];
                unsigned off = base + ((tp * 16 + fr) * 72 + kk + fc8) * 2;
                LDSM4(bh, off);
                LDSM4(bl, off + 9216u);
#pragma unroll
                for (int u = 0; u < 2; u++) {
                    float* c4 = S[tp * 2 + u];
                    MMA_BF16v(c4, qh[c], bh[u], bh[u + 2]);
                    MMA_BF16v(c4, qh[c], bl[u], bl[u + 2]);
                    MMA_BF16v(c4, ql[c], bh[u], bh[u + 2]);
                }
            }
        }

        float rm0 = -1e30f, rm1 = -1e30f;
#pragma unroll
        for (int t = 0; t < 8; t++) {
            rm0 = fmaxf(rm0, fmaxf(S[t][0], S[t][1]));
            rm1 = fmaxf(rm1, fmaxf(S[t][2], S[t][3]));
        }
        rm0 = fmaxf(rm0, __shfl_xor_sync(0xffffffffu, rm0, 1));
        rm0 = fmaxf(rm0, __shfl_xor_sync(0xffffffffu, rm0, 2));
        rm1 = fmaxf(rm1, __shfl_xor_sync(0xffffffffu, rm1, 1));
        rm1 = fmaxf(rm1, __shfl_xor_sync(0xffffffffu, rm1, 2));
        float mn0 = fmaxf(m0, rm0), mn1 = fmaxf(m1, rm1);
        float c0 = __expf(m0 - mn0), c1 = __expf(m1 - mn1);
        m0 = mn0; m1 = mn1;
        float ps0 = 0.f, ps1 = 0.f;
#pragma unroll
        for (int t = 0; t < 8; t++) {
            S[t][0] = __expf(S[t][0] - mn0);
            S[t][1] = __expf(S[t][1] - mn0);
            S[t][2] = __expf(S[t][2] - mn1);
            S[t][3] = __expf(S[t][3] - mn1);
            ps0 += S[t][0] + S[t][1];
            ps1 += S[t][2] + S[t][3];
        }
        ps0 += __shfl_xor_sync(0xffffffffu, ps0, 1);
        ps0 += __shfl_xor_sync(0xffffffffu, ps0, 2);
        ps1 += __shfl_xor_sync(0xffffffffu, ps1, 1);
        ps1 += __shfl_xor_sync(0xffffffffu, ps1, 2);
        l0 = l0 * c0 + ps0;
        l1 = l1 * c1 + ps1;
#pragma unroll
        for (int t = 0; t < 8; t++) {
            O[t][0] *= c0; O[t][1] *= c0; O[t][2] *= c1; O[t][3] *= c1;
        }

        unsigned ph[4][4], pl[4][4];
#pragma unroll
        for (int c = 0; c < 4; c++) {
            int t0 = 2 * c, t1 = 2 * c + 1;
            ph[c][0] = pk2(S[t0][0], S[t0][1]);
            ph[c][1] = pk2(S[t0][2], S[t0][3]);
            ph[c][2] = pk2(S[t1][0], S[t1][1]);
            ph[c][3] = pk2(S[t1][2], S[t1][3]);
            pl[c][0] = pk2(lores(S[t0][0]), lores(S[t0][1]));
            pl[c][1] = pk2(lores(S[t0][2]), lores(S[t0][3]));
            pl[c][2] = pk2(lores(S[t1][0]), lores(S[t1][1]));
            pl[c][3] = pk2(lores(S[t1][2]), lores(S[t1][3]));
        }

#pragma unroll
        for (int c = 0; c < 4; c++) {
#pragma unroll
            for (int tp = 0; tp < 4; tp++) {
                unsigned bh[4], bl[4];
                unsigned off = base + 18432u
                    + ((c * 16 + vr) * 72 + tp * 16 + vc8) * 2;
                LDSM4T(bh, off);
                LDSM4T(bl, off + 9216u);
#pragma unroll
                for (int u = 0; u < 2; u++) {
                    float* c4 = O[tp * 2 + u];
                    MMA_BF16v(c4, ph[c], bh[u], bh[u + 2]);
                    MMA_BF16v(c4, ph[c], bl[u], bl[u + 2]);
                    MMA_BF16v(c4, pl[c], bh[u], bh[u + 2]);
                }
            }
        }
        __syncthreads();
        if (kb + 2 < 16) issue_kv(kb + 2, kb & 1);
    }

    float inv0 = 1.f / l0, inv1 = 1.f / l1;
#pragma unroll
    for (int t = 0; t < 8; t++) {
        int col = h * 64 + 8 * t + 2 * tg;
        size_t o0 = (size_t)qrow * 1024 + col;
        size_t o1 = o0 + 8 * 1024;
        float2 gg0 = *(const float2*)(g_g + o0);
        float2 gg1 = *(const float2*)(g_g + o1);
        float v0 = O[t][0] * inv0 * gg0.x;
        float v1 = O[t][1] * inv0 * gg0.y;
        float v2 = O[t][2] * inv1 * gg1.x;
        float v3 = O[t][3] * inv1 * gg1.y;
        *(unsigned*)(g_ohi + o0) = pk2(v0, v1);
        *(unsigned*)(g_ohi + o1) = pk2(v2, v3);
        *(unsigned*)(g_olo + o0) = pk2(lores(v0), lores(v1));
        *(unsigned*)(g_olo + o1) = pk2(lores(v2), lores(v3));
    }
}

// ---------------------------------------------------------------------------
extern "C" void kernel_launch(void* const* d_in, const int* in_sizes, int n_in,
                              void* d_out, int out_size)
{
    const float* single = (const float*)d_in[0];
    const float* pw     = (const float*)d_in[1];
    const float* gamma  = (const float*)d_in[2];
    const float* beta   = (const float*)d_in[3];
    const float* Wb     = (const float*)d_in[4];
    const float* Wq     = (const float*)d_in[5];
    const float* Wk     = (const float*)d_in[6];
    const float* Wv     = (const float*)d_in[7];
    const float* Wg     = (const float*)d_in[8];
    const float* bg     = (const float*)d_in[9];
    const float* Wo     = (const float*)d_in[10];
    float* out = (float*)d_out;

    const int GEMM_SMEM = 81920;
    const int ATTN_SMEM = 73728;
    cudaFuncSetAttribute(gemm_mma, cudaFuncAttributeMaxDynamicSharedMemorySize,
                         GEMM_SMEM);
    cudaFuncSetAttribute(attn_kernel, cudaFuncAttributeMaxDynamicSharedMemorySize,
                         ATTN_SMEM);

    bias_setup<<<1, 128>>>(gamma, beta, Wb);
    dim3 bgrid(16, 1024);
    bias_kernel<<<bgrid, 256>>>(pw);

    conv_plain<<<1024, 256>>>(single);
    dim3 tgrid(32, 32, 5), tblk(32, 8);
    convT<<<tgrid, tblk>>>(Wq, Wk, Wv, Wg, Wo);

    dim3 ggrid(8, 8, 4);   // (n-tile 128, m-tile 128, widx)
    gemm_mma<<<ggrid, 256, GEMM_SMEM>>>(1, nullptr, bg);

    dim3 agrid(8, 16);
    attn_kernel<<<agrid, 256, ATTN_SMEM>>>();

    dim3 ogrid(8, 8, 1);
    gemm_mma<<<ogrid, 256, GEMM_SMEM>>>(0, out, nullptr);
}

// round 8
// speedup vs baseline: 3.2007x; 1.2431x over previous
#include <cuda_runtime.h>
#include <cuda_bf16.h>
#include <cstdint>

#define NN (1024u*1024u)

// scratch (device globals: allocation-free)
__device__ float g_bias[16u*1024u*1024u]; // [h][i][j]
__device__ float g_g [NN];                // gates fp32 [token][dim_inner]
__device__ __nv_bfloat16 g_shi[NN], g_slo[NN];      // single_repr hi/lo [m][k]
__device__ __nv_bfloat16 g_wh[5][NN], g_wl[5][NN];  // W [k][n] hi/lo (natural!)
__device__ __nv_bfloat16 g_ohi[NN], g_olo[NN];      // gated attn out hi/lo
__device__ __nv_bfloat16 g_qh[NN], g_ql[NN];        // Q [tok][d_inner] *0.125
__device__ __nv_bfloat16 g_kh[NN], g_kl[NN];        // K [tok][d_inner]
__device__ __nv_bfloat16 g_vh[NN], g_vl[NN];        // V [tok][d_inner]
__device__ __nv_bfloat16 g_wbth[16*128], g_wbtl[16*128]; // (gamma*Wb)^T [h][p]
__device__ float g_binit[16];                            // beta @ Wb

__device__ __forceinline__ unsigned pk2(float a, float b) {
    __nv_bfloat162 t = __floats2bfloat162_rn(a, b);
    return *reinterpret_cast<unsigned*>(&t);
}
__device__ __forceinline__ float lores(float a) {
    return a - __bfloat162float(__float2bfloat16(a));
}
__device__ __forceinline__ unsigned cvta_s(const void* p) {
    return (unsigned)__cvta_generic_to_shared(p);
}

#define MMA_BF16v(c, a, b0, b1) asm volatile( \
    "mma.sync.aligned.m16n8k16.row.col.f32.bf16.bf16.f32 " \
    "{%0,%1,%2,%3},{%4,%5,%6,%7},{%8,%9},{%0,%1,%2,%3};" \
    : "+f"((c)[0]), "+f"((c)[1]), "+f"((c)[2]), "+f"((c)[3]) \
    : "r"((a)[0]), "r"((a)[1]), "r"((a)[2]), "r"((a)[3]), \
      "r"(b0), "r"(b1))
#define LDSM4(R, addr) asm volatile( \
    "ldmatrix.sync.aligned.m8n8.x4.shared.b16 {%0,%1,%2,%3}, [%4];" \
    : "=r"((R)[0]), "=r"((R)[1]), "=r"((R)[2]), "=r"((R)[3]) : "r"(addr))
#define LDSM4T(R, addr) asm volatile( \
    "ldmatrix.sync.aligned.m8n8.x4.trans.shared.b16 {%0,%1,%2,%3}, [%4];" \
    : "=r"((R)[0]), "=r"((R)[1]), "=r"((R)[2]), "=r"((R)[3]) : "r"(addr))
#define CP_ASYNC16(dst, src) asm volatile( \
    "cp.async.cg.shared.global [%0], [%1], 16;" :: "r"(dst), "l"(src) : "memory")
#define CP_COMMIT() asm volatile("cp.async.commit_group;" ::: "memory")
#define CP_WAIT1()  asm volatile("cp.async.wait_group 1;" ::: "memory")
#define CP_WAIT0()  asm volatile("cp.async.wait_group 0;" ::: "memory")

// ---------------------------------------------------------------------------
// One-time prep: (gamma*W_bias)^T as bf16 hi/lo, and beta@W_bias.
// ---------------------------------------------------------------------------
__global__ void bias_setup(const float* __restrict__ gamma,
                           const float* __restrict__ beta,
                           const float* __restrict__ Wb)
{
    int tid = threadIdx.x;
    for (int idx = tid; idx < 2048; idx += 128) {
        int p = idx >> 4, h = idx & 15;
        float w = gamma[p] * Wb[idx];
        __nv_bfloat16 hi = __float2bfloat16(w);
        g_wbth[h * 128 + p] = hi;
        g_wbtl[h * 128 + p] = __float2bfloat16(w - __bfloat162float(hi));
    }
    if (tid < 16) {
        float s = 0.f;
        for (int p = 0; p < 128; p++) s += beta[p] * Wb[p * 16 + tid];
        g_binit[tid] = s;
    }
}

// ---------------------------------------------------------------------------
// Bias kernel: LN (SIMT fp32 stats) + 128->16 projection on tensor cores.
// Batch front-load: each warp issues all 8 row loads (MLP=8) before LN math.
// ---------------------------------------------------------------------------
__global__ __launch_bounds__(256) void bias_kernel(const float* __restrict__ pw)
{
    __shared__ __nv_bfloat16 sXh[64][136], sXl[64][136];
    __shared__ __nv_bfloat16 sWh[16][136], sWl[16][136];
    __shared__ float stage[16][64];
    __shared__ float sbin[16];

    int tid  = threadIdx.x;
    int lane = tid & 31, warp = tid >> 5;
    int i  = blockIdx.y;
    int j0 = blockIdx.x * 64;

    // front-load all 8 rows for this warp (MLP = 8)
    const float4* rowp = (const float4*)(pw
        + ((size_t)i * 1024 + j0 + warp * 8) * 128) + lane;
    float4 x[8];
#pragma unroll
    for (int rr = 0; rr < 8; rr++) x[rr] = rowp[rr * 32];

    for (int idx = tid; idx < 2048; idx += 256) {
        int h = idx >> 7, p = idx & 127;
        sWh[h][p] = g_wbth[idx];
        sWl[h][p] = g_wbtl[idx];
    }
    if (tid < 16) sbin[tid] = g_binit[tid];

#pragma unroll
    for (int rr = 0; rr < 8; rr++) {
        float s  = x[rr].x + x[rr].y + x[rr].z + x[rr].w;
        float ss = x[rr].x*x[rr].x + x[rr].y*x[rr].y
                 + x[rr].z*x[rr].z + x[rr].w*x[rr].w;
#pragma unroll
        for (int off = 16; off >= 1; off >>= 1) {
            s  += __shfl_xor_sync(0xffffffffu, s,  off);
            ss += __shfl_xor_sync(0xffffffffu, ss, off);
        }
        float mu  = s * 0.0078125f;
        float var = ss * 0.0078125f - mu * mu;
        float rs  = rsqrtf(var + 1e-5f);
        float y0 = (x[rr].x - mu) * rs, y1 = (x[rr].y - mu) * rs;
        float y2 = (x[rr].z - mu) * rs, y3 = (x[rr].w - mu) * rs;
        int r = warp * 8 + rr;
        *(uint2*)&sXh[r][lane * 4] = make_uint2(pk2(y0, y1), pk2(y2, y3));
        *(uint2*)&sXl[r][lane * 4] =
            make_uint2(pk2(lores(y0), lores(y1)), pk2(lores(y2), lores(y3)));
    }
    __syncthreads();

    if (warp < 4) {
        int gid  = lane >> 2, tg = lane & 3;
        float acc[2][4] = {};
        int warp_m = warp * 16;
        unsigned aXh = cvta_s(sXh), aXl = cvta_s(sXl);
        unsigned aWh = cvta_s(sWh), aWl = cvta_s(sWl);
        int fr = lane & 15, fc = lane >> 4;
#pragma unroll
        for (int c = 0; c < 8; c++) {
            int kk = c * 16;
            unsigned ah[4], al[4], bh[4], bl[4];
            LDSM4(ah, aXh + ((warp_m + fr) * 136 + kk + fc * 8) * 2);
            LDSM4(al, aXl + ((warp_m + fr) * 136 + kk + fc * 8) * 2);
            LDSM4(bh, aWh + ((fr) * 136 + kk + fc * 8) * 2);
            LDSM4(bl, aWl + ((fr) * 136 + kk + fc * 8) * 2);
#pragma unroll
            for (int t = 0; t < 2; t++) {
                MMA_BF16v(acc[t], ah, bh[t], bh[t + 2]);
                MMA_BF16v(acc[t], ah, bl[t], bl[t + 2]);
                MMA_BF16v(acc[t], al, bh[t], bh[t + 2]);
            }
        }
#pragma unroll
        for (int t = 0; t < 2; t++) {
            int hc = t * 8 + tg * 2;
            int r  = warp_m + gid;
            stage[hc][r]         = acc[t][0];
            stage[hc + 1][r]     = acc[t][1];
            stage[hc][r + 8]     = acc[t][2];
            stage[hc + 1][r + 8] = acc[t][3];
        }
    }
    __syncthreads();
    size_t obase = (size_t)i * 1024 + j0;
    for (int e = tid; e < 1024; e += 256) {
        int hh = e >> 6, j = e & 63;
        g_bias[(size_t)hh * NN + obase + j] = stage[hh][j] + sbin[hh];
    }
}

// ---------------------------------------------------------------------------
// Convert single_repr + all 5 weights -> bf16 hi/lo (no transpose needed).
// blockIdx.y: 0=single, 1..5=W{q,k,v,g,o}.
// ---------------------------------------------------------------------------
__global__ __launch_bounds__(256) void conv_all(
    const float* __restrict__ s0, const float* __restrict__ s1,
    const float* __restrict__ s2, const float* __restrict__ s3,
    const float* __restrict__ s4, const float* __restrict__ s5)
{
    const float* srcs[6] = {s0, s1, s2, s3, s4, s5};
    const float* src = srcs[blockIdx.y];
    __nv_bfloat16 *Dh, *Dl;
    if (blockIdx.y == 0) { Dh = g_shi; Dl = g_slo; }
    else { Dh = g_wh[blockIdx.y - 1]; Dl = g_wl[blockIdx.y - 1]; }

    unsigned i = blockIdx.x * 256u + threadIdx.x;
    float4 v = ((const float4*)src)[i];
    *(unsigned*)(Dh + 4u*i)     = pk2(v.x, v.y);
    *(unsigned*)(Dh + 4u*i + 2) = pk2(v.z, v.w);
    *(unsigned*)(Dl + 4u*i)     = pk2(lores(v.x), lores(v.y));
    *(unsigned*)(Dl + 4u*i + 2) = pk2(lores(v.z), lores(v.w));
}

// ---------------------------------------------------------------------------
// Tensor-core GEMM, 128xNT block tile, BK=32, cp.async depth-2 pipeline.
// A hi/lo row-major [m][k]; B hi/lo NATURAL [k][n] via ldmatrix.trans.
// 3-pass bf16 split, fp32 acc.
// fused=1 (NT=128): blockIdx.z in {Q,K,V,gates}. fused=0 (NT=64): fp32->Cext.
// ---------------------------------------------------------------------------
template <int NT>
__global__ __launch_bounds__(256) void gemm_mma(
    int fused, float* __restrict__ Cext, const float* __restrict__ aux)
{
    extern __shared__ __nv_bfloat16 dsm[];
    constexpr int TPW    = NT / 32;            // n16-tiles per warp
    constexpr int SEGS_B = 32 * NT / 8;        // 16B segments per B matrix
    constexpr int NSEG_T = (1024 + 2 * SEGS_B) / 256;
    constexpr unsigned SZB   = 32u * (NT + 8) * 2;   // bytes per B matrix
    constexpr unsigned BUFSZ = 20480u + 2 * SZB;

    int widx = fused ? blockIdx.z : 4;
    int mode = fused ? ((widx == 3) ? 3 : 4) : 0;
    float scale = (widx == 0) ? 0.125f : 1.0f;

    const __nv_bfloat16* gAh = fused ? g_shi : g_ohi;
    const __nv_bfloat16* gAl = fused ? g_slo : g_olo;
    const __nv_bfloat16* gBh = g_wh[widx];
    const __nv_bfloat16* gBl = g_wl[widx];

    int tid  = threadIdx.x;
    int lane = tid & 31, warp = tid >> 5;
    int gid  = lane >> 2, tg = lane & 3;
    int fr = lane & 15, fc8 = (lane >> 4) * 8;
    int vr = (lane >> 4) * 8 + (lane & 7);         // ldmatrix.trans row
    int vc8 = ((lane >> 3) & 1) * 8;               // ldmatrix.trans col8
    int warp_m = (warp >> 1) * 32, warp_n = (warp & 1) * (NT / 2);
    int m0 = blockIdx.y * 128, n0 = blockIdx.x * NT;
    unsigned sb = cvta_s(dsm);

    auto issue = [&](int ch, int buf) {
        int k0 = ch * 32;
        unsigned bo = buf * BUFSZ;
#pragma unroll
        for (int t = 0; t < NSEG_T; t++) {
            int s = tid + t * 256;
            unsigned dst;
            const __nv_bfloat16* src;
            if (s < 1024) {
                int mt = s >> 9, rem = s & 511;
                int row = rem >> 2, seg = rem & 3;
                dst = sb + bo + mt * 10240u + row * 80u + seg * 16u;
                src = (mt ? gAl : gAh) + (size_t)(m0 + row) * 1024 + k0 + seg * 8;
            } else {
                int ss = s - 1024;
                int mt = ss / SEGS_B, rem = ss % SEGS_B;
                int row = rem / (NT / 8), seg = rem % (NT / 8);
                dst = sb + bo + 20480u + mt * SZB + row * (NT + 8) * 2u + seg * 16u;
                src = (mt ? gBl : gBh) + (size_t)(k0 + row) * 1024 + n0 + seg * 8;
            }
            CP_ASYNC16(dst, src);
        }
        CP_COMMIT();
    };

    float acc[2][2 * TPW][4];
#pragma unroll
    for (int a = 0; a < 2; a++)
#pragma unroll
        for (int b = 0; b < 2 * TPW; b++)
#pragma unroll
            for (int q = 0; q < 4; q++) acc[a][b][q] = 0.f;

    issue(0, 0);
    issue(1, 1);

#pragma unroll 1
    for (int ch = 0; ch < 32; ch++) {
        if (ch < 31) { CP_WAIT1(); } else { CP_WAIT0(); }
        __syncthreads();
        unsigned base = sb + (ch & 1) * BUFSZ;
#pragma unroll
        for (int k16 = 0; k16 < 32; k16 += 16) {
            unsigned a_h[2][4], a_l[2][4], b_h[TPW][4], b_l[TPW][4];
#pragma unroll
            for (int mt = 0; mt < 2; mt++) {
                unsigned off = base + ((warp_m + mt * 16 + fr) * 40 + k16 + fc8) * 2;
                LDSM4(a_h[mt], off);
                LDSM4(a_l[mt], off + 10240u);
            }
#pragma unroll
            for (int tp = 0; tp < TPW; tp++) {
                unsigned off = base + 20480u
                    + ((k16 + vr) * (NT + 8) + warp_n + tp * 16 + vc8) * 2;
                LDSM4T(b_h[tp], off);
                LDSM4T(b_l[tp], off + SZB);
            }
#pragma unroll
            for (int mt = 0; mt < 2; mt++)
#pragma unroll
                for (int tp = 0; tp < TPW; tp++)
#pragma unroll
                    for (int u = 0; u < 2; u++) {
                        float* c4 = acc[mt][tp * 2 + u];
                        MMA_BF16v(c4, a_h[mt], b_h[tp][u], b_h[tp][u + 2]);
                        MMA_BF16v(c4, a_h[mt], b_l[tp][u], b_l[tp][u + 2]);
                        MMA_BF16v(c4, a_l[mt], b_h[tp][u], b_h[tp][u + 2]);
                    }
        }
        __syncthreads();
        if (ch + 2 < 32) issue(ch + 2, ch & 1);
    }

    __nv_bfloat16* Dh = (widx == 0) ? g_qh : (widx == 1) ? g_kh : g_vh;
    __nv_bfloat16* Dl = (widx == 0) ? g_ql : (widx == 1) ? g_kl : g_vl;
#pragma unroll
    for (int mt = 0; mt < 2; mt++) {
#pragma unroll
        for (int j = 0; j < 2 * TPW; j++) {
            int rg = m0 + warp_m + mt * 16 + gid;
            int cg = n0 + warp_n + j * 8 + tg * 2;
            float* a4 = acc[mt][j];
            if (mode == 0) {
                *(float2*)&Cext[(size_t)rg * 1024 + cg]       = make_float2(a4[0], a4[1]);
                *(float2*)&Cext[(size_t)(rg + 8) * 1024 + cg] = make_float2(a4[2], a4[3]);
            } else if (mode == 3) {
                float b0 = aux[cg], b1 = aux[cg + 1];
                float v0 = 1.f / (1.f + __expf(-(a4[0] + b0)));
                float v1 = 1.f / (1.f + __expf(-(a4[1] + b1)));
                float v2 = 1.f / (1.f + __expf(-(a4[2] + b0)));
                float v3 = 1.f / (1.f + __expf(-(a4[3] + b1)));
                *(float2*)&g_g[(size_t)rg * 1024 + cg]       = make_float2(v0, v1);
                *(float2*)&g_g[(size_t)(rg + 8) * 1024 + cg] = make_float2(v2, v3);
            } else {
                float v0 = a4[0] * scale, v1 = a4[1] * scale;
                float v2 = a4[2] * scale, v3 = a4[3] * scale;
                *(unsigned*)&Dh[(size_t)rg * 1024 + cg]       = pk2(v0, v1);
                *(unsigned*)&Dh[(size_t)(rg + 8) * 1024 + cg] = pk2(v2, v3);
                *(unsigned*)&Dl[(size_t)rg * 1024 + cg]       = pk2(lores(v0), lores(v1));
                *(unsigned*)&Dl[(size_t)(rg + 8) * 1024 + cg] =
                    pk2(lores(v2), lores(v3));
            }
        }
    }
}

// ---------------------------------------------------------------------------
// Flash attention, mma.sync + ldmatrix, cp.async depth-2 K/V pipeline.
// 256 thr = 8 warps x m16 -> 128 queries/CTA. Grid (8, 16).
// ---------------------------------------------------------------------------
__global__ __launch_bounds__(256) void attn_kernel()
{
    extern __shared__ __nv_bfloat16 dsm[];
    int tid  = threadIdx.x;
    int lane = tid & 31, warp = tid >> 5;
    int gid  = lane >> 2, tg = lane & 3;
    int h  = blockIdx.y;
    int q0 = blockIdx.x * 128;
    int warp_m = warp * 16;
    int qrow = q0 + warp_m + gid;
    unsigned sb = cvta_s(dsm);

    int fr = lane & 15, fc8 = (lane >> 4) * 8;
    int vr = (lane >> 4) * 8 + (lane & 7);
    int vc8 = ((lane >> 3) & 1) * 8;

    auto issue_kv = [&](int kb, int buf) {
        int k0 = kb * 64;
        unsigned bo = buf * 36864u;
#pragma unroll
        for (int t = 0; t < 8; t++) {
            int s = tid + t * 256;
            int mt = s >> 9, rem = s & 511;
            int row = rem >> 3, seg = rem & 7;
            unsigned dst = sb + bo + mt * 9216u + row * 144u + seg * 16u;
            const __nv_bfloat16* src;
            if      (mt == 0) src = g_kh + (size_t)(k0 + row) * 1024 + h * 64 + seg * 8;
            else if (mt == 1) src = g_kl + (size_t)(k0 + row) * 1024 + h * 64 + seg * 8;
            else if (mt == 2) src = g_vh + (size_t)(k0 + row) * 1024 + h * 64 + seg * 8;
            else              src = g_vl + (size_t)(k0 + row) * 1024 + h * 64 + seg * 8;
            CP_ASYNC16(dst, src);
        }
        CP_COMMIT();
    };

    unsigned qh[4][4], ql[4][4];
    {
        const __nv_bfloat16* Qh = g_qh + (size_t)qrow * 1024 + h * 64;
        const __nv_bfloat16* Ql = g_ql + (size_t)qrow * 1024 + h * 64;
#pragma unroll
        for (int c = 0; c < 4; c++) {
            int kk = c * 16 + tg * 2;
            qh[c][0] = *(const unsigned*)(Qh + kk);
            qh[c][1] = *(const unsigned*)(Qh + 8 * 1024 + kk);
            qh[c][2] = *(const unsigned*)(Qh + kk + 8);
            qh[c][3] = *(const unsigned*)(Qh + 8 * 1024 + kk + 8);
            ql[c][0] = *(const unsigned*)(Ql + kk);
            ql[c][1] = *(const unsigned*)(Ql + 8 * 1024 + kk);
            ql[c][2] = *(const unsigned*)(Ql + kk + 8);
            ql[c][3] = *(const unsigned*)(Ql + 8 * 1024 + kk + 8);
        }
    }

    float m0 = -1e30f, m1 = -1e30f, l0 = 0.f, l1 = 0.f;
    float O[8][4] = {};

    issue_kv(0, 0);
    issue_kv(1, 1);

#pragma unroll 1
    for (int kb = 0; kb < 16; kb++) {
        if (kb < 15) { CP_WAIT1(); } else { CP_WAIT0(); }
        __syncthreads();
        unsigned base = sb + (kb & 1) * 36864u;
        int k0 = kb * 64;

        float S[8][4];
        {
            const float* bptr = g_bias + (size_t)h * NN + (size_t)qrow * 1024 + k0;
#pragma unroll
            for (int t = 0; t < 8; t++) {
                float2 b0 = *(const float2*)(bptr + 8 * t + 2 * tg);
                float2 b1 = *(const float2*)(bptr + 8 * 1024 + 8 * t + 2 * tg);
                S[t][0] = b0.x; S[t][1] = b0.y; S[t][2] = b1.x; S[t][3] = b1.y;
            }
        }
#pragma unroll
        for (int c = 0; c < 4; c++) {
            int kk = c * 16;
#pragma unroll
            for (int tp = 0; tp < 4; tp++) {
                unsigned bh[4], bl[4];
                unsigned off = base + ((tp * 16 + fr) * 72 + kk + fc8) * 2;
                LDSM4(bh, off);
                LDSM4(bl, off + 9216u);
#pragma unroll
                for (int u = 0; u < 2; u++) {
                    float* c4 = S[tp * 2 + u];
                    MMA_BF16v(c4, qh[c], bh[u], bh[u + 2]);
                    MMA_BF16v(c4, qh[c], bl[u], bl[u + 2]);
                    MMA_BF16v(c4, ql[c], bh[u], bh[u + 2]);
                }
            }
        }

        float rm0 = -1e30f, rm1 = -1e30f;
#pragma unroll
        for (int t = 0; t < 8; t++) {
            rm0 = fmaxf(rm0, fmaxf(S[t][0], S[t][1]));
            rm1 = fmaxf(rm1, fmaxf(S[t][2], S[t][3]));
        }
        rm0 = fmaxf(rm0, __shfl_xor_sync(0xffffffffu, rm0, 1));
        rm0 = fmaxf(rm0, __shfl_xor_sync(0xffffffffu, rm0, 2));
        rm1 = fmaxf(rm1, __shfl_xor_sync(0xffffffffu, rm1, 1));
        rm1 = fmaxf(rm1, __shfl_xor_sync(0xffffffffu, rm1, 2));
        float mn0 = fmaxf(m0, rm0), mn1 = fmaxf(m1, rm1);
        float c0 = __expf(m0 - mn0), c1 = __expf(m1 - mn1);
        m0 = mn0; m1 = mn1;
        float ps0 = 0.f, ps1 = 0.f;
#pragma unroll
        for (int t = 0; t < 8; t++) {
            S[t][0] = __expf(S[t][0] - mn0);
            S[t][1] = __expf(S[t][1] - mn0);
            S[t][2] = __expf(S[t][2] - mn1);
            S[t][3] = __expf(S[t][3] - mn1);
            ps0 += S[t][0] + S[t][1];
            ps1 += S[t][2] + S[t][3];
        }
        ps0 += __shfl_xor_sync(0xffffffffu, ps0, 1);
        ps0 += __shfl_xor_sync(0xffffffffu, ps0, 2);
        ps1 += __shfl_xor_sync(0xffffffffu, ps1, 1);
        ps1 += __shfl_xor_sync(0xffffffffu, ps1, 2);
        l0 = l0 * c0 + ps0;
        l1 = l1 * c1 + ps1;
#pragma unroll
        for (int t = 0; t < 8; t++) {
            O[t][0] *= c0; O[t][1] *= c0; O[t][2] *= c1; O[t][3] *= c1;
        }

        unsigned ph[4][4], pl[4][4];
#pragma unroll
        for (int c = 0; c < 4; c++) {
            int t0 = 2 * c, t1 = 2 * c + 1;
            ph[c][0] = pk2(S[t0][0], S[t0][1]);
            ph[c][1] = pk2(S[t0][2], S[t0][3]);
            ph[c][2] = pk2(S[t1][0], S[t1][1]);
            ph[c][3] = pk2(S[t1][2], S[t1][3]);
            pl[c][0] = pk2(lores(S[t0][0]), lores(S[t0][1]));
            pl[c][1] = pk2(lores(S[t0][2]), lores(S[t0][3]));
            pl[c][2] = pk2(lores(S[t1][0]), lores(S[t1][1]));
            pl[c][3] = pk2(lores(S[t1][2]), lores(S[t1][3]));
        }

#pragma unroll
        for (int c = 0; c < 4; c++) {
#pragma unroll
            for (int tp = 0; tp < 4; tp++) {
                unsigned bh[4], bl[4];
                unsigned off = base + 18432u
                    + ((c * 16 + vr) * 72 + tp * 16 + vc8) * 2;
                LDSM4T(bh, off);
                LDSM4T(bl, off + 9216u);
#pragma unroll
                for (int u = 0; u < 2; u++) {
                    float* c4 = O[tp * 2 + u];
                    MMA_BF16v(c4, ph[c], bh[u], bh[u + 2]);
                    MMA_BF16v(c4, ph[c], bl[u], bl[u + 2]);
                    MMA_BF16v(c4, pl[c], bh[u], bh[u + 2]);
                }
            }
        }
        __syncthreads();
        if (kb + 2 < 16) issue_kv(kb + 2, kb & 1);
    }

    float inv0 = 1.f / l0, inv1 = 1.f / l1;
#pragma unroll
    for (int t = 0; t < 8; t++) {
        int col = h * 64 + 8 * t + 2 * tg;
        size_t o0 = (size_t)qrow * 1024 + col;
        size_t o1 = o0 + 8 * 1024;
        float2 gg0 = *(const float2*)(g_g + o0);
        float2 gg1 = *(const float2*)(g_g + o1);
        float v0 = O[t][0] * inv0 * gg0.x;
        float v1 = O[t][1] * inv0 * gg0.y;
        float v2 = O[t][2] * inv1 * gg1.x;
        float v3 = O[t][3] * inv1 * gg1.y;
        *(unsigned*)(g_ohi + o0) = pk2(v0, v1);
        *(unsigned*)(g_ohi + o1) = pk2(v2, v3);
        *(unsigned*)(g_olo + o0) = pk2(lores(v0), lores(v1));
        *(unsigned*)(g_olo + o1) = pk2(lores(v2), lores(v3));
    }
}

// ---------------------------------------------------------------------------
extern "C" void kernel_launch(void* const* d_in, const int* in_sizes, int n_in,
                              void* d_out, int out_size)
{
    const float* single = (const float*)d_in[0];
    const float* pw     = (const float*)d_in[1];
    const float* gamma  = (const float*)d_in[2];
    const float* beta   = (const float*)d_in[3];
    const float* Wb     = (const float*)d_in[4];
    const float* Wq     = (const float*)d_in[5];
    const float* Wk     = (const float*)d_in[6];
    const float* Wv     = (const float*)d_in[7];
    const float* Wg     = (const float*)d_in[8];
    const float* bg     = (const float*)d_in[9];
    const float* Wo     = (const float*)d_in[10];
    float* out = (float*)d_out;

    // smem sizes: BUFSZ = 20480 + 2*(32*(NT+8)*2); two buffers
    const int SM128 = 2 * (20480 + 2 * (32 * 136 * 2));  // 75776
    const int SM64  = 2 * (20480 + 2 * (32 * 72  * 2));  // 59392
    const int ATTN_SMEM = 73728;
    cudaFuncSetAttribute(gemm_mma<128>,
        cudaFuncAttributeMaxDynamicSharedMemorySize, SM128);
    cudaFuncSetAttribute(gemm_mma<64>,
        cudaFuncAttributeMaxDynamicSharedMemorySize, SM64);
    cudaFuncSetAttribute(attn_kernel,
        cudaFuncAttributeMaxDynamicSharedMemorySize, ATTN_SMEM);

    bias_setup<<<1, 128>>>(gamma, beta, Wb);
    dim3 bgrid(16, 1024);
    bias_kernel<<<bgrid, 256>>>(pw);

    dim3 cgrid(1024, 6);
    conv_all<<<cgrid, 256>>>(single, Wq, Wk, Wv, Wg, Wo);

    dim3 ggrid(8, 8, 4);   // (n-tile 128, m-tile 128, widx)
    gemm_mma<128><<<ggrid, 256, SM128>>>(1, nullptr, bg);

    dim3 agrid(8, 16);
    attn_kernel<<<agrid, 256, ATTN_SMEM>>>();

    dim3 ogrid(16, 8);     // n-tile 64 -> 128 CTAs, one full wave
    gemm_mma<64><<<ogrid, 256, SM64>>>(0, out, nullptr);
}

// round 9
// speedup vs baseline: 3.2485x; 1.0149x over previous
#include <cuda_runtime.h>
#include <cuda_bf16.h>
#include <cstdint>

#define NN (1024u*1024u)

// scratch (device globals: allocation-free)
__device__ float g_bias[16u*1024u*1024u]; // [h][i][j]
__device__ float g_g [NN];                // gates fp32 [token][dim_inner]
__device__ __nv_bfloat16 g_shi[NN], g_slo[NN];      // single_repr hi/lo [m][k]
__device__ __nv_bfloat16 g_wh[5][NN], g_wl[5][NN];  // W [k][n] hi/lo (natural)
__device__ __nv_bfloat16 g_ohi[NN], g_olo[NN];      // gated attn out hi/lo
__device__ __nv_bfloat16 g_qh[NN], g_ql[NN];        // Q [tok][d_inner] *0.125
__device__ __nv_bfloat16 g_kh[NN], g_kl[NN];        // K [tok][d_inner]
__device__ __nv_bfloat16 g_vh[NN], g_vl[NN];        // V [tok][d_inner]
__device__ __nv_bfloat16 g_wbth[16*128], g_wbtl[16*128]; // (gamma*Wb)^T [h][p]
__device__ float g_binit[16];                            // beta @ Wb

__device__ __forceinline__ unsigned pk2(float a, float b) {
    __nv_bfloat162 t = __floats2bfloat162_rn(a, b);
    return *reinterpret_cast<unsigned*>(&t);
}
__device__ __forceinline__ float lores(float a) {
    return a - __bfloat162float(__float2bfloat16(a));
}
__device__ __forceinline__ unsigned cvta_s(const void* p) {
    return (unsigned)__cvta_generic_to_shared(p);
}

#define MMA_BF16v(c, a, b0, b1) asm volatile( \
    "mma.sync.aligned.m16n8k16.row.col.f32.bf16.bf16.f32 " \
    "{%0,%1,%2,%3},{%4,%5,%6,%7},{%8,%9},{%0,%1,%2,%3};" \
    : "+f"((c)[0]), "+f"((c)[1]), "+f"((c)[2]), "+f"((c)[3]) \
    : "r"((a)[0]), "r"((a)[1]), "r"((a)[2]), "r"((a)[3]), \
      "r"(b0), "r"(b1))
#define LDSM4(R, addr) asm volatile( \
    "ldmatrix.sync.aligned.m8n8.x4.shared.b16 {%0,%1,%2,%3}, [%4];" \
    : "=r"((R)[0]), "=r"((R)[1]), "=r"((R)[2]), "=r"((R)[3]) : "r"(addr))
#define LDSM4T(R, addr) asm volatile( \
    "ldmatrix.sync.aligned.m8n8.x4.trans.shared.b16 {%0,%1,%2,%3}, [%4];" \
    : "=r"((R)[0]), "=r"((R)[1]), "=r"((R)[2]), "=r"((R)[3]) : "r"(addr))
#define CP_ASYNC16(dst, src) asm volatile( \
    "cp.async.cg.shared.global [%0], [%1], 16;" :: "r"(dst), "l"(src) : "memory")
#define CP_COMMIT() asm volatile("cp.async.commit_group;" ::: "memory")
#define CP_WAIT1()  asm volatile("cp.async.wait_group 1;" ::: "memory")
#define CP_WAIT0()  asm volatile("cp.async.wait_group 0;" ::: "memory")

// ---------------------------------------------------------------------------
// One-time prep: (gamma*W_bias)^T as bf16 hi/lo, and beta@W_bias.
// ---------------------------------------------------------------------------
__global__ void bias_setup(const float* __restrict__ gamma,
                           const float* __restrict__ beta,
                           const float* __restrict__ Wb)
{
    int tid = threadIdx.x;
    for (int idx = tid; idx < 2048; idx += 128) {
        int p = idx >> 4, h = idx & 15;
        float w = gamma[p] * Wb[idx];
        __nv_bfloat16 hi = __float2bfloat16(w);
        g_wbth[h * 128 + p] = hi;
        g_wbtl[h * 128 + p] = __float2bfloat16(w - __bfloat162float(hi));
    }
    if (tid < 16) {
        float s = 0.f;
        for (int p = 0; p < 128; p++) s += beta[p] * Wb[p * 16 + tid];
        g_binit[tid] = s;
    }
}

// ---------------------------------------------------------------------------
// Bias kernel: LN (SIMT fp32 stats) + 128->16 projection on tensor cores.
// ---------------------------------------------------------------------------
__global__ __launch_bounds__(256) void bias_kernel(const float* __restrict__ pw)
{
    __shared__ __nv_bfloat16 sXh[64][136], sXl[64][136];
    __shared__ __nv_bfloat16 sWh[16][136], sWl[16][136];
    __shared__ float stage[16][64];
    __shared__ float sbin[16];

    int tid  = threadIdx.x;
    int lane = tid & 31, warp = tid >> 5;
    int i  = blockIdx.y;
    int j0 = blockIdx.x * 64;

    const float4* rowp = (const float4*)(pw
        + ((size_t)i * 1024 + j0 + warp * 8) * 128) + lane;
    float4 x[8];
#pragma unroll
    for (int rr = 0; rr < 8; rr++) x[rr] = rowp[rr * 32];

    for (int idx = tid; idx < 2048; idx += 256) {
        int h = idx >> 7, p = idx & 127;
        sWh[h][p] = g_wbth[idx];
        sWl[h][p] = g_wbtl[idx];
    }
    if (tid < 16) sbin[tid] = g_binit[tid];

#pragma unroll
    for (int rr = 0; rr < 8; rr++) {
        float s  = x[rr].x + x[rr].y + x[rr].z + x[rr].w;
        float ss = x[rr].x*x[rr].x + x[rr].y*x[rr].y
                 + x[rr].z*x[rr].z + x[rr].w*x[rr].w;
#pragma unroll
        for (int off = 16; off >= 1; off >>= 1) {
            s  += __shfl_xor_sync(0xffffffffu, s,  off);
            ss += __shfl_xor_sync(0xffffffffu, ss, off);
        }
        float mu  = s * 0.0078125f;
        float var = ss * 0.0078125f - mu * mu;
        float rs  = rsqrtf(var + 1e-5f);
        float y0 = (x[rr].x - mu) * rs, y1 = (x[rr].y - mu) * rs;
        float y2 = (x[rr].z - mu) * rs, y3 = (x[rr].w - mu) * rs;
        int r = warp * 8 + rr;
        *(uint2*)&sXh[r][lane * 4] = make_uint2(pk2(y0, y1), pk2(y2, y3));
        *(uint2*)&sXl[r][lane * 4] =
            make_uint2(pk2(lores(y0), lores(y1)), pk2(lores(y2), lores(y3)));
    }
    __syncthreads();

    if (warp < 4) {
        int gid  = lane >> 2, tg = lane & 3;
        float acc[2][4] = {};
        int warp_m = warp * 16;
        unsigned aXh = cvta_s(sXh), aXl = cvta_s(sXl);
        unsigned aWh = cvta_s(sWh), aWl = cvta_s(sWl);
        int fr = lane & 15, fc = lane >> 4;
#pragma unroll
        for (int c = 0; c < 8; c++) {
            int kk = c * 16;
            unsigned ah[4], al[4], bh[4], bl[4];
            LDSM4(ah, aXh + ((warp_m + fr) * 136 + kk + fc * 8) * 2);
            LDSM4(al, aXl + ((warp_m + fr) * 136 + kk + fc * 8) * 2);
            LDSM4(bh, aWh + ((fr) * 136 + kk + fc * 8) * 2);
            LDSM4(bl, aWl + ((fr) * 136 + kk + fc * 8) * 2);
#pragma unroll
            for (int t = 0; t < 2; t++) {
                MMA_BF16v(acc[t], ah, bh[t], bh[t + 2]);
                MMA_BF16v(acc[t], ah, bl[t], bl[t + 2]);
                MMA_BF16v(acc[t], al, bh[t], bh[t + 2]);
            }
        }
#pragma unroll
        for (int t = 0; t < 2; t++) {
            int hc = t * 8 + tg * 2;
            int r  = warp_m + gid;
            stage[hc][r]         = acc[t][0];
            stage[hc + 1][r]     = acc[t][1];
            stage[hc][r + 8]     = acc[t][2];
            stage[hc + 1][r + 8] = acc[t][3];
        }
    }
    __syncthreads();
    size_t obase = (size_t)i * 1024 + j0;
    for (int e = tid; e < 1024; e += 256) {
        int hh = e >> 6, j = e & 63;
        g_bias[(size_t)hh * NN + obase + j] = stage[hh][j] + sbin[hh];
    }
}

// ---------------------------------------------------------------------------
// Convert single_repr + all 5 weights -> bf16 hi/lo.
// ---------------------------------------------------------------------------
__global__ __launch_bounds__(256) void conv_all(
    const float* __restrict__ s0, const float* __restrict__ s1,
    const float* __restrict__ s2, const float* __restrict__ s3,
    const float* __restrict__ s4, const float* __restrict__ s5)
{
    const float* srcs[6] = {s0, s1, s2, s3, s4, s5};
    const float* src = srcs[blockIdx.y];
    __nv_bfloat16 *Dh, *Dl;
    if (blockIdx.y == 0) { Dh = g_shi; Dl = g_slo; }
    else { Dh = g_wh[blockIdx.y - 1]; Dl = g_wl[blockIdx.y - 1]; }

    unsigned i = blockIdx.x * 256u + threadIdx.x;
    float4 v = ((const float4*)src)[i];
    *(unsigned*)(Dh + 4u*i)     = pk2(v.x, v.y);
    *(unsigned*)(Dh + 4u*i + 2) = pk2(v.z, v.w);
    *(unsigned*)(Dl + 4u*i)     = pk2(lores(v.x), lores(v.y));
    *(unsigned*)(Dl + 4u*i + 2) = pk2(lores(v.z), lores(v.w));
}

// ---------------------------------------------------------------------------
// QKVG GEMM: 512 thr, tile 128x256, BK=32, cp.async depth-2.
// Grid (4, 8, 4) = 128 CTAs = exactly one full wave.
// A hi/lo [m][k] via ldmatrix; B hi/lo natural [k][n] via ldmatrix.trans.
// smem/buf: Ah 10240 | Al 10240 | Bh 16896 | Bl 16896 = 54272; x2 = 108544.
// ---------------------------------------------------------------------------
__global__ __launch_bounds__(512, 1) void gemm_qkvg(const float* __restrict__ aux)
{
    extern __shared__ __nv_bfloat16 dsm[];
    constexpr unsigned SZB   = 16896u;   // 32 * 264 * 2
    constexpr unsigned BUFSZ = 54272u;

    int widx = blockIdx.z;
    float scale = (widx == 0) ? 0.125f : 1.0f;
    const __nv_bfloat16* gBh = g_wh[widx];
    const __nv_bfloat16* gBl = g_wl[widx];

    int tid  = threadIdx.x;
    int lane = tid & 31, warp = tid >> 5;
    int gid  = lane >> 2, tg = lane & 3;
    int fr = lane & 15, fc8 = (lane >> 4) * 8;
    int vr = (lane >> 4) * 8 + (lane & 7);
    int vc8 = ((lane >> 3) & 1) * 8;
    int warp_m = (warp >> 2) * 32, warp_n = (warp & 3) * 64;
    int m0 = blockIdx.y * 128, n0 = blockIdx.x * 256;
    unsigned sb = cvta_s(dsm);

    // per-thread fixed load mapping
    int a_row = (tid & 511) >> 2, a_seg = tid & 3;         // for s<1024 halves
    int b_row = (tid & 1023) >> 5, b_seg = tid & 31;

    auto issue = [&](int ch, int buf) {
        int k0 = ch * 32;
        unsigned bo = sb + buf * BUFSZ;
        // t=0: A hi, t=1: A lo
        {
            unsigned d0 = bo + a_row * 80u + a_seg * 16u;
            const __nv_bfloat16* s0 = g_shi + (size_t)(m0 + a_row) * 1024 + k0 + a_seg * 8;
            const __nv_bfloat16* s1 = g_slo + (size_t)(m0 + a_row) * 1024 + k0 + a_seg * 8;
            CP_ASYNC16(d0,          s0);
            CP_ASYNC16(d0 + 10240u, s1);
        }
        // t=2..5: B hi (2 passes), B lo (2 passes)
        {
            unsigned db = bo + 20480u + b_row * 528u + b_seg * 16u;
            const __nv_bfloat16* sh = gBh + (size_t)(k0 + b_row) * 1024 + n0 + b_seg * 8;
            const __nv_bfloat16* sl = gBl + (size_t)(k0 + b_row) * 1024 + n0 + b_seg * 8;
            CP_ASYNC16(db,          sh);
            CP_ASYNC16(db + SZB,    sl);
            unsigned db2 = bo + 20480u + (b_row + 16) * 528u + b_seg * 16u;
            const __nv_bfloat16* sh2 = gBh + (size_t)(k0 + b_row + 16) * 1024 + n0 + b_seg * 8;
            const __nv_bfloat16* sl2 = gBl + (size_t)(k0 + b_row + 16) * 1024 + n0 + b_seg * 8;
            CP_ASYNC16(db2,         sh2);
            CP_ASYNC16(db2 + SZB,   sl2);
        }
        CP_COMMIT();
    };

    float acc[2][8][4];
#pragma unroll
    for (int a = 0; a < 2; a++)
#pragma unroll
        for (int b = 0; b < 8; b++)
#pragma unroll
            for (int q = 0; q < 4; q++) acc[a][b][q] = 0.f;

    issue(0, 0);
    issue(1, 1);

#pragma unroll 1
    for (int ch = 0; ch < 32; ch++) {
        if (ch < 31) { CP_WAIT1(); } else { CP_WAIT0(); }
        __syncthreads();
        unsigned base = sb + (ch & 1) * BUFSZ;
#pragma unroll
        for (int k16 = 0; k16 < 32; k16 += 16) {
            unsigned a_h[2][4], a_l[2][4], b_h[4][4], b_l[4][4];
#pragma unroll
            for (int mt = 0; mt < 2; mt++) {
                unsigned off = base + ((warp_m + mt * 16 + fr) * 40 + k16 + fc8) * 2;
                LDSM4(a_h[mt], off);
                LDSM4(a_l[mt], off + 10240u);
            }
#pragma unroll
            for (int tp = 0; tp < 4; tp++) {
                unsigned off = base + 20480u
                    + ((k16 + vr) * 264 + warp_n + tp * 16 + vc8) * 2;
                LDSM4T(b_h[tp], off);
                LDSM4T(b_l[tp], off + SZB);
            }
#pragma unroll
            for (int mt = 0; mt < 2; mt++)
#pragma unroll
                for (int tp = 0; tp < 4; tp++)
#pragma unroll
                    for (int u = 0; u < 2; u++) {
                        float* c4 = acc[mt][tp * 2 + u];
                        MMA_BF16v(c4, a_h[mt], b_h[tp][u], b_h[tp][u + 2]);
                        MMA_BF16v(c4, a_h[mt], b_l[tp][u], b_l[tp][u + 2]);
                        MMA_BF16v(c4, a_l[mt], b_h[tp][u], b_h[tp][u + 2]);
                    }
        }
        __syncthreads();
        if (ch + 2 < 32) issue(ch + 2, ch & 1);
    }

    __nv_bfloat16* Dh = (widx == 0) ? g_qh : (widx == 1) ? g_kh : g_vh;
    __nv_bfloat16* Dl = (widx == 0) ? g_ql : (widx == 1) ? g_kl : g_vl;
#pragma unroll
    for (int mt = 0; mt < 2; mt++) {
#pragma unroll
        for (int j = 0; j < 8; j++) {
            int rg = m0 + warp_m + mt * 16 + gid;
            int cg = n0 + warp_n + j * 8 + tg * 2;
            float* a4 = acc[mt][j];
            if (widx == 3) {
                float b0 = aux[cg], b1 = aux[cg + 1];
                float v0 = 1.f / (1.f + __expf(-(a4[0] + b0)));
                float v1 = 1.f / (1.f + __expf(-(a4[1] + b1)));
                float v2 = 1.f / (1.f + __expf(-(a4[2] + b0)));
                float v3 = 1.f / (1.f + __expf(-(a4[3] + b1)));
                *(float2*)&g_g[(size_t)rg * 1024 + cg]       = make_float2(v0, v1);
                *(float2*)&g_g[(size_t)(rg + 8) * 1024 + cg] = make_float2(v2, v3);
            } else {
                float v0 = a4[0] * scale, v1 = a4[1] * scale;
                float v2 = a4[2] * scale, v3 = a4[3] * scale;
                *(unsigned*)&Dh[(size_t)rg * 1024 + cg]       = pk2(v0, v1);
                *(unsigned*)&Dh[(size_t)(rg + 8) * 1024 + cg] = pk2(v2, v3);
                *(unsigned*)&Dl[(size_t)rg * 1024 + cg]       = pk2(lores(v0), lores(v1));
                *(unsigned*)&Dl[(size_t)(rg + 8) * 1024 + cg] =
                    pk2(lores(v2), lores(v3));
            }
        }
    }
}

// ---------------------------------------------------------------------------
// Output GEMM: 256 thr, tile 128x64, BK=32, cp.async depth-2. Grid (16,8)=128.
// ---------------------------------------------------------------------------
__global__ __launch_bounds__(256) void gemm_out(float* __restrict__ Cext)
{
    extern __shared__ __nv_bfloat16 dsm[];
    constexpr unsigned SZB   = 32u * 72 * 2;          // 4608
    constexpr unsigned BUFSZ = 20480u + 2 * SZB;      // 29696

    const __nv_bfloat16* gBh = g_wh[4];
    const __nv_bfloat16* gBl = g_wl[4];

    int tid  = threadIdx.x;
    int lane = tid & 31, warp = tid >> 5;
    int gid  = lane >> 2, tg = lane & 3;
    int fr = lane & 15, fc8 = (lane >> 4) * 8;
    int vr = (lane >> 4) * 8 + (lane & 7);
    int vc8 = ((lane >> 3) & 1) * 8;
    int warp_m = (warp >> 1) * 32, warp_n = (warp & 1) * 32;
    int m0 = blockIdx.y * 128, n0 = blockIdx.x * 64;
    unsigned sb = cvta_s(dsm);

    auto issue = [&](int ch, int buf) {
        int k0 = ch * 32;
        unsigned bo = sb + buf * BUFSZ;
#pragma unroll
        for (int t = 0; t < 6; t++) {
            int s = tid + t * 256;
            unsigned dst;
            const __nv_bfloat16* src;
            if (s < 1024) {
                int mt = s >> 9, rem = s & 511;
                int row = rem >> 2, seg = rem & 3;
                dst = bo + mt * 10240u + row * 80u + seg * 16u;
                src = (mt ? g_olo : g_ohi) + (size_t)(m0 + row) * 1024 + k0 + seg * 8;
            } else {
                int ss = s - 1024;               // 0..511
                int mt = ss >> 8, rem = ss & 255;
                int row = rem >> 3, seg = rem & 7;
                dst = bo + 20480u + mt * SZB + row * 144u + seg * 16u;
                src = (mt ? gBl : gBh) + (size_t)(k0 + row) * 1024 + n0 + seg * 8;
            }
            CP_ASYNC16(dst, src);
        }
        CP_COMMIT();
    };

    float acc[2][4][4];
#pragma unroll
    for (int a = 0; a < 2; a++)
#pragma unroll
        for (int b = 0; b < 4; b++)
#pragma unroll
            for (int q = 0; q < 4; q++) acc[a][b][q] = 0.f;

    issue(0, 0);
    issue(1, 1);

#pragma unroll 1
    for (int ch = 0; ch < 32; ch++) {
        if (ch < 31) { CP_WAIT1(); } else { CP_WAIT0(); }
        __syncthreads();
        unsigned base = sb + (ch & 1) * BUFSZ;
#pragma unroll
        for (int k16 = 0; k16 < 32; k16 += 16) {
            unsigned a_h[2][4], a_l[2][4], b_h[2][4], b_l[2][4];
#pragma unroll
            for (int mt = 0; mt < 2; mt++) {
                unsigned off = base + ((warp_m + mt * 16 + fr) * 40 + k16 + fc8) * 2;
                LDSM4(a_h[mt], off);
                LDSM4(a_l[mt], off + 10240u);
            }
#pragma unroll
            for (int tp = 0; tp < 2; tp++) {
                unsigned off = base + 20480u
                    + ((k16 + vr) * 72 + warp_n + tp * 16 + vc8) * 2;
                LDSM4T(b_h[tp], off);
                LDSM4T(b_l[tp], off + SZB);
            }
#pragma unroll
            for (int mt = 0; mt < 2; mt++)
#pragma unroll
                for (int tp = 0; tp < 2; tp++)
#pragma unroll
                    for (int u = 0; u < 2; u++) {
                        float* c4 = acc[mt][tp * 2 + u];
                        MMA_BF16v(c4, a_h[mt], b_h[tp][u], b_h[tp][u + 2]);
                        MMA_BF16v(c4, a_h[mt], b_l[tp][u], b_l[tp][u + 2]);
                        MMA_BF16v(c4, a_l[mt], b_h[tp][u], b_h[tp][u + 2]);
                    }
        }
        __syncthreads();
        if (ch + 2 < 32) issue(ch + 2, ch & 1);
    }

#pragma unroll
    for (int mt = 0; mt < 2; mt++) {
#pragma unroll
        for (int j = 0; j < 4; j++) {
            int rg = m0 + warp_m + mt * 16 + gid;
            int cg = n0 + warp_n + j * 8 + tg * 2;
            float* a4 = acc[mt][j];
            *(float2*)&Cext[(size_t)rg * 1024 + cg]       = make_float2(a4[0], a4[1]);
            *(float2*)&Cext[(size_t)(rg + 8) * 1024 + cg] = make_float2(a4[2], a4[3]);
        }
    }
}

// ---------------------------------------------------------------------------
// Flash attention, mma.sync + ldmatrix, cp.async depth-2 K/V pipeline.
// 256 thr = 8 warps x m16 -> 128 queries/CTA. Grid (8, 16).
// ---------------------------------------------------------------------------
__global__ __launch_bounds__(256) void attn_kernel()
{
    extern __shared__ __nv_bfloat16 dsm[];
    int tid  = threadIdx.x;
    int lane = tid & 31, warp = tid >> 5;
    int gid  = lane >> 2, tg = lane & 3;
    int h  = blockIdx.y;
    int q0 = blockIdx.x * 128;
    int warp_m = warp * 16;
    int qrow = q0 + warp_m + gid;
    unsigned sb = cvta_s(dsm);

    int fr = lane & 15, fc8 = (lane >> 4) * 8;
    int vr = (lane >> 4) * 8 + (lane & 7);
    int vc8 = ((lane >> 3) & 1) * 8;

    auto issue_kv = [&](int kb, int buf) {
        int k0 = kb * 64;
        unsigned bo = buf * 36864u;
#pragma unroll
        for (int t = 0; t < 8; t++) {
            int s = tid + t * 256;
            int mt = s >> 9, rem = s & 511;
            int row = rem >> 3, seg = rem & 7;
            unsigned dst = sb + bo + mt * 9216u + row * 144u + seg * 16u;
            const __nv_bfloat16* src;
            if      (mt == 0) src = g_kh + (size_t)(k0 + row) * 1024 + h * 64 + seg * 8;
            else if (mt == 1) src = g_kl + (size_t)(k0 + row) * 1024 + h * 64 + seg * 8;
            else if (mt == 2) src = g_vh + (size_t)(k0 + row) * 1024 + h * 64 + seg * 8;
            else              src = g_vl + (size_t)(k0 + row) * 1024 + h * 64 + seg * 8;
            CP_ASYNC16(dst, src);
        }
        CP_COMMIT();
    };

    unsigned qh[4][4], ql[4][4];
    {
        const __nv_bfloat16* Qh = g_qh + (size_t)qrow * 1024 + h * 64;
        const __nv_bfloat16* Ql = g_ql + (size_t)qrow * 1024 + h * 64;
#pragma unroll
        for (int c = 0; c < 4; c++) {
            int kk = c * 16 + tg * 2;
            qh[c][0] = *(const unsigned*)(Qh + kk);
            qh[c][1] = *(const unsigned*)(Qh + 8 * 1024 + kk);
            qh[c][2] = *(const unsigned*)(Qh + kk + 8);
            qh[c][3] = *(const unsigned*)(Qh + 8 * 1024 + kk + 8);
            ql[c][0] = *(const unsigned*)(Ql + kk);
            ql[c][1] = *(const unsigned*)(Ql + 8 * 1024 + kk);
            ql[c][2] = *(const unsigned*)(Ql + kk + 8);
            ql[c][3] = *(const unsigned*)(Ql + 8 * 1024 + kk + 8);
        }
    }

    float m0 = -1e30f, m1 = -1e30f, l0 = 0.f, l1 = 0.f;
    float O[8][4] = {};

    issue_kv(0, 0);
    issue_kv(1, 1);

#pragma unroll 1
    for (int kb = 0; kb < 16; kb++) {
        if (kb < 15) { CP_WAIT1(); } else { CP_WAIT0(); }
        __syncthreads();
        unsigned base = sb + (kb & 1) * 36864u;
        int k0 = kb * 64;

        float S[8][4];
        {
            const float* bptr = g_bias + (size_t)h * NN + (size_t)qrow * 1024 + k0;
#pragma unroll
            for (int t = 0; t < 8; t++) {
                float2 b0 = *(const float2*)(bptr + 8 * t + 2 * tg);
                float2 b1 = *(const float2*)(bptr + 8 * 1024 + 8 * t + 2 * tg);
                S[t][0] = b0.x; S[t][1] = b0.y; S[t][2] = b1.x; S[t][3] = b1.y;
            }
        }
#pragma unroll
        for (int c = 0; c < 4; c++) {
            int kk = c * 16;
#pragma unroll
            for (int tp = 0; tp < 4; tp++) {
                unsigned bh[4], bl[4];
                unsigned off = base + ((tp * 16 + fr) * 72 + kk + fc8) * 2;
                LDSM4(bh, off);
                LDSM4(bl, off + 9216u);
#pragma unroll
                for (int u = 0; u < 2; u++) {
                    float* c4 = S[tp * 2 + u];
                    MMA_BF16v(c4, qh[c], bh[u], bh[u + 2]);
                    MMA_BF16v(c4, qh[c], bl[u], bl[u + 2]);
                    MMA_BF16v(c4, ql[c], bh[u], bh[u + 2]);
                }
            }
        }

        float rm0 = -1e30f, rm1 = -1e30f;
#pragma unroll
        for (int t = 0; t < 8; t++) {
            rm0 = fmaxf(rm0, fmaxf(S[t][0], S[t][1]));
            rm1 = fmaxf(rm1, fmaxf(S[t][2], S[t][3]));
        }
        rm0 = fmaxf(rm0, __shfl_xor_sync(0xffffffffu, rm0, 1));
        rm0 = fmaxf(rm0, __shfl_xor_sync(0xffffffffu, rm0, 2));
        rm1 = fmaxf(rm1, __shfl_xor_sync(0xffffffffu, rm1, 1));
        rm1 = fmaxf(rm1, __shfl_xor_sync(0xffffffffu, rm1, 2));
        float mn0 = fmaxf(m0, rm0), mn1 = fmaxf(m1, rm1);
        float c0 = __expf(m0 - mn0), c1 = __expf(m1 - mn1);
        m0 = mn0; m1 = mn1;
        float ps0 = 0.f, ps1 = 0.f;
#pragma unroll
        for (int t = 0; t < 8; t++) {
            S[t][0] = __expf(S[t][0] - mn0);
            S[t][1] = __expf(S[t][1] - mn0);
            S[t][2] = __expf(S[t][2] - mn1);
            S[t][3] = __expf(S[t][3] - mn1);
            ps0 += S[t][0] + S[t][1];
            ps1 += S[t][2] + S[t][3];
        }
        ps0 += __shfl_xor_sync(0xffffffffu, ps0, 1);
        ps0 += __shfl_xor_sync(0xffffffffu, ps0, 2);
        ps1 += __shfl_xor_sync(0xffffffffu, ps1, 1);
        ps1 += __shfl_xor_sync(0xffffffffu, ps1, 2);
        l0 = l0 * c0 + ps0;
        l1 = l1 * c1 + ps1;
#pragma unroll
        for (int t = 0; t < 8; t++) {
            O[t][0] *= c0; O[t][1] *= c0; O[t][2] *= c1; O[t][3] *= c1;
        }

        unsigned ph[4][4], pl[4][4];
#pragma unroll
        for (int c = 0; c < 4; c++) {
            int t0 = 2 * c, t1 = 2 * c + 1;
            ph[c][0] = pk2(S[t0][0], S[t0][1]);
            ph[c][1] = pk2(S[t0][2], S[t0][3]);
            ph[c][2] = pk2(S[t1][0], S[t1][1]);
            ph[c][3] = pk2(S[t1][2], S[t1][3]);
            pl[c][0] = pk2(lores(S[t0][0]), lores(S[t0][1]));
            pl[c][1] = pk2(lores(S[t0][2]), lores(S[t0][3]));
            pl[c][2] = pk2(lores(S[t1][0]), lores(S[t1][1]));
            pl[c][3] = pk2(lores(S[t1][2]), lores(S[t1][3]));
        }

#pragma unroll
        for (int c = 0; c < 4; c++) {
#pragma unroll
            for (int tp = 0; tp < 4; tp++) {
                unsigned bh[4], bl[4];
                unsigned off = base + 18432u
                    + ((c * 16 + vr) * 72 + tp * 16 + vc8) * 2;
                LDSM4T(bh, off);
                LDSM4T(bl, off + 9216u);
#pragma unroll
                for (int u = 0; u < 2; u++) {
                    float* c4 = O[tp * 2 + u];
                    MMA_BF16v(c4, ph[c], bh[u], bh[u + 2]);
                    MMA_BF16v(c4, ph[c], bl[u], bl[u + 2]);
                    MMA_BF16v(c4, pl[c], bh[u], bh[u + 2]);
                }
            }
        }
        __syncthreads();
        if (kb + 2 < 16) issue_kv(kb + 2, kb & 1);
    }

    float inv0 = 1.f / l0, inv1 = 1.f / l1;
#pragma unroll
    for (int t = 0; t < 8; t++) {
        int col = h * 64 + 8 * t + 2 * tg;
        size_t o0 = (size_t)qrow * 1024 + col;
        size_t o1 = o0 + 8 * 1024;
        float2 gg0 = *(const float2*)(g_g + o0);
        float2 gg1 = *(const float2*)(g_g + o1);
        float v0 = O[t][0] * inv0 * gg0.x;
        float v1 = O[t][1] * inv0 * gg0.y;
        float v2 = O[t][2] * inv1 * gg1.x;
        float v3 = O[t][3] * inv1 * gg1.y;
        *(unsigned*)(g_ohi + o0) = pk2(v0, v1);
        *(unsigned*)(g_ohi + o1) = pk2(v2, v3);
        *(unsigned*)(g_olo + o0) = pk2(lores(v0), lores(v1));
        *(unsigned*)(g_olo + o1) = pk2(lores(v2), lores(v3));
    }
}

// ---------------------------------------------------------------------------
extern "C" void kernel_launch(void* const* d_in, const int* in_sizes, int n_in,
                              void* d_out, int out_size)
{
    const float* single = (const float*)d_in[0];
    const float* pw     = (const float*)d_in[1];
    const float* gamma  = (const float*)d_in[2];
    const float* beta   = (const float*)d_in[3];
    const float* Wb     = (const float*)d_in[4];
    const float* Wq     = (const float*)d_in[5];
    const float* Wk     = (const float*)d_in[6];
    const float* Wv     = (const float*)d_in[7];
    const float* Wg     = (const float*)d_in[8];
    const float* bg     = (const float*)d_in[9];
    const float* Wo     = (const float*)d_in[10];
    float* out = (float*)d_out;

    const int QKVG_SMEM = 2 * 54272;   // 108544
    const int OUT_SMEM  = 2 * 29696;   // 59392
    const int ATTN_SMEM = 73728;
    cudaFuncSetAttribute(gemm_qkvg,
        cudaFuncAttributeMaxDynamicSharedMemorySize, QKVG_SMEM);
    cudaFuncSetAttribute(gemm_out,
        cudaFuncAttributeMaxDynamicSharedMemorySize, OUT_SMEM);
    cudaFuncSetAttribute(attn_kernel,
        cudaFuncAttributeMaxDynamicSharedMemorySize, ATTN_SMEM);

    bias_setup<<<1, 128>>>(gamma, beta, Wb);
    dim3 bgrid(16, 1024);
    bias_kernel<<<bgrid, 256>>>(pw);

    dim3 cgrid(1024, 6);
    conv_all<<<cgrid, 256>>>(single, Wq, Wk, Wv, Wg, Wo);

    dim3 ggrid(4, 8, 4);   // (n-tile 256, m-tile 128, widx) = 128 CTAs
    gemm_qkvg<<<ggrid, 512, QKVG_SMEM>>>(bg);

    dim3 agrid(8, 16);
    attn_kernel<<<agrid, 256, ATTN_SMEM>>>();

    dim3 ogrid(16, 8);     // 128 CTAs
    gemm_out<<<ogrid, 256, OUT_SMEM>>>(out);
}

// round 10
// speedup vs baseline: 3.2523x; 1.0012x over previous
#include <cuda_runtime.h>
#include <cuda_bf16.h>
#include <cstdint>

#define NN (1024u*1024u)

// scratch (device globals: allocation-free)
__device__ float g_bias[16u*1024u*1024u]; // [h][i][j]
__device__ float g_g [NN];                // gates fp32 [token][dim_inner]
__device__ __nv_bfloat16 g_shi[NN], g_slo[NN];      // single_repr hi/lo [m][k]
__device__ __nv_bfloat16 g_wh[5][NN], g_wl[5][NN];  // W [k][n] hi/lo (natural)
__device__ __nv_bfloat16 g_ohi[NN], g_olo[NN];      // gated attn out hi/lo
__device__ __nv_bfloat16 g_qh[NN], g_ql[NN];        // Q [tok][d_inner] *0.125
__device__ __nv_bfloat16 g_kh[NN], g_kl[NN];        // K [tok][d_inner]
__device__ __nv_bfloat16 g_vh[NN], g_vl[NN];        // V [tok][d_inner]
__device__ __nv_bfloat16 g_wbth[16*128], g_wbtl[16*128]; // (gamma*Wb)^T [h][p]
__device__ float g_binit[16];                            // beta @ Wb

__device__ __forceinline__ unsigned pk2(float a, float b) {
    __nv_bfloat162 t = __floats2bfloat162_rn(a, b);
    return *reinterpret_cast<unsigned*>(&t);
}
__device__ __forceinline__ float lores(float a) {
    return a - __bfloat162float(__float2bfloat16(a));
}
__device__ __forceinline__ unsigned cvta_s(const void* p) {
    return (unsigned)__cvta_generic_to_shared(p);
}

#define MMA_BF16v(c, a, b0, b1) asm volatile( \
    "mma.sync.aligned.m16n8k16.row.col.f32.bf16.bf16.f32 " \
    "{%0,%1,%2,%3},{%4,%5,%6,%7},{%8,%9},{%0,%1,%2,%3};" \
    : "+f"((c)[0]), "+f"((c)[1]), "+f"((c)[2]), "+f"((c)[3]) \
    : "r"((a)[0]), "r"((a)[1]), "r"((a)[2]), "r"((a)[3]), \
      "r"(b0), "r"(b1))
#define LDSM4(R, addr) asm volatile( \
    "ldmatrix.sync.aligned.m8n8.x4.shared.b16 {%0,%1,%2,%3}, [%4];" \
    : "=r"((R)[0]), "=r"((R)[1]), "=r"((R)[2]), "=r"((R)[3]) : "r"(addr))
#define LDSM4T(R, addr) asm volatile( \
    "ldmatrix.sync.aligned.m8n8.x4.trans.shared.b16 {%0,%1,%2,%3}, [%4];" \
    : "=r"((R)[0]), "=r"((R)[1]), "=r"((R)[2]), "=r"((R)[3]) : "r"(addr))
#define CP_ASYNC16(dst, src) asm volatile( \
    "cp.async.cg.shared.global [%0], [%1], 16;" :: "r"(dst), "l"(src) : "memory")
#define CP_COMMIT() asm volatile("cp.async.commit_group;" ::: "memory")
#define CP_WAIT1()  asm volatile("cp.async.wait_group 1;" ::: "memory")
#define CP_WAIT0()  asm volatile("cp.async.wait_group 0;" ::: "memory")

// ---------------------------------------------------------------------------
// One-time prep: (gamma*W_bias)^T as bf16 hi/lo, and beta@W_bias.
// ---------------------------------------------------------------------------
__global__ void bias_setup(const float* __restrict__ gamma,
                           const float* __restrict__ beta,
                           const float* __restrict__ Wb)
{
    int tid = threadIdx.x;
    for (int idx = tid; idx < 2048; idx += 128) {
        int p = idx >> 4, h = idx & 15;
        float w = gamma[p] * Wb[idx];
        __nv_bfloat16 hi = __float2bfloat16(w);
        g_wbth[h * 128 + p] = hi;
        g_wbtl[h * 128 + p] = __float2bfloat16(w - __bfloat162float(hi));
    }
    if (tid < 16) {
        float s = 0.f;
        for (int p = 0; p < 128; p++) s += beta[p] * Wb[p * 16 + tid];
        g_binit[tid] = s;
    }
}

// ---------------------------------------------------------------------------
// Bias kernel: LN (SIMT fp32 stats) + 128->16 projection on tensor cores.
// ---------------------------------------------------------------------------
__global__ __launch_bounds__(256) void bias_kernel(const float* __restrict__ pw)
{
    __shared__ __nv_bfloat16 sXh[64][136], sXl[64][136];
    __shared__ __nv_bfloat16 sWh[16][136], sWl[16][136];
    __shared__ float stage[16][64];
    __shared__ float sbin[16];

    int tid  = threadIdx.x;
    int lane = tid & 31, warp = tid >> 5;
    int i  = blockIdx.y;
    int j0 = blockIdx.x * 64;

    const float4* rowp = (const float4*)(pw
        + ((size_t)i * 1024 + j0 + warp * 8) * 128) + lane;
    float4 x[8];
#pragma unroll
    for (int rr = 0; rr < 8; rr++) x[rr] = rowp[rr * 32];

    for (int idx = tid; idx < 2048; idx += 256) {
        int h = idx >> 7, p = idx & 127;
        sWh[h][p] = g_wbth[idx];
        sWl[h][p] = g_wbtl[idx];
    }
    if (tid < 16) sbin[tid] = g_binit[tid];

#pragma unroll
    for (int rr = 0; rr < 8; rr++) {
        float s  = x[rr].x + x[rr].y + x[rr].z + x[rr].w;
        float ss = x[rr].x*x[rr].x + x[rr].y*x[rr].y
                 + x[rr].z*x[rr].z + x[rr].w*x[rr].w;
#pragma unroll
        for (int off = 16; off >= 1; off >>= 1) {
            s  += __shfl_xor_sync(0xffffffffu, s,  off);
            ss += __shfl_xor_sync(0xffffffffu, ss, off);
        }
        float mu  = s * 0.0078125f;
        float var = ss * 0.0078125f - mu * mu;
        float rs  = rsqrtf(var + 1e-5f);
        float y0 = (x[rr].x - mu) * rs, y1 = (x[rr].y - mu) * rs;
        float y2 = (x[rr].z - mu) * rs, y3 = (x[rr].w - mu) * rs;
        int r = warp * 8 + rr;
        *(uint2*)&sXh[r][lane * 4] = make_uint2(pk2(y0, y1), pk2(y2, y3));
        *(uint2*)&sXl[r][lane * 4] =
            make_uint2(pk2(lores(y0), lores(y1)), pk2(lores(y2), lores(y3)));
    }
    __syncthreads();

    if (warp < 4) {
        int gid  = lane >> 2, tg = lane & 3;
        float acc[2][4] = {};
        int warp_m = warp * 16;
        unsigned aXh = cvta_s(sXh), aXl = cvta_s(sXl);
        unsigned aWh = cvta_s(sWh), aWl = cvta_s(sWl);
        int fr = lane & 15, fc = lane >> 4;
#pragma unroll
        for (int c = 0; c < 8; c++) {
            int kk = c * 16;
            unsigned ah[4], al[4], bh[4], bl[4];
            LDSM4(ah, aXh + ((warp_m + fr) * 136 + kk + fc * 8) * 2);
            LDSM4(al, aXl + ((warp_m + fr) * 136 + kk + fc * 8) * 2);
            LDSM4(bh, aWh + ((fr) * 136 + kk + fc * 8) * 2);
            LDSM4(bl, aWl + ((fr) * 136 + kk + fc * 8) * 2);
#pragma unroll
            for (int t = 0; t < 2; t++) {
                MMA_BF16v(acc[t], ah, bh[t], bh[t + 2]);
                MMA_BF16v(acc[t], ah, bl[t], bl[t + 2]);
                MMA_BF16v(acc[t], al, bh[t], bh[t + 2]);
            }
        }
#pragma unroll
        for (int t = 0; t < 2; t++) {
            int hc = t * 8 + tg * 2;
            int r  = warp_m + gid;
            stage[hc][r]         = acc[t][0];
            stage[hc + 1][r]     = acc[t][1];
            stage[hc][r + 8]     = acc[t][2];
            stage[hc + 1][r + 8] = acc[t][3];
        }
    }
    __syncthreads();
    size_t obase = (size_t)i * 1024 + j0;
    for (int e = tid; e < 1024; e += 256) {
        int hh = e >> 6, j = e & 63;
        g_bias[(size_t)hh * NN + obase + j] = stage[hh][j] + sbin[hh];
    }
}

// ---------------------------------------------------------------------------
// Convert single_repr + all 5 weights -> bf16 hi/lo.
// ---------------------------------------------------------------------------
__global__ __launch_bounds__(256) void conv_all(
    const float* __restrict__ s0, const float* __restrict__ s1,
    const float* __restrict__ s2, const float* __restrict__ s3,
    const float* __restrict__ s4, const float* __restrict__ s5)
{
    const float* srcs[6] = {s0, s1, s2, s3, s4, s5};
    const float* src = srcs[blockIdx.y];
    __nv_bfloat16 *Dh, *Dl;
    if (blockIdx.y == 0) { Dh = g_shi; Dl = g_slo; }
    else { Dh = g_wh[blockIdx.y - 1]; Dl = g_wl[blockIdx.y - 1]; }

    unsigned i = blockIdx.x * 256u + threadIdx.x;
    float4 v = ((const float4*)src)[i];
    *(unsigned*)(Dh + 4u*i)     = pk2(v.x, v.y);
    *(unsigned*)(Dh + 4u*i + 2) = pk2(v.z, v.w);
    *(unsigned*)(Dl + 4u*i)     = pk2(lores(v.x), lores(v.y));
    *(unsigned*)(Dl + 4u*i + 2) = pk2(lores(v.z), lores(v.w));
}

// ---------------------------------------------------------------------------
// QKVG GEMM: 512 thr, tile 128x256, BK=32, cp.async depth-3 (ONE barrier/chunk).
// Grid (4, 8, 4) = 128 CTAs = one full wave.
// smem/buf 54272 x 3 = 162816.
// ---------------------------------------------------------------------------
__global__ __launch_bounds__(512, 1) void gemm_qkvg(const float* __restrict__ aux)
{
    extern __shared__ __nv_bfloat16 dsm[];
    constexpr unsigned SZB   = 16896u;   // 32 * 264 * 2
    constexpr unsigned BUFSZ = 54272u;

    int widx = blockIdx.z;
    float scale = (widx == 0) ? 0.125f : 1.0f;
    const __nv_bfloat16* gBh = g_wh[widx];
    const __nv_bfloat16* gBl = g_wl[widx];

    int tid  = threadIdx.x;
    int lane = tid & 31, warp = tid >> 5;
    int gid  = lane >> 2, tg = lane & 3;
    int fr = lane & 15, fc8 = (lane >> 4) * 8;
    int vr = (lane >> 4) * 8 + (lane & 7);
    int vc8 = ((lane >> 3) & 1) * 8;
    int warp_m = (warp >> 2) * 32, warp_n = (warp & 3) * 64;
    int m0 = blockIdx.y * 128, n0 = blockIdx.x * 256;
    unsigned sb = cvta_s(dsm);

    int a_row = (tid & 511) >> 2, a_seg = tid & 3;
    int b_row = (tid & 1023) >> 5, b_seg = tid & 31;

    // hoisted source bases (advance by k0 per chunk)
    const __nv_bfloat16* pAh = g_shi + (size_t)(m0 + a_row) * 1024 + a_seg * 8;
    const __nv_bfloat16* pAl = g_slo + (size_t)(m0 + a_row) * 1024 + a_seg * 8;
    const __nv_bfloat16* pBh0 = gBh + (size_t)b_row * 1024 + n0 + b_seg * 8;
    const __nv_bfloat16* pBl0 = gBl + (size_t)b_row * 1024 + n0 + b_seg * 8;
    const __nv_bfloat16* pBh1 = pBh0 + 16 * 1024;
    const __nv_bfloat16* pBl1 = pBl0 + 16 * 1024;
    unsigned dA  = a_row * 80u + a_seg * 16u;
    unsigned dB0 = 20480u + b_row * 528u + b_seg * 16u;
    unsigned dB1 = 20480u + (b_row + 16) * 528u + b_seg * 16u;

    auto issue = [&](int ch, int buf) {
        unsigned k0 = ch * 32u;
        size_t kq = ch * 32u * 1024u;
        unsigned bo = sb + buf * BUFSZ;
        CP_ASYNC16(bo + dA,           pAh + k0);
        CP_ASYNC16(bo + dA + 10240u,  pAl + k0);
        CP_ASYNC16(bo + dB0,          pBh0 + kq);
        CP_ASYNC16(bo + dB0 + SZB,    pBl0 + kq);
        CP_ASYNC16(bo + dB1,          pBh1 + kq);
        CP_ASYNC16(bo + dB1 + SZB,    pBl1 + kq);
        CP_COMMIT();
    };

    float acc[2][8][4];
#pragma unroll
    for (int a = 0; a < 2; a++)
#pragma unroll
        for (int b = 0; b < 8; b++)
#pragma unroll
            for (int q = 0; q < 4; q++) acc[a][b][q] = 0.f;

    issue(0, 0);
    issue(1, 1);

    int buf = 0;
#pragma unroll 1
    for (int ch = 0; ch < 32; ch++) {
        if (ch < 31) { CP_WAIT1(); } else { CP_WAIT0(); }
        __syncthreads();
        unsigned base = sb + buf * BUFSZ;
#pragma unroll
        for (int k16 = 0; k16 < 32; k16 += 16) {
            unsigned a_h[2][4], a_l[2][4], b_h[4][4], b_l[4][4];
#pragma unroll
            for (int mt = 0; mt < 2; mt++) {
                unsigned off = base + ((warp_m + mt * 16 + fr) * 40 + k16 + fc8) * 2;
                LDSM4(a_h[mt], off);
                LDSM4(a_l[mt], off + 10240u);
            }
#pragma unroll
            for (int tp = 0; tp < 4; tp++) {
                unsigned off = base + 20480u
                    + ((k16 + vr) * 264 + warp_n + tp * 16 + vc8) * 2;
                LDSM4T(b_h[tp], off);
                LDSM4T(b_l[tp], off + SZB);
            }
#pragma unroll
            for (int mt = 0; mt < 2; mt++)
#pragma unroll
                for (int tp = 0; tp < 4; tp++)
#pragma unroll
                    for (int u = 0; u < 2; u++) {
                        float* c4 = acc[mt][tp * 2 + u];
                        MMA_BF16v(c4, a_h[mt], b_h[tp][u], b_h[tp][u + 2]);
                        MMA_BF16v(c4, a_h[mt], b_l[tp][u], b_l[tp][u + 2]);
                        MMA_BF16v(c4, a_l[mt], b_h[tp][u], b_h[tp][u + 2]);
                    }
        }
        // depth-3: buffer (ch+2)%3 was consumed at ch-1; the barrier above
        // proves all warps finished ch-1 -> safe to overwrite, no 2nd barrier.
        if (ch + 2 < 32) {
            int nb = buf + 2; if (nb >= 3) nb -= 3;
            issue(ch + 2, nb);
        }
        if (++buf == 3) buf = 0;
    }

    __nv_bfloat16* Dh = (widx == 0) ? g_qh : (widx == 1) ? g_kh : g_vh;
    __nv_bfloat16* Dl = (widx == 0) ? g_ql : (widx == 1) ? g_kl : g_vl;
#pragma unroll
    for (int mt = 0; mt < 2; mt++) {
#pragma unroll
        for (int j = 0; j < 8; j++) {
            int rg = m0 + warp_m + mt * 16 + gid;
            int cg = n0 + warp_n + j * 8 + tg * 2;
            float* a4 = acc[mt][j];
            if (widx == 3) {
                float b0 = aux[cg], b1 = aux[cg + 1];
                float v0 = 1.f / (1.f + __expf(-(a4[0] + b0)));
                float v1 = 1.f / (1.f + __expf(-(a4[1] + b1)));
                float v2 = 1.f / (1.f + __expf(-(a4[2] + b0)));
                float v3 = 1.f / (1.f + __expf(-(a4[3] + b1)));
                *(float2*)&g_g[(size_t)rg * 1024 + cg]       = make_float2(v0, v1);
                *(float2*)&g_g[(size_t)(rg + 8) * 1024 + cg] = make_float2(v2, v3);
            } else {
                float v0 = a4[0] * scale, v1 = a4[1] * scale;
                float v2 = a4[2] * scale, v3 = a4[3] * scale;
                *(unsigned*)&Dh[(size_t)rg * 1024 + cg]       = pk2(v0, v1);
                *(unsigned*)&Dh[(size_t)(rg + 8) * 1024 + cg] = pk2(v2, v3);
                *(unsigned*)&Dl[(size_t)rg * 1024 + cg]       = pk2(lores(v0), lores(v1));
                *(unsigned*)&Dl[(size_t)(rg + 8) * 1024 + cg] =
                    pk2(lores(v2), lores(v3));
            }
        }
    }
}

// ---------------------------------------------------------------------------
// Output GEMM: 256 thr, tile 128x64, BK=32, depth-3. Grid (16,8)=128.
// smem/buf 29696 x 3 = 89088.
// ---------------------------------------------------------------------------
__global__ __launch_bounds__(256) void gemm_out(float* __restrict__ Cext)
{
    extern __shared__ __nv_bfloat16 dsm[];
    constexpr unsigned SZB   = 32u * 72 * 2;          // 4608
    constexpr unsigned BUFSZ = 20480u + 2 * SZB;      // 29696

    const __nv_bfloat16* gBh = g_wh[4];
    const __nv_bfloat16* gBl = g_wl[4];

    int tid  = threadIdx.x;
    int lane = tid & 31, warp = tid >> 5;
    int gid  = lane >> 2, tg = lane & 3;
    int fr = lane & 15, fc8 = (lane >> 4) * 8;
    int vr = (lane >> 4) * 8 + (lane & 7);
    int vc8 = ((lane >> 3) & 1) * 8;
    int warp_m = (warp >> 1) * 32, warp_n = (warp & 1) * 32;
    int m0 = blockIdx.y * 128, n0 = blockIdx.x * 64;
    unsigned sb = cvta_s(dsm);

    auto issue = [&](int ch, int buf) {
        int k0 = ch * 32;
        unsigned bo = sb + buf * BUFSZ;
#pragma unroll
        for (int t = 0; t < 6; t++) {
            int s = tid + t * 256;
            unsigned dst;
            const __nv_bfloat16* src;
            if (s < 1024) {
                int mt = s >> 9, rem = s & 511;
                int row = rem >> 2, seg = rem & 3;
                dst = bo + mt * 10240u + row * 80u + seg * 16u;
                src = (mt ? g_olo : g_ohi) + (size_t)(m0 + row) * 1024 + k0 + seg * 8;
            } else {
                int ss = s - 1024;
                int mt = ss >> 8, rem = ss & 255;
                int row = rem >> 3, seg = rem & 7;
                dst = bo + 20480u + mt * SZB + row * 144u + seg * 16u;
                src = (mt ? gBl : gBh) + (size_t)(k0 + row) * 1024 + n0 + seg * 8;
            }
            CP_ASYNC16(dst, src);
        }
        CP_COMMIT();
    };

    float acc[2][4][4];
#pragma unroll
    for (int a = 0; a < 2; a++)
#pragma unroll
        for (int b = 0; b < 4; b++)
#pragma unroll
            for (int q = 0; q < 4; q++) acc[a][b][q] = 0.f;

    issue(0, 0);
    issue(1, 1);

    int buf = 0;
#pragma unroll 1
    for (int ch = 0; ch < 32; ch++) {
        if (ch < 31) { CP_WAIT1(); } else { CP_WAIT0(); }
        __syncthreads();
        unsigned base = sb + buf * BUFSZ;
#pragma unroll
        for (int k16 = 0; k16 < 32; k16 += 16) {
            unsigned a_h[2][4], a_l[2][4], b_h[2][4], b_l[2][4];
#pragma unroll
            for (int mt = 0; mt < 2; mt++) {
                unsigned off = base + ((warp_m + mt * 16 + fr) * 40 + k16 + fc8) * 2;
                LDSM4(a_h[mt], off);
                LDSM4(a_l[mt], off + 10240u);
            }
#pragma unroll
            for (int tp = 0; tp < 2; tp++) {
                unsigned off = base + 20480u
                    + ((k16 + vr) * 72 + warp_n + tp * 16 + vc8) * 2;
                LDSM4T(b_h[tp], off);
                LDSM4T(b_l[tp], off + SZB);
            }
#pragma unroll
            for (int mt = 0; mt < 2; mt++)
#pragma unroll
                for (int tp = 0; tp < 2; tp++)
#pragma unroll
                    for (int u = 0; u < 2; u++) {
                        float* c4 = acc[mt][tp * 2 + u];
                        MMA_BF16v(c4, a_h[mt], b_h[tp][u], b_h[tp][u + 2]);
                        MMA_BF16v(c4, a_h[mt], b_l[tp][u], b_l[tp][u + 2]);
                        MMA_BF16v(c4, a_l[mt], b_h[tp][u], b_h[tp][u + 2]);
                    }
        }
        if (ch + 2 < 32) {
            int nb = buf + 2; if (nb >= 3) nb -= 3;
            issue(ch + 2, nb);
        }
        if (++buf == 3) buf = 0;
    }

#pragma unroll
    for (int mt = 0; mt < 2; mt++) {
#pragma unroll
        for (int j = 0; j < 4; j++) {
            int rg = m0 + warp_m + mt * 16 + gid;
            int cg = n0 + warp_n + j * 8 + tg * 2;
            float* a4 = acc[mt][j];
            *(float2*)&Cext[(size_t)rg * 1024 + cg]       = make_float2(a4[0], a4[1]);
            *(float2*)&Cext[(size_t)(rg + 8) * 1024 + cg] = make_float2(a4[2], a4[3]);
        }
    }
}

// ---------------------------------------------------------------------------
// Flash attention, mma.sync + ldmatrix, cp.async depth-3 K/V pipeline
// (one barrier per k-block). 256 thr, 128 queries/CTA. Grid (8, 16).
// smem/buf 36864 x 3 = 110592.
// ---------------------------------------------------------------------------
__global__ __launch_bounds__(256) void attn_kernel()
{
    extern __shared__ __nv_bfloat16 dsm[];
    int tid  = threadIdx.x;
    int lane = tid & 31, warp = tid >> 5;
    int gid  = lane >> 2, tg = lane & 3;
    int h  = blockIdx.y;
    int q0 = blockIdx.x * 128;
    int warp_m = warp * 16;
    int qrow = q0 + warp_m + gid;
    unsigned sb = cvta_s(dsm);

    int fr = lane & 15, fc8 = (lane >> 4) * 8;
    int vr = (lane >> 4) * 8 + (lane & 7);
    int vc8 = ((lane >> 3) & 1) * 8;

    auto issue_kv = [&](int kb, int buf) {
        int k0 = kb * 64;
        unsigned bo = buf * 36864u;
#pragma unroll
        for (int t = 0; t < 8; t++) {
            int s = tid + t * 256;
            int mt = s >> 9, rem = s & 511;
            int row = rem >> 3, seg = rem & 7;
            unsigned dst = sb + bo + mt * 9216u + row * 144u + seg * 16u;
            const __nv_bfloat16* src;
            if      (mt == 0) src = g_kh + (size_t)(k0 + row) * 1024 + h * 64 + seg * 8;
            else if (mt == 1) src = g_kl + (size_t)(k0 + row) * 1024 + h * 64 + seg * 8;
            else if (mt == 2) src = g_vh + (size_t)(k0 + row) * 1024 + h * 64 + seg * 8;
            else              src = g_vl + (size_t)(k0 + row) * 1024 + h * 64 + seg * 8;
            CP_ASYNC16(dst, src);
        }
        CP_COMMIT();
    };

    unsigned qh[4][4], ql[4][4];
    {
        const __nv_bfloat16* Qh = g_qh + (size_t)qrow * 1024 + h * 64;
        const __nv_bfloat16* Ql = g_ql + (size_t)qrow * 1024 + h * 64;
#pragma unroll
        for (int c = 0; c < 4; c++) {
            int kk = c * 16 + tg * 2;
            qh[c][0] = *(const unsigned*)(Qh + kk);
            qh[c][1] = *(const unsigned*)(Qh + 8 * 1024 + kk);
            qh[c][2] = *(const unsigned*)(Qh + kk + 8);
            qh[c][3] = *(const unsigned*)(Qh + 8 * 1024 + kk + 8);
            ql[c][0] = *(const unsigned*)(Ql + kk);
            ql[c][1] = *(const unsigned*)(Ql + 8 * 1024 + kk);
            ql[c][2] = *(const unsigned*)(Ql + kk + 8);
            ql[c][3] = *(const unsigned*)(Ql + 8 * 1024 + kk + 8);
        }
    }

    float m0 = -1e30f, m1 = -1e30f, l0 = 0.f, l1 = 0.f;
    float O[8][4] = {};

    issue_kv(0, 0);
    issue_kv(1, 1);

    int buf = 0;
#pragma unroll 1
    for (int kb = 0; kb < 16; kb++) {
        if (kb < 15) { CP_WAIT1(); } else { CP_WAIT0(); }
        __syncthreads();
        unsigned base = sb + buf * 36864u;
        int k0 = kb * 64;

        float S[8][4];
        {
            const float* bptr = g_bias + (size_t)h * NN + (size_t)qrow * 1024 + k0;
#pragma unroll
            for (int t = 0; t < 8; t++) {
                float2 b0 = *(const float2*)(bptr + 8 * t + 2 * tg);
                float2 b1 = *(const float2*)(bptr + 8 * 1024 + 8 * t + 2 * tg);
                S[t][0] = b0.x; S[t][1] = b0.y; S[t][2] = b1.x; S[t][3] = b1.y;
            }
        }
#pragma unroll
        for (int c = 0; c < 4; c++) {
            int kk = c * 16;
#pragma unroll
            for (int tp = 0; tp < 4; tp++) {
                unsigned bh[4], bl[4];
                unsigned off = base + ((tp * 16 + fr) * 72 + kk + fc8) * 2;
                LDSM4(bh, off);
                LDSM4(bl, off + 9216u);
#pragma unroll
                for (int u = 0; u < 2; u++) {
                    float* c4 = S[tp * 2 + u];
                    MMA_BF16v(c4, qh[c], bh[u], bh[u + 2]);
                    MMA_BF16v(c4, qh[c], bl[u], bl[u + 2]);
                    MMA_BF16v(c4, ql[c], bh[u], bh[u + 2]);
                }
            }
        }

        float rm0 = -1e30f, rm1 = -1e30f;
#pragma unroll
        for (int t = 0; t < 8; t++) {
            rm0 = fmaxf(rm0, fmaxf(S[t][0], S[t][1]));
            rm1 = fmaxf(rm1, fmaxf(S[t][2], S[t][3]));
        }
        rm0 = fmaxf(rm0, __shfl_xor_sync(0xffffffffu, rm0, 1));
        rm0 = fmaxf(rm0, __shfl_xor_sync(0xffffffffu, rm0, 2));
        rm1 = fmaxf(rm1, __shfl_xor_sync(0xffffffffu, rm1, 1));
        rm1 = fmaxf(rm1, __shfl_xor_sync(0xffffffffu, rm1, 2));
        float mn0 = fmaxf(m0, rm0), mn1 = fmaxf(m1, rm1);
        float c0 = __expf(m0 - mn0), c1 = __expf(m1 - mn1);
        m0 = mn0; m1 = mn1;
        float ps0 = 0.f, ps1 = 0.f;
#pragma unroll
        for (int t = 0; t < 8; t++) {
            S[t][0] = __expf(S[t][0] - mn0);
            S[t][1] = __expf(S[t][1] - mn0);
            S[t][2] = __expf(S[t][2] - mn1);
            S[t][3] = __expf(S[t][3] - mn1);
            ps0 += S[t][0] + S[t][1];
            ps1 += S[t][2] + S[t][3];
        }
        ps0 += __shfl_xor_sync(0xffffffffu, ps0, 1);
        ps0 += __shfl_xor_sync(0xffffffffu, ps0, 2);
        ps1 += __shfl_xor_sync(0xffffffffu, ps1, 1);
        ps1 += __shfl_xor_sync(0xffffffffu, ps1, 2);
        l0 = l0 * c0 + ps0;
        l1 = l1 * c1 + ps1;
#pragma unroll
        for (int t = 0; t < 8; t++) {
            O[t][0] *= c0; O[t][1] *= c0; O[t][2] *= c1; O[t][3] *= c1;
        }

        unsigned ph[4][4], pl[4][4];
#pragma unroll
        for (int c = 0; c < 4; c++) {
            int t0 = 2 * c, t1 = 2 * c + 1;
            ph[c][0] = pk2(S[t0][0], S[t0][1]);
            ph[c][1] = pk2(S[t0][2], S[t0][3]);
            ph[c][2] = pk2(S[t1][0], S[t1][1]);
            ph[c][3] = pk2(S[t1][2], S[t1][3]);
            pl[c][0] = pk2(lores(S[t0][0]), lores(S[t0][1]));
            pl[c][1] = pk2(lores(S[t0][2]), lores(S[t0][3]));
            pl[c][2] = pk2(lores(S[t1][0]), lores(S[t1][1]));
            pl[c][3] = pk2(lores(S[t1][2]), lores(S[t1][3]));
        }

#pragma unroll
        for (int c = 0; c < 4; c++) {
#pragma unroll
            for (int tp = 0; tp < 4; tp++) {
                unsigned bh[4], bl[4];
                unsigned off = base + 18432u
                    + ((c * 16 + vr) * 72 + tp * 16 + vc8) * 2;
                LDSM4T(bh, off);
                LDSM4T(bl, off + 9216u);
#pragma unroll
                for (int u = 0; u < 2; u++) {
                    float* c4 = O[tp * 2 + u];
                    MMA_BF16v(c4, ph[c], bh[u], bh[u + 2]);
                    MMA_BF16v(c4, ph[c], bl[u], bl[u + 2]);
                    MMA_BF16v(c4, pl[c], bh[u], bh[u + 2]);
                }
            }
        }
        // depth-3: buffer (kb+2)%3 was consumed at kb-1; barrier above proves
        // all warps finished kb-1 -> safe to overwrite, no 2nd barrier.
        if (kb + 2 < 16) {
            int nb = buf + 2; if (nb >= 3) nb -= 3;
            issue_kv(kb + 2, nb);
        }
        if (++buf == 3) buf = 0;
    }

    float inv0 = 1.f / l0, inv1 = 1.f / l1;
#pragma unroll
    for (int t = 0; t < 8; t++) {
        int col = h * 64 + 8 * t + 2 * tg;
        size_t o0 = (size_t)qrow * 1024 + col;
        size_t o1 = o0 + 8 * 1024;
        float2 gg0 = *(const float2*)(g_g + o0);
        float2 gg1 = *(const float2*)(g_g + o1);
        float v0 = O[t][0] * inv0 * gg0.x;
        float v1 = O[t][1] * inv0 * gg0.y;
        float v2 = O[t][2] * inv1 * gg1.x;
        float v3 = O[t][3] * inv1 * gg1.y;
        *(unsigned*)(g_ohi + o0) = pk2(v0, v1);
        *(unsigned*)(g_ohi + o1) = pk2(v2, v3);
        *(unsigned*)(g_olo + o0) = pk2(lores(v0), lores(v1));
        *(unsigned*)(g_olo + o1) = pk2(lores(v2), lores(v3));
    }
}

// ---------------------------------------------------------------------------
extern "C" void kernel_launch(void* const* d_in, const int* in_sizes, int n_in,
                              void* d_out, int out_size)
{
    const float* single = (const float*)d_in[0];
    const float* pw     = (const float*)d_in[1];
    const float* gamma  = (const float*)d_in[2];
    const float* beta   = (const float*)d_in[3];
    const float* Wb     = (const float*)d_in[4];
    const float* Wq     = (const float*)d_in[5];
    const float* Wk     = (const float*)d_in[6];
    const float* Wv     = (const float*)d_in[7];
    const float* Wg     = (const float*)d_in[8];
    const float* bg     = (const float*)d_in[9];
    const float* Wo     = (const float*)d_in[10];
    float* out = (float*)d_out;

    const int QKVG_SMEM = 3 * 54272;   // 162816
    const int OUT_SMEM  = 3 * 29696;   // 89088
    const int ATTN_SMEM = 3 * 36864;   // 110592
    cudaFuncSetAttribute(gemm_qkvg,
        cudaFuncAttributeMaxDynamicSharedMemorySize, QKVG_SMEM);
    cudaFuncSetAttribute(gemm_out,
        cudaFuncAttributeMaxDynamicSharedMemorySize, OUT_SMEM);
    cudaFuncSetAttribute(attn_kernel,
        cudaFuncAttributeMaxDynamicSharedMemorySize, ATTN_SMEM);

    bias_setup<<<1, 128>>>(gamma, beta, Wb);
    dim3 bgrid(16, 1024);
    bias_kernel<<<bgrid, 256>>>(pw);

    dim3 cgrid(1024, 6);
    conv_all<<<cgrid, 256>>>(single, Wq, Wk, Wv, Wg, Wo);

    dim3 ggrid(4, 8, 4);   // 128 CTAs
    gemm_qkvg<<<ggrid, 512, QKVG_SMEM>>>(bg);

    dim3 agrid(8, 16);
    attn_kernel<<<agrid, 256, ATTN_SMEM>>>();

    dim3 ogrid(16, 8);     // 128 CTAs
    gemm_out<<<ogrid, 256, OUT_SMEM>>>(out);
}

// round 11
// speedup vs baseline: 3.3744x; 1.0375x over previous
#include <cuda_runtime.h>
#include <cuda_bf16.h>
#include <cstdint>

#define NN (1024u*1024u)

// scratch (device globals: allocation-free)
__device__ float g_bias[16u*1024u*1024u]; // [h][i][j]
__device__ float g_g [NN];                // gates fp32 [token][dim_inner]
__device__ __nv_bfloat16 g_shi[NN], g_slo[NN];      // single_repr hi/lo [m][k]
__device__ __nv_bfloat16 g_wh[5][NN], g_wl[5][NN];  // W [k][n] hi/lo (natural)
__device__ __nv_bfloat16 g_ohi[NN], g_olo[NN];      // gated attn out hi/lo
__device__ __nv_bfloat16 g_qh[NN], g_ql[NN];        // Q [tok][d_inner] *0.125
__device__ __nv_bfloat16 g_kh[NN], g_kl[NN];        // K [tok][d_inner]
__device__ __nv_bfloat16 g_vh[NN], g_vl[NN];        // V [tok][d_inner]
__device__ __nv_bfloat16 g_wbth[16*128], g_wbtl[16*128]; // (gamma*Wb)^T [h][p]
__device__ float g_binit[16];                            // beta @ Wb

__device__ __forceinline__ unsigned pk2(float a, float b) {
    __nv_bfloat162 t = __floats2bfloat162_rn(a, b);
    return *reinterpret_cast<unsigned*>(&t);
}
__device__ __forceinline__ float lores(float a) {
    return a - __bfloat162float(__float2bfloat16(a));
}
__device__ __forceinline__ unsigned cvta_s(const void* p) {
    return (unsigned)__cvta_generic_to_shared(p);
}

#define MMA_BF16v(c, a, b0, b1) asm volatile( \
    "mma.sync.aligned.m16n8k16.row.col.f32.bf16.bf16.f32 " \
    "{%0,%1,%2,%3},{%4,%5,%6,%7},{%8,%9},{%0,%1,%2,%3};" \
    : "+f"((c)[0]), "+f"((c)[1]), "+f"((c)[2]), "+f"((c)[3]) \
    : "r"((a)[0]), "r"((a)[1]), "r"((a)[2]), "r"((a)[3]), \
      "r"(b0), "r"(b1))
#define LDSM4(R, addr) asm volatile( \
    "ldmatrix.sync.aligned.m8n8.x4.shared.b16 {%0,%1,%2,%3}, [%4];" \
    : "=r"((R)[0]), "=r"((R)[1]), "=r"((R)[2]), "=r"((R)[3]) : "r"(addr))
#define LDSM4T(R, addr) asm volatile( \
    "ldmatrix.sync.aligned.m8n8.x4.trans.shared.b16 {%0,%1,%2,%3}, [%4];" \
    : "=r"((R)[0]), "=r"((R)[1]), "=r"((R)[2]), "=r"((R)[3]) : "r"(addr))
#define CP_ASYNC16(dst, src) asm volatile( \
    "cp.async.cg.shared.global [%0], [%1], 16;" :: "r"(dst), "l"(src) : "memory")
#define CP_COMMIT() asm volatile("cp.async.commit_group;" ::: "memory")
#define CP_WAIT1()  asm volatile("cp.async.wait_group 1;" ::: "memory")
#define CP_WAIT0()  asm volatile("cp.async.wait_group 0;" ::: "memory")

// ---------------------------------------------------------------------------
// One-time prep: (gamma*W_bias)^T as bf16 hi/lo, and beta@W_bias.
// ---------------------------------------------------------------------------
__global__ void bias_setup(const float* __restrict__ gamma,
                           const float* __restrict__ beta,
                           const float* __restrict__ Wb)
{
    int tid = threadIdx.x;
    for (int idx = tid; idx < 2048; idx += 128) {
        int p = idx >> 4, h = idx & 15;
        float w = gamma[p] * Wb[idx];
        __nv_bfloat16 hi = __float2bfloat16(w);
        g_wbth[h * 128 + p] = hi;
        g_wbtl[h * 128 + p] = __float2bfloat16(w - __bfloat162float(hi));
    }
    if (tid < 16) {
        float s = 0.f;
        for (int p = 0; p < 128; p++) s += beta[p] * Wb[p * 16 + tid];
        g_binit[tid] = s;
    }
}

// ---------------------------------------------------------------------------
// Bias kernel: LN (SIMT fp32 stats) + 128->16 projection on tensor cores.
// ---------------------------------------------------------------------------
__global__ __launch_bounds__(256) void bias_kernel(const float* __restrict__ pw)
{
    __shared__ __nv_bfloat16 sXh[64][136], sXl[64][136];
    __shared__ __nv_bfloat16 sWh[16][136], sWl[16][136];
    __shared__ float stage[16][64];
    __shared__ float sbin[16];

    int tid  = threadIdx.x;
    int lane = tid & 31, warp = tid >> 5;
    int i  = blockIdx.y;
    int j0 = blockIdx.x * 64;

    const float4* rowp = (const float4*)(pw
        + ((size_t)i * 1024 + j0 + warp * 8) * 128) + lane;
    float4 x[8];
#pragma unroll
    for (int rr = 0; rr < 8; rr++) x[rr] = rowp[rr * 32];

    for (int idx = tid; idx < 2048; idx += 256) {
        int h = idx >> 7, p = idx & 127;
        sWh[h][p] = g_wbth[idx];
        sWl[h][p] = g_wbtl[idx];
    }
    if (tid < 16) sbin[tid] = g_binit[tid];

#pragma unroll
    for (int rr = 0; rr < 8; rr++) {
        float s  = x[rr].x + x[rr].y + x[rr].z + x[rr].w;
        float ss = x[rr].x*x[rr].x + x[rr].y*x[rr].y
                 + x[rr].z*x[rr].z + x[rr].w*x[rr].w;
#pragma unroll
        for (int off = 16; off >= 1; off >>= 1) {
            s  += __shfl_xor_sync(0xffffffffu, s,  off);
            ss += __shfl_xor_sync(0xffffffffu, ss, off);
        }
        float mu  = s * 0.0078125f;
        float var = ss * 0.0078125f - mu * mu;
        float rs  = rsqrtf(var + 1e-5f);
        float y0 = (x[rr].x - mu) * rs, y1 = (x[rr].y - mu) * rs;
        float y2 = (x[rr].z - mu) * rs, y3 = (x[rr].w - mu) * rs;
        int r = warp * 8 + rr;
        *(uint2*)&sXh[r][lane * 4] = make_uint2(pk2(y0, y1), pk2(y2, y3));
        *(uint2*)&sXl[r][lane * 4] =
            make_uint2(pk2(lores(y0), lores(y1)), pk2(lores(y2), lores(y3)));
    }
    __syncthreads();

    if (warp < 4) {
        int gid  = lane >> 2, tg = lane & 3;
        float acc[2][4] = {};
        int warp_m = warp * 16;
        unsigned aXh = cvta_s(sXh), aXl = cvta_s(sXl);
        unsigned aWh = cvta_s(sWh), aWl = cvta_s(sWl);
        int fr = lane & 15, fc = lane >> 4;
#pragma unroll
        for (int c = 0; c < 8; c++) {
            int kk = c * 16;
            unsigned ah[4], al[4], bh[4], bl[4];
            LDSM4(ah, aXh + ((warp_m + fr) * 136 + kk + fc * 8) * 2);
            LDSM4(al, aXl + ((warp_m + fr) * 136 + kk + fc * 8) * 2);
            LDSM4(bh, aWh + ((fr) * 136 + kk + fc * 8) * 2);
            LDSM4(bl, aWl + ((fr) * 136 + kk + fc * 8) * 2);
            // pass-major: per-acc sequence unchanged (hh -> hl -> lh)
#pragma unroll
            for (int t = 0; t < 2; t++)
                MMA_BF16v(acc[t], ah, bh[t], bh[t + 2]);
#pragma unroll
            for (int t = 0; t < 2; t++)
                MMA_BF16v(acc[t], ah, bl[t], bl[t + 2]);
#pragma unroll
            for (int t = 0; t < 2; t++)
                MMA_BF16v(acc[t], al, bh[t], bh[t + 2]);
        }
#pragma unroll
        for (int t = 0; t < 2; t++) {
            int hc = t * 8 + tg * 2;
            int r  = warp_m + gid;
            stage[hc][r]         = acc[t][0];
            stage[hc + 1][r]     = acc[t][1];
            stage[hc][r + 8]     = acc[t][2];
            stage[hc + 1][r + 8] = acc[t][3];
        }
    }
    __syncthreads();
    size_t obase = (size_t)i * 1024 + j0;
    for (int e = tid; e < 1024; e += 256) {
        int hh = e >> 6, j = e & 63;
        g_bias[(size_t)hh * NN + obase + j] = stage[hh][j] + sbin[hh];
    }
}

// ---------------------------------------------------------------------------
// Convert single_repr + all 5 weights -> bf16 hi/lo.
// ---------------------------------------------------------------------------
__global__ __launch_bounds__(256) void conv_all(
    const float* __restrict__ s0, const float* __restrict__ s1,
    const float* __restrict__ s2, const float* __restrict__ s3,
    const float* __restrict__ s4, const float* __restrict__ s5)
{
    const float* srcs[6] = {s0, s1, s2, s3, s4, s5};
    const float* src = srcs[blockIdx.y];
    __nv_bfloat16 *Dh, *Dl;
    if (blockIdx.y == 0) { Dh = g_shi; Dl = g_slo; }
    else { Dh = g_wh[blockIdx.y - 1]; Dl = g_wl[blockIdx.y - 1]; }

    unsigned i = blockIdx.x * 256u + threadIdx.x;
    float4 v = ((const float4*)src)[i];
    *(unsigned*)(Dh + 4u*i)     = pk2(v.x, v.y);
    *(unsigned*)(Dh + 4u*i + 2) = pk2(v.z, v.w);
    *(unsigned*)(Dl + 4u*i)     = pk2(lores(v.x), lores(v.y));
    *(unsigned*)(Dl + 4u*i + 2) = pk2(lores(v.z), lores(v.w));
}

// ---------------------------------------------------------------------------
// QKVG GEMM: 512 thr, tile 128x256, BK=32, depth-3, pass-major MMA order.
// Grid (4, 8, 4) = 128 CTAs = one full wave.
// ---------------------------------------------------------------------------
__global__ __launch_bounds__(512, 1) void gemm_qkvg(const float* __restrict__ aux)
{
    extern __shared__ __nv_bfloat16 dsm[];
    constexpr unsigned SZB   = 16896u;   // 32 * 264 * 2
    constexpr unsigned BUFSZ = 54272u;

    int widx = blockIdx.z;
    float scale = (widx == 0) ? 0.125f : 1.0f;
    const __nv_bfloat16* gBh = g_wh[widx];
    const __nv_bfloat16* gBl = g_wl[widx];

    int tid  = threadIdx.x;
    int lane = tid & 31, warp = tid >> 5;
    int gid  = lane >> 2, tg = lane & 3;
    int fr = lane & 15, fc8 = (lane >> 4) * 8;
    int vr = (lane >> 4) * 8 + (lane & 7);
    int vc8 = ((lane >> 3) & 1) * 8;
    int warp_m = (warp >> 2) * 32, warp_n = (warp & 3) * 64;
    int m0 = blockIdx.y * 128, n0 = blockIdx.x * 256;
    unsigned sb = cvta_s(dsm);

    int a_row = (tid & 511) >> 2, a_seg = tid & 3;
    int b_row = (tid & 1023) >> 5, b_seg = tid & 31;

    const __nv_bfloat16* pAh = g_shi + (size_t)(m0 + a_row) * 1024 + a_seg * 8;
    const __nv_bfloat16* pAl = g_slo + (size_t)(m0 + a_row) * 1024 + a_seg * 8;
    const __nv_bfloat16* pBh0 = gBh + (size_t)b_row * 1024 + n0 + b_seg * 8;
    const __nv_bfloat16* pBl0 = gBl + (size_t)b_row * 1024 + n0 + b_seg * 8;
    const __nv_bfloat16* pBh1 = pBh0 + 16 * 1024;
    const __nv_bfloat16* pBl1 = pBl0 + 16 * 1024;
    unsigned dA  = a_row * 80u + a_seg * 16u;
    unsigned dB0 = 20480u + b_row * 528u + b_seg * 16u;
    unsigned dB1 = 20480u + (b_row + 16) * 528u + b_seg * 16u;

    auto issue = [&](int ch, int buf) {
        unsigned k0 = ch * 32u;
        size_t kq = ch * 32u * 1024u;
        unsigned bo = sb + buf * BUFSZ;
        CP_ASYNC16(bo + dA,           pAh + k0);
        CP_ASYNC16(bo + dA + 10240u,  pAl + k0);
        CP_ASYNC16(bo + dB0,          pBh0 + kq);
        CP_ASYNC16(bo + dB0 + SZB,    pBl0 + kq);
        CP_ASYNC16(bo + dB1,          pBh1 + kq);
        CP_ASYNC16(bo + dB1 + SZB,    pBl1 + kq);
        CP_COMMIT();
    };

    float acc[2][8][4];
#pragma unroll
    for (int a = 0; a < 2; a++)
#pragma unroll
        for (int b = 0; b < 8; b++)
#pragma unroll
            for (int q = 0; q < 4; q++) acc[a][b][q] = 0.f;

    issue(0, 0);
    issue(1, 1);

    int buf = 0;
#pragma unroll 1
    for (int ch = 0; ch < 32; ch++) {
        if (ch < 31) { CP_WAIT1(); } else { CP_WAIT0(); }
        __syncthreads();
        unsigned base = sb + buf * BUFSZ;
#pragma unroll
        for (int k16 = 0; k16 < 32; k16 += 16) {
            unsigned a_h[2][4], a_l[2][4], b_h[4][4], b_l[4][4];
#pragma unroll
            for (int mt = 0; mt < 2; mt++) {
                unsigned off = base + ((warp_m + mt * 16 + fr) * 40 + k16 + fc8) * 2;
                LDSM4(a_h[mt], off);
                LDSM4(a_l[mt], off + 10240u);
            }
#pragma unroll
            for (int tp = 0; tp < 4; tp++) {
                unsigned off = base + 20480u
                    + ((k16 + vr) * 264 + warp_n + tp * 16 + vc8) * 2;
                LDSM4T(b_h[tp], off);
                LDSM4T(b_l[tp], off + SZB);
            }
            // pass-major: 16 independent MMAs per pass; per-acc order hh->hl->lh
#pragma unroll
            for (int mt = 0; mt < 2; mt++)
#pragma unroll
                for (int tp = 0; tp < 4; tp++)
#pragma unroll
                    for (int u = 0; u < 2; u++)
                        MMA_BF16v(acc[mt][tp * 2 + u], a_h[mt],
                                  b_h[tp][u], b_h[tp][u + 2]);
#pragma unroll
            for (int mt = 0; mt < 2; mt++)
#pragma unroll
                for (int tp = 0; tp < 4; tp++)
#pragma unroll
                    for (int u = 0; u < 2; u++)
                        MMA_BF16v(acc[mt][tp * 2 + u], a_h[mt],
                                  b_l[tp][u], b_l[tp][u + 2]);
#pragma unroll
            for (int mt = 0; mt < 2; mt++)
#pragma unroll
                for (int tp = 0; tp < 4; tp++)
#pragma unroll
                    for (int u = 0; u < 2; u++)
                        MMA_BF16v(acc[mt][tp * 2 + u], a_l[mt],
                                  b_h[tp][u], b_h[tp][u + 2]);
        }
        if (ch + 2 < 32) {
            int nb = buf + 2; if (nb >= 3) nb -= 3;
            issue(ch + 2, nb);
        }
        if (++buf == 3) buf = 0;
    }

    __nv_bfloat16* Dh = (widx == 0) ? g_qh : (widx == 1) ? g_kh : g_vh;
    __nv_bfloat16* Dl = (widx == 0) ? g_ql : (widx == 1) ? g_kl : g_vl;
#pragma unroll
    for (int mt = 0; mt < 2; mt++) {
#pragma unroll
        for (int j = 0; j < 8; j++) {
            int rg = m0 + warp_m + mt * 16 + gid;
            int cg = n0 + warp_n + j * 8 + tg * 2;
            float* a4 = acc[mt][j];
            if (widx == 3) {
                float b0 = aux[cg], b1 = aux[cg + 1];
                float v0 = 1.f / (1.f + __expf(-(a4[0] + b0)));
                float v1 = 1.f / (1.f + __expf(-(a4[1] + b1)));
                float v2 = 1.f / (1.f + __expf(-(a4[2] + b0)));
                float v3 = 1.f / (1.f + __expf(-(a4[3] + b1)));
                *(float2*)&g_g[(size_t)rg * 1024 + cg]       = make_float2(v0, v1);
                *(float2*)&g_g[(size_t)(rg + 8) * 1024 + cg] = make_float2(v2, v3);
            } else {
                float v0 = a4[0] * scale, v1 = a4[1] * scale;
                float v2 = a4[2] * scale, v3 = a4[3] * scale;
                *(unsigned*)&Dh[(size_t)rg * 1024 + cg]       = pk2(v0, v1);
                *(unsigned*)&Dh[(size_t)(rg + 8) * 1024 + cg] = pk2(v2, v3);
                *(unsigned*)&Dl[(size_t)rg * 1024 + cg]       = pk2(lores(v0), lores(v1));
                *(unsigned*)&Dl[(size_t)(rg + 8) * 1024 + cg] =
                    pk2(lores(v2), lores(v3));
            }
        }
    }
}

// ---------------------------------------------------------------------------
// Output GEMM: 256 thr, tile 128x64, BK=32, depth-3, pass-major. Grid (16,8).
// ---------------------------------------------------------------------------
__global__ __launch_bounds__(256) void gemm_out(float* __restrict__ Cext)
{
    extern __shared__ __nv_bfloat16 dsm[];
    constexpr unsigned SZB   = 32u * 72 * 2;          // 4608
    constexpr unsigned BUFSZ = 20480u + 2 * SZB;      // 29696

    const __nv_bfloat16* gBh = g_wh[4];
    const __nv_bfloat16* gBl = g_wl[4];

    int tid  = threadIdx.x;
    int lane = tid & 31, warp = tid >> 5;
    int gid  = lane >> 2, tg = lane & 3;
    int fr = lane & 15, fc8 = (lane >> 4) * 8;
    int vr = (lane >> 4) * 8 + (lane & 7);
    int vc8 = ((lane >> 3) & 1) * 8;
    int warp_m = (warp >> 1) * 32, warp_n = (warp & 1) * 32;
    int m0 = blockIdx.y * 128, n0 = blockIdx.x * 64;
    unsigned sb = cvta_s(dsm);

    auto issue = [&](int ch, int buf) {
        int k0 = ch * 32;
        unsigned bo = sb + buf * BUFSZ;
#pragma unroll
        for (int t = 0; t < 6; t++) {
            int s = tid + t * 256;
            unsigned dst;
            const __nv_bfloat16* src;
            if (s < 1024) {
                int mt = s >> 9, rem = s & 511;
                int row = rem >> 2, seg = rem & 3;
                dst = bo + mt * 10240u + row * 80u + seg * 16u;
                src = (mt ? g_olo : g_ohi) + (size_t)(m0 + row) * 1024 + k0 + seg * 8;
            } else {
                int ss = s - 1024;
                int mt = ss >> 8, rem = ss & 255;
                int row = rem >> 3, seg = rem & 7;
                dst = bo + 20480u + mt * SZB + row * 144u + seg * 16u;
                src = (mt ? gBl : gBh) + (size_t)(k0 + row) * 1024 + n0 + seg * 8;
            }
            CP_ASYNC16(dst, src);
        }
        CP_COMMIT();
    };

    float acc[2][4][4];
#pragma unroll
    for (int a = 0; a < 2; a++)
#pragma unroll
        for (int b = 0; b < 4; b++)
#pragma unroll
            for (int q = 0; q < 4; q++) acc[a][b][q] = 0.f;

    issue(0, 0);
    issue(1, 1);

    int buf = 0;
#pragma unroll 1
    for (int ch = 0; ch < 32; ch++) {
        if (ch < 31) { CP_WAIT1(); } else { CP_WAIT0(); }
        __syncthreads();
        unsigned base = sb + buf * BUFSZ;
#pragma unroll
        for (int k16 = 0; k16 < 32; k16 += 16) {
            unsigned a_h[2][4], a_l[2][4], b_h[2][4], b_l[2][4];
#pragma unroll
            for (int mt = 0; mt < 2; mt++) {
                unsigned off = base + ((warp_m + mt * 16 + fr) * 40 + k16 + fc8) * 2;
                LDSM4(a_h[mt], off);
                LDSM4(a_l[mt], off + 10240u);
            }
#pragma unroll
            for (int tp = 0; tp < 2; tp++) {
                unsigned off = base + 20480u
                    + ((k16 + vr) * 72 + warp_n + tp * 16 + vc8) * 2;
                LDSM4T(b_h[tp], off);
                LDSM4T(b_l[tp], off + SZB);
            }
            // pass-major (8 independent per pass)
#pragma unroll
            for (int mt = 0; mt < 2; mt++)
#pragma unroll
                for (int tp = 0; tp < 2; tp++)
#pragma unroll
                    for (int u = 0; u < 2; u++)
                        MMA_BF16v(acc[mt][tp * 2 + u], a_h[mt],
                                  b_h[tp][u], b_h[tp][u + 2]);
#pragma unroll
            for (int mt = 0; mt < 2; mt++)
#pragma unroll
                for (int tp = 0; tp < 2; tp++)
#pragma unroll
                    for (int u = 0; u < 2; u++)
                        MMA_BF16v(acc[mt][tp * 2 + u], a_h[mt],
                                  b_l[tp][u], b_l[tp][u + 2]);
#pragma unroll
            for (int mt = 0; mt < 2; mt++)
#pragma unroll
                for (int tp = 0; tp < 2; tp++)
#pragma unroll
                    for (int u = 0; u < 2; u++)
                        MMA_BF16v(acc[mt][tp * 2 + u], a_l[mt],
                                  b_h[tp][u], b_h[tp][u + 2]);
        }
        if (ch + 2 < 32) {
            int nb = buf + 2; if (nb >= 3) nb -= 3;
            issue(ch + 2, nb);
        }
        if (++buf == 3) buf = 0;
    }

#pragma unroll
    for (int mt = 0; mt < 2; mt++) {
#pragma unroll
        for (int j = 0; j < 4; j++) {
            int rg = m0 + warp_m + mt * 16 + gid;
            int cg = n0 + warp_n + j * 8 + tg * 2;
            float* a4 = acc[mt][j];
            *(float2*)&Cext[(size_t)rg * 1024 + cg]       = make_float2(a4[0], a4[1]);
            *(float2*)&Cext[(size_t)(rg + 8) * 1024 + cg] = make_float2(a4[2], a4[3]);
        }
    }
}

// ---------------------------------------------------------------------------
// Flash attention, depth-3 K/V pipeline, tp-pair pass-major MMA order.
// 256 thr, 128 queries/CTA. Grid (8, 16).
// ---------------------------------------------------------------------------
__global__ __launch_bounds__(256) void attn_kernel()
{
    extern __shared__ __nv_bfloat16 dsm[];
    int tid  = threadIdx.x;
    int lane = tid & 31, warp = tid >> 5;
    int gid  = lane >> 2, tg = lane & 3;
    int h  = blockIdx.y;
    int q0 = blockIdx.x * 128;
    int warp_m = warp * 16;
    int qrow = q0 + warp_m + gid;
    unsigned sb = cvta_s(dsm);

    int fr = lane & 15, fc8 = (lane >> 4) * 8;
    int vr = (lane >> 4) * 8 + (lane & 7);
    int vc8 = ((lane >> 3) & 1) * 8;

    auto issue_kv = [&](int kb, int buf) {
        int k0 = kb * 64;
        unsigned bo = buf * 36864u;
#pragma unroll
        for (int t = 0; t < 8; t++) {
            int s = tid + t * 256;
            int mt = s >> 9, rem = s & 511;
            int row = rem >> 3, seg = rem & 7;
            unsigned dst = sb + bo + mt * 9216u + row * 144u + seg * 16u;
            const __nv_bfloat16* src;
            if      (mt == 0) src = g_kh + (size_t)(k0 + row) * 1024 + h * 64 + seg * 8;
            else if (mt == 1) src = g_kl + (size_t)(k0 + row) * 1024 + h * 64 + seg * 8;
            else if (mt == 2) src = g_vh + (size_t)(k0 + row) * 1024 + h * 64 + seg * 8;
            else              src = g_vl + (size_t)(k0 + row) * 1024 + h * 64 + seg * 8;
            CP_ASYNC16(dst, src);
        }
        CP_COMMIT();
    };

    unsigned qh[4][4], ql[4][4];
    {
        const __nv_bfloat16* Qh = g_qh + (size_t)qrow * 1024 + h * 64;
        const __nv_bfloat16* Ql = g_ql + (size_t)qrow * 1024 + h * 64;
#pragma unroll
        for (int c = 0; c < 4; c++) {
            int kk = c * 16 + tg * 2;
            qh[c][0] = *(const unsigned*)(Qh + kk);
            qh[c][1] = *(const unsigned*)(Qh + 8 * 1024 + kk);
            qh[c][2] = *(const unsigned*)(Qh + kk + 8);
            qh[c][3] = *(const unsigned*)(Qh + 8 * 1024 + kk + 8);
            ql[c][0] = *(const unsigned*)(Ql + kk);
            ql[c][1] = *(const unsigned*)(Ql + 8 * 1024 + kk);
            ql[c][2] = *(const unsigned*)(Ql + kk + 8);
            ql[c][3] = *(const unsigned*)(Ql + 8 * 1024 + kk + 8);
        }
    }

    float m0 = -1e30f, m1 = -1e30f, l0 = 0.f, l1 = 0.f;
    float O[8][4] = {};

    issue_kv(0, 0);
    issue_kv(1, 1);

    int buf = 0;
#pragma unroll 1
    for (int kb = 0; kb < 16; kb++) {
        if (kb < 15) { CP_WAIT1(); } else { CP_WAIT0(); }
        __syncthreads();
        unsigned base = sb + buf * 36864u;
        int k0 = kb * 64;

        float S[8][4];
        {
            const float* bptr = g_bias + (size_t)h * NN + (size_t)qrow * 1024 + k0;
#pragma unroll
            for (int t = 0; t < 8; t++) {
                float2 b0 = *(const float2*)(bptr + 8 * t + 2 * tg);
                float2 b1 = *(const float2*)(bptr + 8 * 1024 + 8 * t + 2 * tg);
                S[t][0] = b0.x; S[t][1] = b0.y; S[t][2] = b1.x; S[t][3] = b1.y;
            }
        }
        // S += Q K^T  (tp-pairs, pass-major within pair: dep distance 4)
#pragma unroll
        for (int c = 0; c < 4; c++) {
            int kk = c * 16;
#pragma unroll
            for (int tpp = 0; tpp < 4; tpp += 2) {
                unsigned bh[2][4], bl[2][4];
#pragma unroll
                for (int j = 0; j < 2; j++) {
                    unsigned off = base + (((tpp + j) * 16 + fr) * 72 + kk + fc8) * 2;
                    LDSM4(bh[j], off);
                    LDSM4(bl[j], off + 9216u);
                }
#pragma unroll
                for (int j = 0; j < 2; j++)
#pragma unroll
                    for (int u = 0; u < 2; u++)
                        MMA_BF16v(S[(tpp + j) * 2 + u], qh[c],
                                  bh[j][u], bh[j][u + 2]);
#pragma unroll
                for (int j = 0; j < 2; j++)
#pragma unroll
                    for (int u = 0; u < 2; u++)
                        MMA_BF16v(S[(tpp + j) * 2 + u], qh[c],
                                  bl[j][u], bl[j][u + 2]);
#pragma unroll
                for (int j = 0; j < 2; j++)
#pragma unroll
                    for (int u = 0; u < 2; u++)
                        MMA_BF16v(S[(tpp + j) * 2 + u], ql[c],
                                  bh[j][u], bh[j][u + 2]);
            }
        }

        float rm0 = -1e30f, rm1 = -1e30f;
#pragma unroll
        for (int t = 0; t < 8; t++) {
            rm0 = fmaxf(rm0, fmaxf(S[t][0], S[t][1]));
            rm1 = fmaxf(rm1, fmaxf(S[t][2], S[t][3]));
        }
        rm0 = fmaxf(rm0, __shfl_xor_sync(0xffffffffu, rm0, 1));
        rm0 = fmaxf(rm0, __shfl_xor_sync(0xffffffffu, rm0, 2));
        rm1 = fmaxf(rm1, __shfl_xor_sync(0xffffffffu, rm1, 1));
        rm1 = fmaxf(rm1, __shfl_xor_sync(0xffffffffu, rm1, 2));
        float mn0 = fmaxf(m0, rm0), mn1 = fmaxf(m1, rm1);
        float c0 = __expf(m0 - mn0), c1 = __expf(m1 - mn1);
        m0 = mn0; m1 = mn1;
        float ps0 = 0.f, ps1 = 0.f;
#pragma unroll
        for (int t = 0; t < 8; t++) {
            S[t][0] = __expf(S[t][0] - mn0);
            S[t][1] = __expf(S[t][1] - mn0);
            S[t][2] = __expf(S[t][2] - mn1);
            S[t][3] = __expf(S[t][3] - mn1);
            ps0 += S[t][0] + S[t][1];
            ps1 += S[t][2] + S[t][3];
        }
        ps0 += __shfl_xor_sync(0xffffffffu, ps0, 1);
        ps0 += __shfl_xor_sync(0xffffffffu, ps0, 2);
        ps1 += __shfl_xor_sync(0xffffffffu, ps1, 1);
        ps1 += __shfl_xor_sync(0xffffffffu, ps1, 2);
        l0 = l0 * c0 + ps0;
        l1 = l1 * c1 + ps1;
#pragma unroll
        for (int t = 0; t < 8; t++) {
            O[t][0] *= c0; O[t][1] *= c0; O[t][2] *= c1; O[t][3] *= c1;
        }

        unsigned ph[4][4], pl[4][4];
#pragma unroll
        for (int c = 0; c < 4; c++) {
            int t0 = 2 * c, t1 = 2 * c + 1;
            ph[c][0] = pk2(S[t0][0], S[t0][1]);
            ph[c][1] = pk2(S[t0][2], S[t0][3]);
            ph[c][2] = pk2(S[t1][0], S[t1][1]);
            ph[c][3] = pk2(S[t1][2], S[t1][3]);
            pl[c][0] = pk2(lores(S[t0][0]), lores(S[t0][1]));
            pl[c][1] = pk2(lores(S[t0][2]), lores(S[t0][3]));
            pl[c][2] = pk2(lores(S[t1][0]), lores(S[t1][1]));
            pl[c][3] = pk2(lores(S[t1][2]), lores(S[t1][3]));
        }

        // O += P V  (tp-pairs, pass-major within pair)
#pragma unroll
        for (int c = 0; c < 4; c++) {
#pragma unroll
            for (int tpp = 0; tpp < 4; tpp += 2) {
                unsigned bh[2][4], bl[2][4];
#pragma unroll
                for (int j = 0; j < 2; j++) {
                    unsigned off = base + 18432u
                        + ((c * 16 + vr) * 72 + (tpp + j) * 16 + vc8) * 2;
                    LDSM4T(bh[j], off);
                    LDSM4T(bl[j], off + 9216u);
                }
#pragma unroll
                for (int j = 0; j < 2; j++)
#pragma unroll
                    for (int u = 0; u < 2; u++)
                        MMA_BF16v(O[(tpp + j) * 2 + u], ph[c],
                                  bh[j][u], bh[j][u + 2]);
#pragma unroll
                for (int j = 0; j < 2; j++)
#pragma unroll
                    for (int u = 0; u < 2; u++)
                        MMA_BF16v(O[(tpp + j) * 2 + u], ph[c],
                                  bl[j][u], bl[j][u + 2]);
#pragma unroll
                for (int j = 0; j < 2; j++)
#pragma unroll
                    for (int u = 0; u < 2; u++)
                        MMA_BF16v(O[(tpp + j) * 2 + u], pl[c],
                                  bh[j][u], bh[j][u + 2]);
            }
        }
        if (kb + 2 < 16) {
            int nb = buf + 2; if (nb >= 3) nb -= 3;
            issue_kv(kb + 2, nb);
        }
        if (++buf == 3) buf = 0;
    }

    float inv0 = 1.f / l0, inv1 = 1.f / l1;
#pragma unroll
    for (int t = 0; t < 8; t++) {
        int col = h * 64 + 8 * t + 2 * tg;
        size_t o0 = (size_t)qrow * 1024 + col;
        size_t o1 = o0 + 8 * 1024;
        float2 gg0 = *(const float2*)(g_g + o0);
        float2 gg1 = *(const float2*)(g_g + o1);
        float v0 = O[t][0] * inv0 * gg0.x;
        float v1 = O[t][1] * inv0 * gg0.y;
        float v2 = O[t][2] * inv1 * gg1.x;
        float v3 = O[t][3] * inv1 * gg1.y;
        *(unsigned*)(g_ohi + o0) = pk2(v0, v1);
        *(unsigned*)(g_ohi + o1) = pk2(v2, v3);
        *(unsigned*)(g_olo + o0) = pk2(lores(v0), lores(v1));
        *(unsigned*)(g_olo + o1) = pk2(lores(v2), lores(v3));
    }
}

// ---------------------------------------------------------------------------
extern "C" void kernel_launch(void* const* d_in, const int* in_sizes, int n_in,
                              void* d_out, int out_size)
{
    const float* single = (const float*)d_in[0];
    const float* pw     = (const float*)d_in[1];
    const float* gamma  = (const float*)d_in[2];
    const float* beta   = (const float*)d_in[3];
    const float* Wb     = (const float*)d_in[4];
    const float* Wq     = (const float*)d_in[5];
    const float* Wk     = (const float*)d_in[6];
    const float* Wv     = (const float*)d_in[7];
    const float* Wg     = (const float*)d_in[8];
    const float* bg     = (const float*)d_in[9];
    const float* Wo     = (const float*)d_in[10];
    float* out = (float*)d_out;

    const int QKVG_SMEM = 3 * 54272;   // 162816
    const int OUT_SMEM  = 3 * 29696;   // 89088
    const int ATTN_SMEM = 3 * 36864;   // 110592
    cudaFuncSetAttribute(gemm_qkvg,
        cudaFuncAttributeMaxDynamicSharedMemorySize, QKVG_SMEM);
    cudaFuncSetAttribute(gemm_out,
        cudaFuncAttributeMaxDynamicSharedMemorySize, OUT_SMEM);
    cudaFuncSetAttribute(attn_kernel,
        cudaFuncAttributeMaxDynamicSharedMemorySize, ATTN_SMEM);

    bias_setup<<<1, 128>>>(gamma, beta, Wb);
    dim3 bgrid(16, 1024);
    bias_kernel<<<bgrid, 256>>>(pw);

    dim3 cgrid(1024, 6);
    conv_all<<<cgrid, 256>>>(single, Wq, Wk, Wv, Wg, Wo);

    dim3 ggrid(4, 8, 4);   // 128 CTAs
    gemm_qkvg<<<ggrid, 512, QKVG_SMEM>>>(bg);

    dim3 agrid(8, 16);
    attn_kernel<<<agrid, 256, ATTN_SMEM>>>();

    dim3 ogrid(16, 8);     // 128 CTAs
    gemm_out<<<ogrid, 256, OUT_SMEM>>>(out);
}